// round 1
// baseline (speedup 1.0000x reference)
#include <cuda_runtime.h>
#include <math.h>

// Problem constants
constexpr int BB  = 2;
constexpr int TT  = 2048;
constexpr int DD  = 1024;
constexpr int HH  = 16;
constexpr int DHD = 64;          // head dim
constexpr int MM  = BB * TT;     // 4096 rows

// Scratch (device globals — no allocation allowed)
__device__ float g_Q[MM * DD];   // head-major [B,H,T,DH]
__device__ float g_K[MM * DD];   // head-major
__device__ float g_V[MM * DD];   // head-major
__device__ float g_O[MM * DD];   // token-major [B,T,D]

// ---------------------------------------------------------------------------
// SGEMM 128x128 tile, BK=8, 256 threads, 8x8 micro-tile.
// MODE 0: C written head-major ([B,H,T,DH]) for Q/K/V.
// MODE 1: C written plain row-major (final projection).
// ---------------------------------------------------------------------------
template <int MODE>
__device__ __forceinline__ void sgemm_body(const float* __restrict__ A,
                                           const float* __restrict__ Bm,
                                           float* __restrict__ C,
                                           int N, int K,
                                           int bx, int by)
{
    __shared__ float As[8][128];
    __shared__ float Bs[8][128];

    const int tid  = threadIdx.x;
    const int arow = tid >> 1;           // 0..127
    const int acol = (tid & 1) * 4;      // 0 or 4
    const int brow = tid >> 5;           // 0..7
    const int bcol = (tid & 31) * 4;     // 0..124
    const int tx   = tid & 15;
    const int ty   = tid >> 4;

    const float* Ap = A  + (size_t)(by * 128 + arow) * K + acol;
    const float* Bp = Bm + (size_t)brow * N + bx * 128 + bcol;

    float acc[8][8];
#pragma unroll
    for (int i = 0; i < 8; i++)
#pragma unroll
        for (int j = 0; j < 8; j++) acc[i][j] = 0.0f;

    for (int k0 = 0; k0 < K; k0 += 8) {
        float4 a4 = *(const float4*)Ap;  Ap += 8;
        float4 b4 = *(const float4*)Bp;  Bp += (size_t)8 * N;

        As[acol + 0][arow] = a4.x;
        As[acol + 1][arow] = a4.y;
        As[acol + 2][arow] = a4.z;
        As[acol + 3][arow] = a4.w;
        *(float4*)&Bs[brow][bcol] = b4;
        __syncthreads();

#pragma unroll
        for (int k = 0; k < 8; k++) {
            float ar[8], br[8];
#pragma unroll
            for (int i = 0; i < 8; i++) ar[i] = As[k][ty * 8 + i];
#pragma unroll
            for (int j = 0; j < 8; j++) br[j] = Bs[k][tx * 8 + j];
#pragma unroll
            for (int i = 0; i < 8; i++)
#pragma unroll
                for (int j = 0; j < 8; j++)
                    acc[i][j] += ar[i] * br[j];
        }
        __syncthreads();
    }

    const int row0 = by * 128 + ty * 8;
    const int col0 = bx * 128 + tx * 8;

    if (MODE == 0) {
        // head-major scatter: row r = b*T + t ; col c = h*DH + dd
#pragma unroll
        for (int i = 0; i < 8; i++) {
            const int r = row0 + i;
            const int bb = r / TT;
            const int t  = r % TT;
#pragma unroll
            for (int j = 0; j < 8; j++) {
                const int c  = col0 + j;
                const int h  = c >> 6;      // /DH
                const int dd = c & 63;      // %DH
                C[(((size_t)bb * HH + h) * TT + t) * DHD + dd] = acc[i][j];
            }
        }
    } else {
#pragma unroll
        for (int i = 0; i < 8; i++) {
            float* crow = C + (size_t)(row0 + i) * N + col0;
            *(float4*)(crow + 0) = make_float4(acc[i][0], acc[i][1], acc[i][2], acc[i][3]);
            *(float4*)(crow + 4) = make_float4(acc[i][4], acc[i][5], acc[i][6], acc[i][7]);
        }
    }
}

// Fused QKV projection: grid.z selects which weight / destination.
__global__ void __launch_bounds__(256)
qkv_gemm_kernel(const float* __restrict__ x,
                const float* __restrict__ Wq,
                const float* __restrict__ Wk,
                const float* __restrict__ Wv)
{
    const int z = blockIdx.z;
    const float* W = (z == 0) ? Wq : (z == 1) ? Wk : Wv;
    float* C = (z == 0) ? g_Q : (z == 1) ? g_K : g_V;
    sgemm_body<0>(x, W, C, DD, DD, blockIdx.x, blockIdx.y);
}

// Output projection: g_O @ Wo -> out
__global__ void __launch_bounds__(256)
proj_gemm_kernel(const float* __restrict__ Wo, float* __restrict__ out)
{
    sgemm_body<1>(g_O, Wo, out, DD, DD, blockIdx.x, blockIdx.y);
}

// ---------------------------------------------------------------------------
// Flash attention (causal). One thread = one query row.
// Block: 128 threads = 128 queries of one (b,h). Key tile BN=32.
// K tile transposed in smem (Kts[d][kk]) so the QK inner loop issues
// LDS.128 broadcasts (1 LDS per 4 FMA). V tile kept natural layout.
// ---------------------------------------------------------------------------
constexpr int ABM = 128;   // queries per block
constexpr int ABN = 32;    // keys per tile
constexpr int KTP = 36;    // padded transposed-K row stride (16B aligned, bank-spread)

__global__ void __launch_bounds__(ABM)
attn_kernel(float* __restrict__ O)
{
    const int bh  = blockIdx.y;        // 0..B*H-1
    const int bb  = bh / HH;
    const int h   = bh % HH;
    const int qt  = blockIdx.x;        // query tile
    const int tid = threadIdx.x;
    const int q_global = qt * ABM + tid;

    const float* Qrow  = g_Q + ((size_t)bh * TT + q_global) * DHD;
    const float* Kbase = g_K + (size_t)bh * TT * DHD;
    const float* Vbase = g_V + (size_t)bh * TT * DHD;

    __shared__ float Kts[DHD][KTP];    // transposed K tile
    __shared__ float Vs[ABN][DHD];     // natural V tile

    float q[DHD];
#pragma unroll
    for (int i = 0; i < DHD / 4; i++)
        ((float4*)q)[i] = ((const float4*)Qrow)[i];
    const float scale = 0.125f;        // 1/sqrt(64)
#pragma unroll
    for (int d = 0; d < DHD; d++) q[d] *= scale;

    float o[DHD];
#pragma unroll
    for (int d = 0; d < DHD; d++) o[d] = 0.0f;
    float m = -1e30f;
    float l = 0.0f;

    const int ntiles = (qt + 1) * (ABM / ABN);   // causal: keys < (qt+1)*128

    for (int jt = 0; jt < ntiles; jt++) {
        const int k0 = jt * ABN;

        // cooperative load: 32x64 floats K (transposed) + V (straight copy)
        const float4* K4 = (const float4*)(Kbase + (size_t)k0 * DHD);
        const float4* V4 = (const float4*)(Vbase + (size_t)k0 * DHD);
#pragma unroll
        for (int r = 0; r < 4; r++) {
            const int i4   = r * ABM + tid;      // float4 index, 512 total
            const int elem = i4 * 4;
            const int kk   = elem >> 6;          // /DH
            const int d0   = elem & 63;          // %DH
            float4 kf = K4[i4];
            Kts[d0 + 0][kk] = kf.x;
            Kts[d0 + 1][kk] = kf.y;
            Kts[d0 + 2][kk] = kf.z;
            Kts[d0 + 3][kk] = kf.w;
            ((float4*)&Vs[0][0])[i4] = V4[i4];
        }
        __syncthreads();

        // scores
        float s[ABN];
#pragma unroll
        for (int kk = 0; kk < ABN; kk++) s[kk] = 0.0f;
#pragma unroll
        for (int d = 0; d < DHD; d++) {
            const float qd = q[d];
#pragma unroll
            for (int kk = 0; kk < ABN; kk++)
                s[kk] += qd * Kts[d][kk];
        }

        // causal mask on the diagonal/over-run tiles
        if (k0 + ABN - 1 > q_global) {
#pragma unroll
            for (int kk = 0; kk < ABN; kk++)
                if (k0 + kk > q_global) s[kk] = -1e30f;
        }

        // online softmax update
        float mt = -1e30f;
#pragma unroll
        for (int kk = 0; kk < ABN; kk++) mt = fmaxf(mt, s[kk]);
        const float m_new = fmaxf(m, mt);
        const float corr = __expf(m - m_new);
        l *= corr;
#pragma unroll
        for (int d = 0; d < DHD; d++) o[d] *= corr;

#pragma unroll
        for (int kk = 0; kk < ABN; kk++) {
            const float p = __expf(s[kk] - m_new);
            l += p;
#pragma unroll
            for (int d = 0; d < DHD; d++)
                o[d] += p * Vs[kk][d];
        }
        m = m_new;
        __syncthreads();
    }

    // write normalized output, token-major [B,T,D]
    const float inv = 1.0f / l;
    float* Orow = O + ((size_t)bb * TT + q_global) * DD + h * DHD;
#pragma unroll
    for (int i = 0; i < DHD / 4; i++) {
        ((float4*)Orow)[i] = make_float4(o[i * 4 + 0] * inv,
                                         o[i * 4 + 1] * inv,
                                         o[i * 4 + 2] * inv,
                                         o[i * 4 + 3] * inv);
    }
}

// ---------------------------------------------------------------------------
extern "C" void kernel_launch(void* const* d_in, const int* in_sizes, int n_in,
                              void* d_out, int out_size)
{
    (void)in_sizes; (void)n_in; (void)out_size;
    const float* x  = (const float*)d_in[0];
    // d_in[1] is the causal mask — statically known, ignored
    const float* Wq = (const float*)d_in[2];
    const float* Wk = (const float*)d_in[3];
    const float* Wv = (const float*)d_in[4];
    const float* Wo = (const float*)d_in[5];
    float* out = (float*)d_out;

    float* Oscratch;
    cudaGetSymbolAddress((void**)&Oscratch, g_O);

    // 1. QKV projections (fused launch, grid.z = which matrix)
    dim3 g1(DD / 128, MM / 128, 3);
    qkv_gemm_kernel<<<g1, 256>>>(x, Wq, Wk, Wv);

    // 2. causal flash attention
    dim3 g2(TT / ABM, BB * HH);
    attn_kernel<<<g2, ABM>>>(Oscratch);

    // 3. output projection
    dim3 g3(DD / 128, MM / 128);
    proj_gemm_kernel<<<g3, 256>>>(Wo, out);
}

// round 3
// speedup vs baseline: 1.3752x; 1.3752x over previous
#include <cuda_runtime.h>
#include <cuda_bf16.h>
#include <math.h>
#include <stdint.h>

// Problem constants
constexpr int BB  = 2;
constexpr int TT  = 2048;
constexpr int DD  = 1024;
constexpr int HH  = 16;
constexpr int DHD = 64;          // head dim
constexpr int MM  = BB * TT;     // 4096 rows

// Scratch (device globals — no allocation allowed)
__device__ float g_Q[MM * DD];   // head-major [B,H,T,DH]
__device__ float g_K[MM * DD];   // head-major
__device__ float g_V[MM * DD];   // head-major
__device__ float g_O[MM * DD];   // token-major [B,T,D]

// ---------------------------------------------------------------------------
// mma.sync helpers (sm_80-baseline PTX — compiles for plain sm_103 target)
// ---------------------------------------------------------------------------
__device__ __forceinline__ void ldsm_x4(uint32_t& r0, uint32_t& r1,
                                        uint32_t& r2, uint32_t& r3, uint32_t addr) {
    asm volatile("ldmatrix.sync.aligned.m8n8.x4.shared.b16 {%0,%1,%2,%3}, [%4];"
                 : "=r"(r0), "=r"(r1), "=r"(r2), "=r"(r3) : "r"(addr));
}

__device__ __forceinline__ void mma_bf16(float* d, const uint32_t* a,
                                         uint32_t b0, uint32_t b1) {
    asm volatile(
        "mma.sync.aligned.m16n8k16.row.col.f32.bf16.bf16.f32 "
        "{%0,%1,%2,%3}, {%4,%5,%6,%7}, {%8,%9}, {%0,%1,%2,%3};"
        : "+f"(d[0]), "+f"(d[1]), "+f"(d[2]), "+f"(d[3])
        : "r"(a[0]), "r"(a[1]), "r"(a[2]), "r"(a[3]), "r"(b0), "r"(b1));
}

__device__ __forceinline__ uint32_t smem_to_u32(const void* p) {
    uint32_t a;
    asm("{ .reg .u64 t; cvta.to.shared.u64 t, %1; cvt.u32.u64 %0, t; }"
        : "=r"(a) : "l"(p));
    return a;
}

__device__ __forceinline__ uint32_t pack_bf2(__nv_bfloat16 a, __nv_bfloat16 b) {
    __nv_bfloat162 t = __halves2bfloat162(a, b);
    return *reinterpret_cast<uint32_t*>(&t);
}

// split 2 floats -> hi/lo bf16 pairs
__device__ __forceinline__ void split2(float f0, float f1, uint32_t& hw, uint32_t& lw) {
    __nv_bfloat16 h0 = __float2bfloat16(f0);
    __nv_bfloat16 h1 = __float2bfloat16(f1);
    __nv_bfloat16 l0 = __float2bfloat16(f0 - __bfloat162float(h0));
    __nv_bfloat16 l1 = __float2bfloat16(f1 - __bfloat162float(h1));
    hw = pack_bf2(h0, h1);
    lw = pack_bf2(l0, l1);
}

// ---------------------------------------------------------------------------
// HMMA GEMM: C[4096,1024] = A[4096,1024] @ W[1024,1024]
// bf16 3-term split (AhBh + AlBh + AhBl), fp32 accumulate.
// CTA tile 128x128, BK=32, 8 warps (2x4), warp tile 64x32, double-buffered.
// MODE 0: head-major scatter (QKV). MODE 1: row-major (output proj).
// ---------------------------------------------------------------------------
constexpr int BK    = 32;
constexpr int NITER = DD / BK;            // 32
constexpr int LDSM_ = 40;                 // padded row stride in bf16 elems (80B)
constexpr int OPB   = 128 * LDSM_ * 2;    // 10240 B per operand tile
constexpr int BUFB  = 4 * OPB;            // Ah, Al, Bh, Bl
constexpr int SMEM_DYN = 2 * BUFB;        // 81920 B

template <int MODE>
__device__ __forceinline__ void gemm_mma(const float* __restrict__ A,
                                         const float* __restrict__ Bm,
                                         float* __restrict__ C,
                                         int bx, int by)
{
    extern __shared__ char smem[];
    const int tid  = threadIdx.x;
    const int lane = tid & 31;
    const int wid  = tid >> 5;
    const int wm   = wid >> 2;       // 0..1  (64-row slab)
    const int wn   = wid & 3;        // 0..3  (32-col slab)
    const int m0 = by * 128, n0 = bx * 128;

    float acc[4][4][4];
#pragma unroll
    for (int i = 0; i < 4; i++)
#pragma unroll
        for (int j = 0; j < 4; j++)
#pragma unroll
            for (int k = 0; k < 4; k++) acc[i][j][k] = 0.0f;

    // gmem -> regs
    const int a_row = tid >> 1;
    const int a_kg  = (tid & 1) * 16;
    const int b_n   = tid & 127;
    const int b_kg  = (tid >> 7) * 16;

    auto load_gmem = [&](int k0, float* af, float* bf) {
        const float* ap = A + (size_t)(m0 + a_row) * DD + k0 + a_kg;
#pragma unroll
        for (int j = 0; j < 4; j++)
            *reinterpret_cast<float4*>(af + 4 * j) = *reinterpret_cast<const float4*>(ap + 4 * j);
        const float* bp = Bm + (size_t)(k0 + b_kg) * DD + n0 + b_n;
#pragma unroll
        for (int j = 0; j < 16; j++)
            bf[j] = bp[(size_t)j * DD];
    };

    // regs -> smem (split + pad + transpose-for-B)
    auto store_smem = [&](int b, const float* af, const float* bf) {
        char* Ah = smem + b * BUFB;
        char* Al = Ah + OPB;
        char* Bh = Al + OPB;
        char* Bl = Bh + OPB;
        uint32_t hw[8], lw[8];
#pragma unroll
        for (int j = 0; j < 8; j++) split2(af[2 * j], af[2 * j + 1], hw[j], lw[j]);
        {
            char* p = Ah + (a_row * LDSM_ + a_kg) * 2;
            *reinterpret_cast<uint4*>(p)      = make_uint4(hw[0], hw[1], hw[2], hw[3]);
            *reinterpret_cast<uint4*>(p + 16) = make_uint4(hw[4], hw[5], hw[6], hw[7]);
            char* q = Al + (a_row * LDSM_ + a_kg) * 2;
            *reinterpret_cast<uint4*>(q)      = make_uint4(lw[0], lw[1], lw[2], lw[3]);
            *reinterpret_cast<uint4*>(q + 16) = make_uint4(lw[4], lw[5], lw[6], lw[7]);
        }
#pragma unroll
        for (int j = 0; j < 8; j++) split2(bf[2 * j], bf[2 * j + 1], hw[j], lw[j]);
        {
            char* p = Bh + (b_n * LDSM_ + b_kg) * 2;
            *reinterpret_cast<uint4*>(p)      = make_uint4(hw[0], hw[1], hw[2], hw[3]);
            *reinterpret_cast<uint4*>(p + 16) = make_uint4(hw[4], hw[5], hw[6], hw[7]);
            char* q = Bl + (b_n * LDSM_ + b_kg) * 2;
            *reinterpret_cast<uint4*>(q)      = make_uint4(lw[0], lw[1], lw[2], lw[3]);
            *reinterpret_cast<uint4*>(q + 16) = make_uint4(lw[4], lw[5], lw[6], lw[7]);
        }
    };

    // ldmatrix lane addressing
    const int ar = wm * 64 + (lane & 15);          // A row
    const int ac = (lane >> 4) * 8;                // A k-half within k16
    const int br = wn * 32 + (lane & 15);          // B n row
    const int bc = (lane >> 4) * 8;                // B k-half

    auto compute = [&](int b) {
        const uint32_t ah_b = smem_to_u32(smem + b * BUFB);
        const uint32_t al_b = ah_b + OPB;
        const uint32_t bh_b = al_b + OPB;
        const uint32_t bl_b = bh_b + OPB;
#pragma unroll
        for (int ks = 0; ks < 2; ks++) {
            uint32_t ah[4][4], al[4][4], bh[2][4], bl[2][4];
#pragma unroll
            for (int mf = 0; mf < 4; mf++) {
                const uint32_t off = (uint32_t)(((ar + mf * 16) * LDSM_ + ks * 16 + ac) * 2);
                ldsm_x4(ah[mf][0], ah[mf][1], ah[mf][2], ah[mf][3], ah_b + off);
                ldsm_x4(al[mf][0], al[mf][1], al[mf][2], al[mf][3], al_b + off);
            }
#pragma unroll
            for (int g = 0; g < 2; g++) {
                const uint32_t off = (uint32_t)(((br + g * 16) * LDSM_ + ks * 16 + bc) * 2);
                ldsm_x4(bh[g][0], bh[g][1], bh[g][2], bh[g][3], bh_b + off);
                ldsm_x4(bl[g][0], bl[g][1], bl[g][2], bl[g][3], bl_b + off);
            }
#pragma unroll
            for (int mf = 0; mf < 4; mf++)
#pragma unroll
                for (int g = 0; g < 2; g++)
#pragma unroll
                    for (int sub = 0; sub < 2; sub++) {
                        const int nf = g * 2 + sub;
                        mma_bf16(acc[mf][nf], ah[mf], bh[g][sub], bh[g][sub + 2]);
                        mma_bf16(acc[mf][nf], al[mf], bh[g][sub], bh[g][sub + 2]);
                        mma_bf16(acc[mf][nf], ah[mf], bl[g][sub], bl[g][sub + 2]);
                    }
        }
    };

    // prologue
    {
        float af[16], bf[16];
        load_gmem(0, af, bf);
        store_smem(0, af, bf);
    }
    __syncthreads();

    for (int it = 0; it < NITER; ++it) {
        const int b = it & 1;
        float af[16], bf[16];
        const bool pf = (it + 1 < NITER);
        if (pf) load_gmem((it + 1) * BK, af, bf);   // LDG latency hides under MMA
        compute(b);
        if (pf) store_smem(b ^ 1, af, bf);
        __syncthreads();
    }

    // epilogue
    const int group = lane >> 2;
    const int qd    = lane & 3;
#pragma unroll
    for (int mf = 0; mf < 4; mf++)
#pragma unroll
        for (int nf = 0; nf < 4; nf++) {
            const int rg = m0 + wm * 64 + mf * 16 + group;
            const int cg = n0 + wn * 32 + nf * 8 + qd * 2;
            float2 v0 = make_float2(acc[mf][nf][0], acc[mf][nf][1]);
            float2 v1 = make_float2(acc[mf][nf][2], acc[mf][nf][3]);
            if (MODE == 0) {
                const int bb = rg >> 11;
                const int t  = rg & 2047;
                const int h  = cg >> 6;
                const int dd = cg & 63;
                float* base = C + (((size_t)bb * HH + h) * TT) * DHD + dd;
                *reinterpret_cast<float2*>(base + (size_t)t * DHD)       = v0;
                *reinterpret_cast<float2*>(base + (size_t)(t + 8) * DHD) = v1;
            } else {
                *reinterpret_cast<float2*>(C + (size_t)rg * DD + cg)       = v0;
                *reinterpret_cast<float2*>(C + (size_t)(rg + 8) * DD + cg) = v1;
            }
        }
}

__global__ void __launch_bounds__(256)
qkv_mma_kernel(const float* __restrict__ x,
               const float* __restrict__ Wq,
               const float* __restrict__ Wk,
               const float* __restrict__ Wv)
{
    const int z = blockIdx.z;
    const float* W = (z == 0) ? Wq : (z == 1) ? Wk : Wv;
    float* C = (z == 0) ? g_Q : (z == 1) ? g_K : g_V;
    gemm_mma<0>(x, W, C, blockIdx.x, blockIdx.y);
}

__global__ void __launch_bounds__(256)
proj_mma_kernel(const float* __restrict__ Wo, float* __restrict__ out)
{
    gemm_mma<1>(g_O, Wo, out, blockIdx.x, blockIdx.y);
}

// ---------------------------------------------------------------------------
// Flash attention (causal), fp32 SIMT — unchanged from R1 (passed, 1.2e-6).
// ---------------------------------------------------------------------------
constexpr int ABM = 128;
constexpr int ABN = 32;
constexpr int KTP = 36;

__global__ void __launch_bounds__(ABM)
attn_kernel(float* __restrict__ O)
{
    const int bh  = blockIdx.y;
    const int bb  = bh / HH;
    const int h   = bh % HH;
    const int qt  = blockIdx.x;
    const int tid = threadIdx.x;
    const int q_global = qt * ABM + tid;

    const float* Qrow  = g_Q + ((size_t)bh * TT + q_global) * DHD;
    const float* Kbase = g_K + (size_t)bh * TT * DHD;
    const float* Vbase = g_V + (size_t)bh * TT * DHD;

    __shared__ float Kts[DHD][KTP];
    __shared__ float Vs[ABN][DHD];

    float q[DHD];
#pragma unroll
    for (int i = 0; i < DHD / 4; i++)
        ((float4*)q)[i] = ((const float4*)Qrow)[i];
    const float scale = 0.125f;
#pragma unroll
    for (int d = 0; d < DHD; d++) q[d] *= scale;

    float o[DHD];
#pragma unroll
    for (int d = 0; d < DHD; d++) o[d] = 0.0f;
    float m = -1e30f;
    float l = 0.0f;

    const int ntiles = (qt + 1) * (ABM / ABN);

    for (int jt = 0; jt < ntiles; jt++) {
        const int k0 = jt * ABN;
        const float4* K4 = (const float4*)(Kbase + (size_t)k0 * DHD);
        const float4* V4 = (const float4*)(Vbase + (size_t)k0 * DHD);
#pragma unroll
        for (int r = 0; r < 4; r++) {
            const int i4   = r * ABM + tid;
            const int elem = i4 * 4;
            const int kk   = elem >> 6;
            const int d0   = elem & 63;
            float4 kf = K4[i4];
            Kts[d0 + 0][kk] = kf.x;
            Kts[d0 + 1][kk] = kf.y;
            Kts[d0 + 2][kk] = kf.z;
            Kts[d0 + 3][kk] = kf.w;
            ((float4*)&Vs[0][0])[i4] = V4[i4];
        }
        __syncthreads();

        float s[ABN];
#pragma unroll
        for (int kk = 0; kk < ABN; kk++) s[kk] = 0.0f;
#pragma unroll
        for (int d = 0; d < DHD; d++) {
            const float qd = q[d];
#pragma unroll
            for (int kk = 0; kk < ABN; kk++)
                s[kk] += qd * Kts[d][kk];
        }

        if (k0 + ABN - 1 > q_global) {
#pragma unroll
            for (int kk = 0; kk < ABN; kk++)
                if (k0 + kk > q_global) s[kk] = -1e30f;
        }

        float mt = -1e30f;
#pragma unroll
        for (int kk = 0; kk < ABN; kk++) mt = fmaxf(mt, s[kk]);
        const float m_new = fmaxf(m, mt);
        const float corr = __expf(m - m_new);
        l *= corr;
#pragma unroll
        for (int d = 0; d < DHD; d++) o[d] *= corr;

#pragma unroll
        for (int kk = 0; kk < ABN; kk++) {
            const float p = __expf(s[kk] - m_new);
            l += p;
#pragma unroll
            for (int d = 0; d < DHD; d++)
                o[d] += p * Vs[kk][d];
        }
        m = m_new;
        __syncthreads();
    }

    const float inv = 1.0f / l;
    float* Orow = O + ((size_t)bb * TT + q_global) * DD + h * DHD;
#pragma unroll
    for (int i = 0; i < DHD / 4; i++) {
        ((float4*)Orow)[i] = make_float4(o[i * 4 + 0] * inv,
                                         o[i * 4 + 1] * inv,
                                         o[i * 4 + 2] * inv,
                                         o[i * 4 + 3] * inv);
    }
}

// ---------------------------------------------------------------------------
extern "C" void kernel_launch(void* const* d_in, const int* in_sizes, int n_in,
                              void* d_out, int out_size)
{
    (void)in_sizes; (void)n_in; (void)out_size;
    const float* x  = (const float*)d_in[0];
    // d_in[1] is the causal mask — statically known, ignored
    const float* Wq = (const float*)d_in[2];
    const float* Wk = (const float*)d_in[3];
    const float* Wv = (const float*)d_in[4];
    const float* Wo = (const float*)d_in[5];
    float* out = (float*)d_out;

    float* Oscratch;
    cudaGetSymbolAddress((void**)&Oscratch, g_O);

    cudaFuncSetAttribute(qkv_mma_kernel,  cudaFuncAttributeMaxDynamicSharedMemorySize, SMEM_DYN);
    cudaFuncSetAttribute(proj_mma_kernel, cudaFuncAttributeMaxDynamicSharedMemorySize, SMEM_DYN);

    // 1. QKV projections (HMMA bf16x3)
    dim3 g1(DD / 128, MM / 128, 3);
    qkv_mma_kernel<<<g1, 256, SMEM_DYN>>>(x, Wq, Wk, Wv);

    // 2. causal flash attention (fp32 SIMT)
    dim3 g2(TT / ABM, BB * HH);
    attn_kernel<<<g2, ABM>>>(Oscratch);

    // 3. output projection (HMMA bf16x3)
    dim3 g3(DD / 128, MM / 128);
    proj_mma_kernel<<<g3, 256, SMEM_DYN>>>(Wo, out);
}

// round 4
// speedup vs baseline: 2.5956x; 1.8874x over previous
#include <cuda_runtime.h>
#include <cuda_bf16.h>
#include <math.h>
#include <stdint.h>

// Problem constants
constexpr int BB  = 2;
constexpr int TT  = 2048;
constexpr int DD  = 1024;
constexpr int HH  = 16;
constexpr int DHD = 64;          // head dim
constexpr int MM  = BB * TT;     // 4096 rows

// Scratch (device globals — no allocation allowed)
__device__ float g_Q[MM * DD];   // head-major [B,H,T,DH]
__device__ float g_K[MM * DD];   // head-major
__device__ float g_V[MM * DD];   // head-major
__device__ float g_O[MM * DD];   // token-major [B,T,D]

// ---------------------------------------------------------------------------
// mma.sync helpers (sm_80-baseline PTX — compiles for plain sm_103 target)
// ---------------------------------------------------------------------------
__device__ __forceinline__ void ldsm_x4(uint32_t& r0, uint32_t& r1,
                                        uint32_t& r2, uint32_t& r3, uint32_t addr) {
    asm volatile("ldmatrix.sync.aligned.m8n8.x4.shared.b16 {%0,%1,%2,%3}, [%4];"
                 : "=r"(r0), "=r"(r1), "=r"(r2), "=r"(r3) : "r"(addr));
}

__device__ __forceinline__ void mma_bf16(float* d, const uint32_t* a,
                                         uint32_t b0, uint32_t b1) {
    asm volatile(
        "mma.sync.aligned.m16n8k16.row.col.f32.bf16.bf16.f32 "
        "{%0,%1,%2,%3}, {%4,%5,%6,%7}, {%8,%9}, {%0,%1,%2,%3};"
        : "+f"(d[0]), "+f"(d[1]), "+f"(d[2]), "+f"(d[3])
        : "r"(a[0]), "r"(a[1]), "r"(a[2]), "r"(a[3]), "r"(b0), "r"(b1));
}

__device__ __forceinline__ uint32_t smem_to_u32(const void* p) {
    uint32_t a;
    asm("{ .reg .u64 t; cvta.to.shared.u64 t, %1; cvt.u32.u64 %0, t; }"
        : "=r"(a) : "l"(p));
    return a;
}

__device__ __forceinline__ uint32_t pack_bf2(__nv_bfloat16 a, __nv_bfloat16 b) {
    __nv_bfloat162 t = __halves2bfloat162(a, b);
    return *reinterpret_cast<uint32_t*>(&t);
}

// split 2 floats -> hi/lo bf16 pairs
__device__ __forceinline__ void split2(float f0, float f1, uint32_t& hw, uint32_t& lw) {
    __nv_bfloat16 h0 = __float2bfloat16(f0);
    __nv_bfloat16 h1 = __float2bfloat16(f1);
    __nv_bfloat16 l0 = __float2bfloat16(f0 - __bfloat162float(h0));
    __nv_bfloat16 l1 = __float2bfloat16(f1 - __bfloat162float(h1));
    hw = pack_bf2(h0, h1);
    lw = pack_bf2(l0, l1);
}

// ---------------------------------------------------------------------------
// HMMA GEMM: C[4096,1024] = A[4096,1024] @ W[1024,1024]  (unchanged from R3)
// ---------------------------------------------------------------------------
constexpr int BK    = 32;
constexpr int NITER = DD / BK;            // 32
constexpr int LDSM_ = 40;                 // padded row stride in bf16 elems (80B)
constexpr int OPB   = 128 * LDSM_ * 2;    // 10240 B per operand tile
constexpr int BUFB  = 4 * OPB;            // Ah, Al, Bh, Bl
constexpr int SMEM_DYN = 2 * BUFB;        // 81920 B

template <int MODE>
__device__ __forceinline__ void gemm_mma(const float* __restrict__ A,
                                         const float* __restrict__ Bm,
                                         float* __restrict__ C,
                                         int bx, int by)
{
    extern __shared__ char smem[];
    const int tid  = threadIdx.x;
    const int lane = tid & 31;
    const int wid  = tid >> 5;
    const int wm   = wid >> 2;
    const int wn   = wid & 3;
    const int m0 = by * 128, n0 = bx * 128;

    float acc[4][4][4];
#pragma unroll
    for (int i = 0; i < 4; i++)
#pragma unroll
        for (int j = 0; j < 4; j++)
#pragma unroll
            for (int k = 0; k < 4; k++) acc[i][j][k] = 0.0f;

    const int a_row = tid >> 1;
    const int a_kg  = (tid & 1) * 16;
    const int b_n   = tid & 127;
    const int b_kg  = (tid >> 7) * 16;

    auto load_gmem = [&](int k0, float* af, float* bf) {
        const float* ap = A + (size_t)(m0 + a_row) * DD + k0 + a_kg;
#pragma unroll
        for (int j = 0; j < 4; j++)
            *reinterpret_cast<float4*>(af + 4 * j) = *reinterpret_cast<const float4*>(ap + 4 * j);
        const float* bp = Bm + (size_t)(k0 + b_kg) * DD + n0 + b_n;
#pragma unroll
        for (int j = 0; j < 16; j++)
            bf[j] = bp[(size_t)j * DD];
    };

    auto store_smem = [&](int b, const float* af, const float* bf) {
        char* Ah = smem + b * BUFB;
        char* Al = Ah + OPB;
        char* Bh = Al + OPB;
        char* Bl = Bh + OPB;
        uint32_t hw[8], lw[8];
#pragma unroll
        for (int j = 0; j < 8; j++) split2(af[2 * j], af[2 * j + 1], hw[j], lw[j]);
        {
            char* p = Ah + (a_row * LDSM_ + a_kg) * 2;
            *reinterpret_cast<uint4*>(p)      = make_uint4(hw[0], hw[1], hw[2], hw[3]);
            *reinterpret_cast<uint4*>(p + 16) = make_uint4(hw[4], hw[5], hw[6], hw[7]);
            char* q = Al + (a_row * LDSM_ + a_kg) * 2;
            *reinterpret_cast<uint4*>(q)      = make_uint4(lw[0], lw[1], lw[2], lw[3]);
            *reinterpret_cast<uint4*>(q + 16) = make_uint4(lw[4], lw[5], lw[6], lw[7]);
        }
#pragma unroll
        for (int j = 0; j < 8; j++) split2(bf[2 * j], bf[2 * j + 1], hw[j], lw[j]);
        {
            char* p = Bh + (b_n * LDSM_ + b_kg) * 2;
            *reinterpret_cast<uint4*>(p)      = make_uint4(hw[0], hw[1], hw[2], hw[3]);
            *reinterpret_cast<uint4*>(p + 16) = make_uint4(hw[4], hw[5], hw[6], hw[7]);
            char* q = Bl + (b_n * LDSM_ + b_kg) * 2;
            *reinterpret_cast<uint4*>(q)      = make_uint4(lw[0], lw[1], lw[2], lw[3]);
            *reinterpret_cast<uint4*>(q + 16) = make_uint4(lw[4], lw[5], lw[6], lw[7]);
        }
    };

    const int ar = wm * 64 + (lane & 15);
    const int ac = (lane >> 4) * 8;
    const int br = wn * 32 + (lane & 15);
    const int bc = (lane >> 4) * 8;

    auto compute = [&](int b) {
        const uint32_t ah_b = smem_to_u32(smem + b * BUFB);
        const uint32_t al_b = ah_b + OPB;
        const uint32_t bh_b = al_b + OPB;
        const uint32_t bl_b = bh_b + OPB;
#pragma unroll
        for (int ks = 0; ks < 2; ks++) {
            uint32_t ah[4][4], al[4][4], bh[2][4], bl[2][4];
#pragma unroll
            for (int mf = 0; mf < 4; mf++) {
                const uint32_t off = (uint32_t)(((ar + mf * 16) * LDSM_ + ks * 16 + ac) * 2);
                ldsm_x4(ah[mf][0], ah[mf][1], ah[mf][2], ah[mf][3], ah_b + off);
                ldsm_x4(al[mf][0], al[mf][1], al[mf][2], al[mf][3], al_b + off);
            }
#pragma unroll
            for (int g = 0; g < 2; g++) {
                const uint32_t off = (uint32_t)(((br + g * 16) * LDSM_ + ks * 16 + bc) * 2);
                ldsm_x4(bh[g][0], bh[g][1], bh[g][2], bh[g][3], bh_b + off);
                ldsm_x4(bl[g][0], bl[g][1], bl[g][2], bl[g][3], bl_b + off);
            }
#pragma unroll
            for (int mf = 0; mf < 4; mf++)
#pragma unroll
                for (int g = 0; g < 2; g++)
#pragma unroll
                    for (int sub = 0; sub < 2; sub++) {
                        const int nf = g * 2 + sub;
                        mma_bf16(acc[mf][nf], ah[mf], bh[g][sub], bh[g][sub + 2]);
                        mma_bf16(acc[mf][nf], al[mf], bh[g][sub], bh[g][sub + 2]);
                        mma_bf16(acc[mf][nf], ah[mf], bl[g][sub], bl[g][sub + 2]);
                    }
        }
    };

    {
        float af[16], bf[16];
        load_gmem(0, af, bf);
        store_smem(0, af, bf);
    }
    __syncthreads();

    for (int it = 0; it < NITER; ++it) {
        const int b = it & 1;
        float af[16], bf[16];
        const bool pf = (it + 1 < NITER);
        if (pf) load_gmem((it + 1) * BK, af, bf);
        compute(b);
        if (pf) store_smem(b ^ 1, af, bf);
        __syncthreads();
    }

    const int group = lane >> 2;
    const int qd    = lane & 3;
#pragma unroll
    for (int mf = 0; mf < 4; mf++)
#pragma unroll
        for (int nf = 0; nf < 4; nf++) {
            const int rg = m0 + wm * 64 + mf * 16 + group;
            const int cg = n0 + wn * 32 + nf * 8 + qd * 2;
            float2 v0 = make_float2(acc[mf][nf][0], acc[mf][nf][1]);
            float2 v1 = make_float2(acc[mf][nf][2], acc[mf][nf][3]);
            if (MODE == 0) {
                const int bb = rg >> 11;
                const int t  = rg & 2047;
                const int h  = cg >> 6;
                const int dd = cg & 63;
                float* base = C + (((size_t)bb * HH + h) * TT) * DHD + dd;
                *reinterpret_cast<float2*>(base + (size_t)t * DHD)       = v0;
                *reinterpret_cast<float2*>(base + (size_t)(t + 8) * DHD) = v1;
            } else {
                *reinterpret_cast<float2*>(C + (size_t)rg * DD + cg)       = v0;
                *reinterpret_cast<float2*>(C + (size_t)(rg + 8) * DD + cg) = v1;
            }
        }
}

__global__ void __launch_bounds__(256)
qkv_mma_kernel(const float* __restrict__ x,
               const float* __restrict__ Wq,
               const float* __restrict__ Wk,
               const float* __restrict__ Wv)
{
    const int z = blockIdx.z;
    const float* W = (z == 0) ? Wq : (z == 1) ? Wk : Wv;
    float* C = (z == 0) ? g_Q : (z == 1) ? g_K : g_V;
    gemm_mma<0>(x, W, C, blockIdx.x, blockIdx.y);
}

__global__ void __launch_bounds__(256)
proj_mma_kernel(const float* __restrict__ Wo, float* __restrict__ out)
{
    gemm_mma<1>(g_O, Wo, out, blockIdx.x, blockIdx.y);
}

// ---------------------------------------------------------------------------
// HMMA flash attention (causal), bf16 3-term split, fp32 accumulate.
// Block: 128 queries of one (b,h). 8 warps, warp tile = 16 q rows x full keys.
// Key tiles of 64, double-buffered smem. Q hi/lo resident in smem.
// ---------------------------------------------------------------------------
constexpr int AST   = 72;                 // smem row stride (bf16 elems)
constexpr int AQOP  = 128 * AST * 2;      // 18432 B per Q operand (hi or lo)
constexpr int AKOP  = 64 * AST * 2;       // 9216 B per K/V operand
constexpr int AKVB  = 4 * AKOP;           // Kh,Kl,Vh,Vl = 36864 B
constexpr int AOFFK = 2 * AQOP;           // 36864
constexpr int SMEM_ATTN = AOFFK + 2 * AKVB;   // 110592 B

__global__ void __launch_bounds__(256)
attn_mma_kernel(float* __restrict__ O)
{
    extern __shared__ char smem[];
    const uint32_t sb = smem_to_u32(smem);
    const int bh  = blockIdx.y;
    const int bb  = bh / HH;
    const int h   = bh % HH;
    const int qt  = (int)gridDim.x - 1 - (int)blockIdx.x;   // big blocks first
    const int tid = threadIdx.x;
    const int lane = tid & 31;
    const int wq   = tid >> 5;            // warp id -> 16-row slab

    const float* Qbase = g_Q + ((size_t)bh * TT + qt * 128) * DHD;
    const float* Kbase = g_K + (size_t)bh * TT * DHD;
    const float* Vbase = g_V + (size_t)bh * TT * DHD;

    // ---- load Q once: scale, split, store hi/lo ----
    {
        const int row = tid >> 1;
        const int c0  = (tid & 1) * 32;
        const float4* src = reinterpret_cast<const float4*>(Qbase + (size_t)row * DHD + c0);
        float f[32];
#pragma unroll
        for (int j = 0; j < 8; j++)
            *reinterpret_cast<float4*>(f + 4 * j) = src[j];
#pragma unroll
        for (int j = 0; j < 32; j++) f[j] *= 0.125f;
        uint32_t hw[16], lw[16];
#pragma unroll
        for (int j = 0; j < 16; j++) split2(f[2 * j], f[2 * j + 1], hw[j], lw[j]);
        char* ph = smem + (row * AST + c0) * 2;
        char* pl = ph + AQOP;
#pragma unroll
        for (int j = 0; j < 4; j++) {
            *reinterpret_cast<uint4*>(ph + 16 * j) = make_uint4(hw[4*j], hw[4*j+1], hw[4*j+2], hw[4*j+3]);
            *reinterpret_cast<uint4*>(pl + 16 * j) = make_uint4(lw[4*j], lw[4*j+1], lw[4*j+2], lw[4*j+3]);
        }
    }

    // softmax state + O accumulator
    float accO[8][4];
#pragma unroll
    for (int i = 0; i < 8; i++)
#pragma unroll
        for (int j = 0; j < 4; j++) accO[i][j] = 0.0f;
    float mrow[2] = {-1e30f, -1e30f};
    float lrow[2] = {0.0f, 0.0f};

    const int qmin_w = qt * 128 + wq * 16;
    const int qmax_w = qmin_w + 15;
    const int r0loc  = qmin_w + (lane >> 2);   // this thread's first row (global)

    // KV loaders
    const int kv_row = tid & 63;
    const int kv_c0  = (tid >> 6) * 16;

    auto loadKV = [&](int jt, float4* kr, float4* vr) {
        const float4* K4 = reinterpret_cast<const float4*>(Kbase + (size_t)(jt * 64 + kv_row) * DHD + kv_c0);
        const float4* V4 = reinterpret_cast<const float4*>(Vbase + (size_t)(jt * 64 + kv_row) * DHD + kv_c0);
#pragma unroll
        for (int j = 0; j < 4; j++) { kr[j] = K4[j]; vr[j] = V4[j]; }
    };

    auto storeKV = [&](int b, const float4* kr, const float4* vr) {
        char* base = smem + AOFFK + b * AKVB;
        // K: natural [key][dh]
        {
            const float* f = reinterpret_cast<const float*>(kr);
            uint32_t hw[8], lw[8];
#pragma unroll
            for (int j = 0; j < 8; j++) split2(f[2*j], f[2*j+1], hw[j], lw[j]);
            char* ph = base + (kv_row * AST + kv_c0) * 2;
            char* pl = ph + AKOP;
            *reinterpret_cast<uint4*>(ph)      = make_uint4(hw[0], hw[1], hw[2], hw[3]);
            *reinterpret_cast<uint4*>(ph + 16) = make_uint4(hw[4], hw[5], hw[6], hw[7]);
            *reinterpret_cast<uint4*>(pl)      = make_uint4(lw[0], lw[1], lw[2], lw[3]);
            *reinterpret_cast<uint4*>(pl + 16) = make_uint4(lw[4], lw[5], lw[6], lw[7]);
        }
        // V: transposed [dh][key]
        {
            const float* f = reinterpret_cast<const float*>(vr);
            __nv_bfloat16* ph = reinterpret_cast<__nv_bfloat16*>(base + 2 * AKOP);
            __nv_bfloat16* pl = reinterpret_cast<__nv_bfloat16*>(base + 3 * AKOP);
#pragma unroll
            for (int j = 0; j < 16; j++) {
                const float v = f[j];
                __nv_bfloat16 vh = __float2bfloat16(v);
                __nv_bfloat16 vl = __float2bfloat16(v - __bfloat162float(vh));
                const int idx = (kv_c0 + j) * AST + kv_row;
                ph[idx] = vh;
                pl[idx] = vl;
            }
        }
    };

    // fragment addressing (same convention validated in the GEMM)
    const int fr = lane & 15;
    const int fc = (lane >> 4) * 8;

    auto compute = [&](int jt, int b) {
        const int key0 = jt * 64;
        if (key0 > qmax_w) return;                 // fully masked for this warp
        const uint32_t kvb = sb + AOFFK + b * AKVB;
        const uint32_t qhb = sb;
        const uint32_t qlb = sb + AQOP;

        // ---- S = Q K^T ----
        float accS[8][4];
#pragma unroll
        for (int i = 0; i < 8; i++)
#pragma unroll
            for (int j = 0; j < 4; j++) accS[i][j] = 0.0f;

#pragma unroll
        for (int ks = 0; ks < 4; ks++) {
            uint32_t qh[4], ql[4];
            const uint32_t qoff = (uint32_t)(((wq * 16 + fr) * AST + ks * 16 + fc) * 2);
            ldsm_x4(qh[0], qh[1], qh[2], qh[3], qhb + qoff);
            ldsm_x4(ql[0], ql[1], ql[2], ql[3], qlb + qoff);
#pragma unroll
            for (int g = 0; g < 4; g++) {
                uint32_t kh[4], kl[4];
                const uint32_t koff = (uint32_t)(((g * 16 + fr) * AST + ks * 16 + fc) * 2);
                ldsm_x4(kh[0], kh[1], kh[2], kh[3], kvb + koff);
                ldsm_x4(kl[0], kl[1], kl[2], kl[3], kvb + AKOP + koff);
#pragma unroll
                for (int sub = 0; sub < 2; sub++) {
                    const int nf = g * 2 + sub;
                    mma_bf16(accS[nf], qh, kh[sub], kh[sub + 2]);
                    mma_bf16(accS[nf], ql, kh[sub], kh[sub + 2]);
                    mma_bf16(accS[nf], qh, kl[sub], kl[sub + 2]);
                }
            }
        }

        // ---- causal mask (diagonal tiles only) ----
        if (key0 + 63 > qmin_w) {
            const int r1loc = r0loc + 8;
#pragma unroll
            for (int nf = 0; nf < 8; nf++) {
                const int c = key0 + nf * 8 + 2 * (lane & 3);
                if (c     > r0loc) accS[nf][0] = -1e30f;
                if (c + 1 > r0loc) accS[nf][1] = -1e30f;
                if (c     > r1loc) accS[nf][2] = -1e30f;
                if (c + 1 > r1loc) accS[nf][3] = -1e30f;
            }
        }

        // ---- online softmax ----
        float ml0 = -1e30f, ml1 = -1e30f;
#pragma unroll
        for (int nf = 0; nf < 8; nf++) {
            ml0 = fmaxf(ml0, fmaxf(accS[nf][0], accS[nf][1]));
            ml1 = fmaxf(ml1, fmaxf(accS[nf][2], accS[nf][3]));
        }
        ml0 = fmaxf(ml0, __shfl_xor_sync(0xffffffffu, ml0, 1));
        ml0 = fmaxf(ml0, __shfl_xor_sync(0xffffffffu, ml0, 2));
        ml1 = fmaxf(ml1, __shfl_xor_sync(0xffffffffu, ml1, 1));
        ml1 = fmaxf(ml1, __shfl_xor_sync(0xffffffffu, ml1, 2));
        const float mn0 = fmaxf(mrow[0], ml0);
        const float mn1 = fmaxf(mrow[1], ml1);
        const float corr0 = __expf(mrow[0] - mn0);
        const float corr1 = __expf(mrow[1] - mn1);
        mrow[0] = mn0; mrow[1] = mn1;

        float ls0 = 0.0f, ls1 = 0.0f;
#pragma unroll
        for (int nf = 0; nf < 8; nf++) {
            accS[nf][0] = __expf(accS[nf][0] - mn0);
            accS[nf][1] = __expf(accS[nf][1] - mn0);
            accS[nf][2] = __expf(accS[nf][2] - mn1);
            accS[nf][3] = __expf(accS[nf][3] - mn1);
            ls0 += accS[nf][0] + accS[nf][1];
            ls1 += accS[nf][2] + accS[nf][3];
        }
        ls0 += __shfl_xor_sync(0xffffffffu, ls0, 1);
        ls0 += __shfl_xor_sync(0xffffffffu, ls0, 2);
        ls1 += __shfl_xor_sync(0xffffffffu, ls1, 1);
        ls1 += __shfl_xor_sync(0xffffffffu, ls1, 2);
        lrow[0] = lrow[0] * corr0 + ls0;
        lrow[1] = lrow[1] * corr1 + ls1;

#pragma unroll
        for (int nf = 0; nf < 8; nf++) {
            accO[nf][0] *= corr0; accO[nf][1] *= corr0;
            accO[nf][2] *= corr1; accO[nf][3] *= corr1;
        }

        // ---- split P into hi/lo fragments ----
        uint32_t p01h[8], p01l[8], p23h[8], p23l[8];
#pragma unroll
        for (int nf = 0; nf < 8; nf++) {
            split2(accS[nf][0], accS[nf][1], p01h[nf], p01l[nf]);
            split2(accS[nf][2], accS[nf][3], p23h[nf], p23l[nf]);
        }

        // ---- O += P V ----
#pragma unroll
        for (int kp = 0; kp < 4; kp++) {
            uint32_t ah[4] = {p01h[2*kp], p23h[2*kp], p01h[2*kp+1], p23h[2*kp+1]};
            uint32_t al[4] = {p01l[2*kp], p23l[2*kp], p01l[2*kp+1], p23l[2*kp+1]};
#pragma unroll
            for (int vg = 0; vg < 4; vg++) {
                uint32_t vh[4], vl[4];
                const uint32_t voff = (uint32_t)(((vg * 16 + fr) * AST + kp * 16 + fc) * 2);
                ldsm_x4(vh[0], vh[1], vh[2], vh[3], kvb + 2 * AKOP + voff);
                ldsm_x4(vl[0], vl[1], vl[2], vl[3], kvb + 3 * AKOP + voff);
#pragma unroll
                for (int sub = 0; sub < 2; sub++) {
                    const int nf = vg * 2 + sub;
                    mma_bf16(accO[nf], ah, vh[sub], vh[sub + 2]);
                    mma_bf16(accO[nf], al, vh[sub], vh[sub + 2]);
                    mma_bf16(accO[nf], ah, vl[sub], vl[sub + 2]);
                }
            }
        }
    };

    // ---- mainloop: double-buffered KV ----
    const int ntiles = 2 * (qt + 1);
    {
        float4 kr[4], vr[4];
        loadKV(0, kr, vr);
        storeKV(0, kr, vr);
    }
    __syncthreads();

    for (int jt = 0; jt < ntiles; jt++) {
        const int b = jt & 1;
        float4 kr[4], vr[4];
        const bool pf = (jt + 1 < ntiles);
        if (pf) loadKV(jt + 1, kr, vr);
        compute(jt, b);
        if (pf) storeKV(b ^ 1, kr, vr);
        __syncthreads();
    }

    // ---- epilogue: normalize + write token-major ----
    const float inv0 = 1.0f / lrow[0];
    const float inv1 = 1.0f / lrow[1];
    const int q0 = qt * 128 + wq * 16 + (lane >> 2);
    const int q1 = q0 + 8;
#pragma unroll
    for (int nf = 0; nf < 8; nf++) {
        const int col = h * DHD + nf * 8 + 2 * (lane & 3);
        *reinterpret_cast<float2*>(O + ((size_t)bb * TT + q0) * DD + col) =
            make_float2(accO[nf][0] * inv0, accO[nf][1] * inv0);
        *reinterpret_cast<float2*>(O + ((size_t)bb * TT + q1) * DD + col) =
            make_float2(accO[nf][2] * inv1, accO[nf][3] * inv1);
    }
}

// ---------------------------------------------------------------------------
extern "C" void kernel_launch(void* const* d_in, const int* in_sizes, int n_in,
                              void* d_out, int out_size)
{
    (void)in_sizes; (void)n_in; (void)out_size;
    const float* x  = (const float*)d_in[0];
    // d_in[1] is the causal mask — statically known, ignored
    const float* Wq = (const float*)d_in[2];
    const float* Wk = (const float*)d_in[3];
    const float* Wv = (const float*)d_in[4];
    const float* Wo = (const float*)d_in[5];
    float* out = (float*)d_out;

    float* Oscratch;
    cudaGetSymbolAddress((void**)&Oscratch, g_O);

    cudaFuncSetAttribute(qkv_mma_kernel,  cudaFuncAttributeMaxDynamicSharedMemorySize, SMEM_DYN);
    cudaFuncSetAttribute(proj_mma_kernel, cudaFuncAttributeMaxDynamicSharedMemorySize, SMEM_DYN);
    cudaFuncSetAttribute(attn_mma_kernel, cudaFuncAttributeMaxDynamicSharedMemorySize, SMEM_ATTN);

    // 1. QKV projections (HMMA bf16x3)
    dim3 g1(DD / 128, MM / 128, 3);
    qkv_mma_kernel<<<g1, 256, SMEM_DYN>>>(x, Wq, Wk, Wv);

    // 2. causal flash attention (HMMA bf16x3)
    dim3 g2(TT / 128, BB * HH);
    attn_mma_kernel<<<g2, 256, SMEM_ATTN>>>(Oscratch);

    // 3. output projection (HMMA bf16x3)
    dim3 g3(DD / 128, MM / 128);
    proj_mma_kernel<<<g3, 256, SMEM_DYN>>>(Wo, out);
}

// round 5
// speedup vs baseline: 2.8330x; 1.0915x over previous
#include <cuda_runtime.h>
#include <cuda_bf16.h>
#include <math.h>
#include <stdint.h>

// Problem constants
constexpr int BB  = 2;
constexpr int TT  = 2048;
constexpr int DD  = 1024;
constexpr int HH  = 16;
constexpr int DHD = 64;
constexpr int MM  = BB * TT;     // 4096

// Pre-split bf16 scratch (device globals)
__device__ __nv_bfloat16 g_xh[MM * DD], g_xl[MM * DD];            // x hi/lo [M][K]
__device__ __nv_bfloat16 g_Wth[4 * DD * DD], g_Wtl[4 * DD * DD];  // W^T hi/lo [N][K] (q,k,v,o; Wq pre-scaled)
__device__ __nv_bfloat16 g_Qh[MM * DD], g_Ql[MM * DD];            // head-major [B,H,T,DH]
__device__ __nv_bfloat16 g_Kh[MM * DD], g_Kl[MM * DD];
__device__ __nv_bfloat16 g_Vh[MM * DD], g_Vl[MM * DD];
__device__ __nv_bfloat16 g_Oh[MM * DD], g_Ol[MM * DD];            // token-major [B,T,D]

// ---------------------------------------------------------------------------
// PTX helpers (sm_80-baseline — compiles for plain sm_103 target)
// ---------------------------------------------------------------------------
__device__ __forceinline__ void ldsm_x4(uint32_t& r0, uint32_t& r1,
                                        uint32_t& r2, uint32_t& r3, uint32_t addr) {
    asm volatile("ldmatrix.sync.aligned.m8n8.x4.shared.b16 {%0,%1,%2,%3}, [%4];"
                 : "=r"(r0), "=r"(r1), "=r"(r2), "=r"(r3) : "r"(addr));
}

__device__ __forceinline__ void mma_bf16(float* d, const uint32_t* a,
                                         uint32_t b0, uint32_t b1) {
    asm volatile(
        "mma.sync.aligned.m16n8k16.row.col.f32.bf16.bf16.f32 "
        "{%0,%1,%2,%3}, {%4,%5,%6,%7}, {%8,%9}, {%0,%1,%2,%3};"
        : "+f"(d[0]), "+f"(d[1]), "+f"(d[2]), "+f"(d[3])
        : "r"(a[0]), "r"(a[1]), "r"(a[2]), "r"(a[3]), "r"(b0), "r"(b1));
}

__device__ __forceinline__ uint32_t smem_to_u32(const void* p) {
    uint32_t a;
    asm("{ .reg .u64 t; cvta.to.shared.u64 t, %1; cvt.u32.u64 %0, t; }"
        : "=r"(a) : "l"(p));
    return a;
}

__device__ __forceinline__ void cp_async16(uint32_t dst, const void* src) {
    asm volatile("cp.async.cg.shared.global [%0], [%1], 16;" :: "r"(dst), "l"(src));
}
#define CP_COMMIT() asm volatile("cp.async.commit_group;" ::: "memory")
#define CP_WAIT0()  asm volatile("cp.async.wait_group 0;"  ::: "memory")

__device__ __forceinline__ uint32_t pack_bf2(__nv_bfloat16 a, __nv_bfloat16 b) {
    __nv_bfloat162 t = __halves2bfloat162(a, b);
    return *reinterpret_cast<uint32_t*>(&t);
}

__device__ __forceinline__ void split2(float f0, float f1, uint32_t& hw, uint32_t& lw) {
    __nv_bfloat16 h0 = __float2bfloat16(f0);
    __nv_bfloat16 h1 = __float2bfloat16(f1);
    __nv_bfloat16 l0 = __float2bfloat16(f0 - __bfloat162float(h0));
    __nv_bfloat16 l1 = __float2bfloat16(f1 - __bfloat162float(h1));
    hw = pack_bf2(h0, h1);
    lw = pack_bf2(l0, l1);
}

// ---------------------------------------------------------------------------
// Prep kernels: split once per element.
// ---------------------------------------------------------------------------
__global__ void __launch_bounds__(256)
prep_split_x(const float* __restrict__ x)
{
    const size_t i = ((size_t)blockIdx.x * 256 + threadIdx.x) * 8;
    float4 f0 = *reinterpret_cast<const float4*>(x + i);
    float4 f1 = *reinterpret_cast<const float4*>(x + i + 4);
    uint32_t h[4], l[4];
    split2(f0.x, f0.y, h[0], l[0]); split2(f0.z, f0.w, h[1], l[1]);
    split2(f1.x, f1.y, h[2], l[2]); split2(f1.z, f1.w, h[3], l[3]);
    *reinterpret_cast<uint4*>(g_xh + i) = make_uint4(h[0], h[1], h[2], h[3]);
    *reinterpret_cast<uint4*>(g_xl + i) = make_uint4(l[0], l[1], l[2], l[3]);
}

// transpose + split W[k][n] -> Wt[n][k]; z selects matrix; Wq scaled by 0.125
__global__ void __launch_bounds__(256)
prep_wt(const float* __restrict__ Wq, const float* __restrict__ Wk,
        const float* __restrict__ Wv, const float* __restrict__ Wo)
{
    const int z = blockIdx.z;
    const float* W = (z == 0) ? Wq : (z == 1) ? Wk : (z == 2) ? Wv : Wo;
    const float scale = (z == 0) ? 0.125f : 1.0f;
    __shared__ float tile[32][33];
    const int k0 = blockIdx.y * 32, n0 = blockIdx.x * 32;
    const int tx = threadIdx.x & 31, ty = threadIdx.x >> 5;   // 32x8
#pragma unroll
    for (int r = 0; r < 32; r += 8)
        tile[ty + r][tx] = W[(size_t)(k0 + ty + r) * DD + n0 + tx];
    __syncthreads();
    __nv_bfloat16* Th = g_Wth + (size_t)z * DD * DD;
    __nv_bfloat16* Tl = g_Wtl + (size_t)z * DD * DD;
#pragma unroll
    for (int r = 0; r < 32; r += 8) {
        const int n = n0 + ty + r, k = k0 + tx;
        const float v = tile[tx][ty + r] * scale;
        __nv_bfloat16 h = __float2bfloat16(v);
        __nv_bfloat16 l = __float2bfloat16(v - __bfloat162float(h));
        Th[(size_t)n * DD + k] = h;
        Tl[(size_t)n * DD + k] = l;
    }
}

// ---------------------------------------------------------------------------
// Pure-bf16 HMMA GEMM (pre-split operands), cp.async double-buffered.
// C = A @ B^T with A[M][K] hi/lo, B[N][K] hi/lo. 3-term split accumulate.
// MODE 0: epilogue splits + stores bf16 hi/lo head-major (QKV).
// MODE 1: epilogue stores fp32 row-major (final output).
// ---------------------------------------------------------------------------
constexpr int BK   = 32;
constexpr int NITER = DD / BK;          // 32
constexpr int GST  = 40;                // padded row stride (bf16)
constexpr int GOP  = 128 * GST * 2;     // 10240 B
constexpr int GBUF = 4 * GOP;           // Ah, Al, Bh, Bl
constexpr int SMEM_GEMM = 2 * GBUF;     // 81920 B

template <int MODE>
__device__ __forceinline__ void gemm_core(const __nv_bfloat16* __restrict__ Ah_g,
                                          const __nv_bfloat16* __restrict__ Al_g,
                                          const __nv_bfloat16* __restrict__ Bh_g,
                                          const __nv_bfloat16* __restrict__ Bl_g,
                                          float* __restrict__ Cf,
                                          __nv_bfloat16* __restrict__ Ch,
                                          __nv_bfloat16* __restrict__ Cl,
                                          int bx, int by)
{
    extern __shared__ char smem[];
    const uint32_t sb = smem_to_u32(smem);
    const int tid  = threadIdx.x;
    const int lane = tid & 31;
    const int wid  = tid >> 5;
    const int wm   = wid >> 2;
    const int wn   = wid & 3;
    const int m0 = by * 128, n0 = bx * 128;

    float acc[4][4][4];
#pragma unroll
    for (int i = 0; i < 4; i++)
#pragma unroll
        for (int j = 0; j < 4; j++)
#pragma unroll
            for (int k = 0; k < 4; k++) acc[i][j][k] = 0.0f;

    auto issue = [&](int b, int k0) {
        const uint32_t base = sb + b * GBUF;
#pragma unroll
        for (int r = 0; r < 2; r++) {
            const int idx = tid + r * 256;
            const int row = idx >> 2;
            const int c   = idx & 3;
            const uint32_t soff = (uint32_t)(row * GST + c * 8) * 2;
            const size_t ga = (size_t)(m0 + row) * DD + k0 + c * 8;
            const size_t gb = (size_t)(n0 + row) * DD + k0 + c * 8;
            cp_async16(base + soff,           Ah_g + ga);
            cp_async16(base + GOP + soff,     Al_g + ga);
            cp_async16(base + 2 * GOP + soff, Bh_g + gb);
            cp_async16(base + 3 * GOP + soff, Bl_g + gb);
        }
        CP_COMMIT();
    };

    const int ar = wm * 64 + (lane & 15);
    const int ac = (lane >> 4) * 8;
    const int br = wn * 32 + (lane & 15);
    const int bc = (lane >> 4) * 8;

    auto compute = [&](int b) {
        const uint32_t ah_b = sb + b * GBUF;
        const uint32_t al_b = ah_b + GOP;
        const uint32_t bh_b = al_b + GOP;
        const uint32_t bl_b = bh_b + GOP;
#pragma unroll
        for (int ks = 0; ks < 2; ks++) {
            uint32_t ah[4][4], al[4][4], bh[2][4], bl[2][4];
#pragma unroll
            for (int mf = 0; mf < 4; mf++) {
                const uint32_t off = (uint32_t)(((ar + mf * 16) * GST + ks * 16 + ac) * 2);
                ldsm_x4(ah[mf][0], ah[mf][1], ah[mf][2], ah[mf][3], ah_b + off);
                ldsm_x4(al[mf][0], al[mf][1], al[mf][2], al[mf][3], al_b + off);
            }
#pragma unroll
            for (int g = 0; g < 2; g++) {
                const uint32_t off = (uint32_t)(((br + g * 16) * GST + ks * 16 + bc) * 2);
                ldsm_x4(bh[g][0], bh[g][1], bh[g][2], bh[g][3], bh_b + off);
                ldsm_x4(bl[g][0], bl[g][1], bl[g][2], bl[g][3], bl_b + off);
            }
#pragma unroll
            for (int mf = 0; mf < 4; mf++)
#pragma unroll
                for (int g = 0; g < 2; g++)
#pragma unroll
                    for (int sub = 0; sub < 2; sub++) {
                        const int nf = g * 2 + sub;
                        mma_bf16(acc[mf][nf], ah[mf], bh[g][sub], bh[g][sub + 2]);
                        mma_bf16(acc[mf][nf], al[mf], bh[g][sub], bh[g][sub + 2]);
                        mma_bf16(acc[mf][nf], ah[mf], bl[g][sub], bl[g][sub + 2]);
                    }
        }
    };

    issue(0, 0);
    for (int it = 0; it < NITER; ++it) {
        const int b = it & 1;
        CP_WAIT0();
        __syncthreads();
        if (it + 1 < NITER) issue(b ^ 1, (it + 1) * BK);
        compute(b);
    }

    const int group = lane >> 2;
    const int qd    = lane & 3;
#pragma unroll
    for (int mf = 0; mf < 4; mf++)
#pragma unroll
        for (int nf = 0; nf < 4; nf++) {
            const int rg = m0 + wm * 64 + mf * 16 + group;
            const int cg = n0 + wn * 32 + nf * 8 + qd * 2;
            if (MODE == 0) {
                const int bbi = rg >> 11;
                const int t   = rg & 2047;
                const int h   = cg >> 6;
                const int dd  = cg & 63;
                const size_t i0 = (((size_t)bbi * HH + h) * TT + t) * DHD + dd;
                const size_t i1 = i0 + (size_t)8 * DHD;
                uint32_t hw, lw;
                split2(acc[mf][nf][0], acc[mf][nf][1], hw, lw);
                *reinterpret_cast<uint32_t*>(Ch + i0) = hw;
                *reinterpret_cast<uint32_t*>(Cl + i0) = lw;
                split2(acc[mf][nf][2], acc[mf][nf][3], hw, lw);
                *reinterpret_cast<uint32_t*>(Ch + i1) = hw;
                *reinterpret_cast<uint32_t*>(Cl + i1) = lw;
            } else {
                *reinterpret_cast<float2*>(Cf + (size_t)rg * DD + cg) =
                    make_float2(acc[mf][nf][0], acc[mf][nf][1]);
                *reinterpret_cast<float2*>(Cf + (size_t)(rg + 8) * DD + cg) =
                    make_float2(acc[mf][nf][2], acc[mf][nf][3]);
            }
        }
}

__global__ void __launch_bounds__(256)
qkv_mma_kernel()
{
    const int z = blockIdx.z;
    const __nv_bfloat16* Bh = g_Wth + (size_t)z * DD * DD;
    const __nv_bfloat16* Bl = g_Wtl + (size_t)z * DD * DD;
    __nv_bfloat16* Ch = (z == 0) ? g_Qh : (z == 1) ? g_Kh : g_Vh;
    __nv_bfloat16* Cl = (z == 0) ? g_Ql : (z == 1) ? g_Kl : g_Vl;
    gemm_core<0>(g_xh, g_xl, Bh, Bl, nullptr, Ch, Cl, blockIdx.x, blockIdx.y);
}

__global__ void __launch_bounds__(256)
proj_mma_kernel(float* __restrict__ out)
{
    gemm_core<1>(g_Oh, g_Ol, g_Wth + (size_t)3 * DD * DD, g_Wtl + (size_t)3 * DD * DD,
                 out, nullptr, nullptr, blockIdx.x, blockIdx.y);
}

// ---------------------------------------------------------------------------
// HMMA flash attention (causal), pre-split bf16 inputs, fp32 accumulate.
// ---------------------------------------------------------------------------
constexpr int AST   = 72;
constexpr int AQOP  = 128 * AST * 2;
constexpr int AKOP  = 64 * AST * 2;
constexpr int AKVB  = 4 * AKOP;
constexpr int AOFFK = 2 * AQOP;
constexpr int SMEM_ATTN = AOFFK + 2 * AKVB;   // 110592 B

__global__ void __launch_bounds__(256)
attn_mma_kernel()
{
    extern __shared__ char smem[];
    const uint32_t sb = smem_to_u32(smem);
    const int bh  = blockIdx.y;
    const int bbi = bh / HH;
    const int h   = bh % HH;
    const int qt  = (int)gridDim.x - 1 - (int)blockIdx.x;
    const int tid = threadIdx.x;
    const int lane = tid & 31;
    const int wq   = tid >> 5;

    const size_t headoff = (size_t)bh * TT * DHD;

    // ---- Q resident: straight copy of pre-split rows ----
    {
        const int row = tid >> 1;
        const int c0  = (tid & 1) * 32;
        const size_t src = headoff + (size_t)(qt * 128 + row) * DHD + c0;
        const uint4* shq = reinterpret_cast<const uint4*>(g_Qh + src);
        const uint4* slq = reinterpret_cast<const uint4*>(g_Ql + src);
        char* ph = smem + (row * AST + c0) * 2;
        char* pl = ph + AQOP;
#pragma unroll
        for (int j = 0; j < 4; j++) {
            *reinterpret_cast<uint4*>(ph + 16 * j) = shq[j];
            *reinterpret_cast<uint4*>(pl + 16 * j) = slq[j];
        }
    }

    float accO[8][4];
#pragma unroll
    for (int i = 0; i < 8; i++)
#pragma unroll
        for (int j = 0; j < 4; j++) accO[i][j] = 0.0f;
    float mrow[2] = {-1e30f, -1e30f};
    float lrow[2] = {0.0f, 0.0f};

    const int qmin_w = qt * 128 + wq * 16;
    const int qmax_w = qmin_w + 15;
    const int r0loc  = qmin_w + (lane >> 2);

    const int kv_row = tid & 63;
    const int kv_c0  = (tid >> 6) * 16;

    auto loadKV = [&](int jt, uint4* kh, uint4* kl, uint4* vh, uint4* vl) {
        const size_t src = headoff + (size_t)(jt * 64 + kv_row) * DHD + kv_c0;
        const uint4* p;
        p = reinterpret_cast<const uint4*>(g_Kh + src); kh[0] = p[0]; kh[1] = p[1];
        p = reinterpret_cast<const uint4*>(g_Kl + src); kl[0] = p[0]; kl[1] = p[1];
        p = reinterpret_cast<const uint4*>(g_Vh + src); vh[0] = p[0]; vh[1] = p[1];
        p = reinterpret_cast<const uint4*>(g_Vl + src); vl[0] = p[0]; vl[1] = p[1];
    };

    auto storeKV = [&](int b, const uint4* kh, const uint4* kl,
                       const uint4* vh, const uint4* vl) {
        char* base = smem + AOFFK + b * AKVB;
        char* pk = base + (kv_row * AST + kv_c0) * 2;
        *reinterpret_cast<uint4*>(pk)             = kh[0];
        *reinterpret_cast<uint4*>(pk + 16)        = kh[1];
        *reinterpret_cast<uint4*>(pk + AKOP)      = kl[0];
        *reinterpret_cast<uint4*>(pk + AKOP + 16) = kl[1];
        // V transposed [dh][key]
        __nv_bfloat16* ph = reinterpret_cast<__nv_bfloat16*>(base + 2 * AKOP);
        __nv_bfloat16* pl = reinterpret_cast<__nv_bfloat16*>(base + 3 * AKOP);
        const __nv_bfloat16* vhp = reinterpret_cast<const __nv_bfloat16*>(vh);
        const __nv_bfloat16* vlp = reinterpret_cast<const __nv_bfloat16*>(vl);
#pragma unroll
        for (int j = 0; j < 16; j++) {
            const int idx = (kv_c0 + j) * AST + kv_row;
            ph[idx] = vhp[j];
            pl[idx] = vlp[j];
        }
    };

    const int fr = lane & 15;
    const int fc = (lane >> 4) * 8;

    auto compute = [&](int jt, int b) {
        const int key0 = jt * 64;
        if (key0 > qmax_w) return;
        const uint32_t kvb = sb + AOFFK + b * AKVB;
        const uint32_t qhb = sb;
        const uint32_t qlb = sb + AQOP;

        float accS[8][4];
#pragma unroll
        for (int i = 0; i < 8; i++)
#pragma unroll
            for (int j = 0; j < 4; j++) accS[i][j] = 0.0f;

#pragma unroll
        for (int ks = 0; ks < 4; ks++) {
            uint32_t qh[4], ql[4];
            const uint32_t qoff = (uint32_t)(((wq * 16 + fr) * AST + ks * 16 + fc) * 2);
            ldsm_x4(qh[0], qh[1], qh[2], qh[3], qhb + qoff);
            ldsm_x4(ql[0], ql[1], ql[2], ql[3], qlb + qoff);
#pragma unroll
            for (int g = 0; g < 4; g++) {
                uint32_t kh[4], kl[4];
                const uint32_t koff = (uint32_t)(((g * 16 + fr) * AST + ks * 16 + fc) * 2);
                ldsm_x4(kh[0], kh[1], kh[2], kh[3], kvb + koff);
                ldsm_x4(kl[0], kl[1], kl[2], kl[3], kvb + AKOP + koff);
#pragma unroll
                for (int sub = 0; sub < 2; sub++) {
                    const int nf = g * 2 + sub;
                    mma_bf16(accS[nf], qh, kh[sub], kh[sub + 2]);
                    mma_bf16(accS[nf], ql, kh[sub], kh[sub + 2]);
                    mma_bf16(accS[nf], qh, kl[sub], kl[sub + 2]);
                }
            }
        }

        if (key0 + 63 > qmin_w) {
            const int r1loc = r0loc + 8;
#pragma unroll
            for (int nf = 0; nf < 8; nf++) {
                const int c = key0 + nf * 8 + 2 * (lane & 3);
                if (c     > r0loc) accS[nf][0] = -1e30f;
                if (c + 1 > r0loc) accS[nf][1] = -1e30f;
                if (c     > r1loc) accS[nf][2] = -1e30f;
                if (c + 1 > r1loc) accS[nf][3] = -1e30f;
            }
        }

        float ml0 = -1e30f, ml1 = -1e30f;
#pragma unroll
        for (int nf = 0; nf < 8; nf++) {
            ml0 = fmaxf(ml0, fmaxf(accS[nf][0], accS[nf][1]));
            ml1 = fmaxf(ml1, fmaxf(accS[nf][2], accS[nf][3]));
        }
        ml0 = fmaxf(ml0, __shfl_xor_sync(0xffffffffu, ml0, 1));
        ml0 = fmaxf(ml0, __shfl_xor_sync(0xffffffffu, ml0, 2));
        ml1 = fmaxf(ml1, __shfl_xor_sync(0xffffffffu, ml1, 1));
        ml1 = fmaxf(ml1, __shfl_xor_sync(0xffffffffu, ml1, 2));
        const float mn0 = fmaxf(mrow[0], ml0);
        const float mn1 = fmaxf(mrow[1], ml1);
        const float corr0 = __expf(mrow[0] - mn0);
        const float corr1 = __expf(mrow[1] - mn1);
        mrow[0] = mn0; mrow[1] = mn1;

        float ls0 = 0.0f, ls1 = 0.0f;
#pragma unroll
        for (int nf = 0; nf < 8; nf++) {
            accS[nf][0] = __expf(accS[nf][0] - mn0);
            accS[nf][1] = __expf(accS[nf][1] - mn0);
            accS[nf][2] = __expf(accS[nf][2] - mn1);
            accS[nf][3] = __expf(accS[nf][3] - mn1);
            ls0 += accS[nf][0] + accS[nf][1];
            ls1 += accS[nf][2] + accS[nf][3];
        }
        ls0 += __shfl_xor_sync(0xffffffffu, ls0, 1);
        ls0 += __shfl_xor_sync(0xffffffffu, ls0, 2);
        ls1 += __shfl_xor_sync(0xffffffffu, ls1, 1);
        ls1 += __shfl_xor_sync(0xffffffffu, ls1, 2);
        lrow[0] = lrow[0] * corr0 + ls0;
        lrow[1] = lrow[1] * corr1 + ls1;

#pragma unroll
        for (int nf = 0; nf < 8; nf++) {
            accO[nf][0] *= corr0; accO[nf][1] *= corr0;
            accO[nf][2] *= corr1; accO[nf][3] *= corr1;
        }

        uint32_t p01h[8], p01l[8], p23h[8], p23l[8];
#pragma unroll
        for (int nf = 0; nf < 8; nf++) {
            split2(accS[nf][0], accS[nf][1], p01h[nf], p01l[nf]);
            split2(accS[nf][2], accS[nf][3], p23h[nf], p23l[nf]);
        }

#pragma unroll
        for (int kp = 0; kp < 4; kp++) {
            uint32_t ah[4] = {p01h[2*kp], p23h[2*kp], p01h[2*kp+1], p23h[2*kp+1]};
            uint32_t al[4] = {p01l[2*kp], p23l[2*kp], p01l[2*kp+1], p23l[2*kp+1]};
#pragma unroll
            for (int vg = 0; vg < 4; vg++) {
                uint32_t vh[4], vl[4];
                const uint32_t voff = (uint32_t)(((vg * 16 + fr) * AST + kp * 16 + fc) * 2);
                ldsm_x4(vh[0], vh[1], vh[2], vh[3], kvb + 2 * AKOP + voff);
                ldsm_x4(vl[0], vl[1], vl[2], vl[3], kvb + 3 * AKOP + voff);
#pragma unroll
                for (int sub = 0; sub < 2; sub++) {
                    const int nf = vg * 2 + sub;
                    mma_bf16(accO[nf], ah, vh[sub], vh[sub + 2]);
                    mma_bf16(accO[nf], al, vh[sub], vh[sub + 2]);
                    mma_bf16(accO[nf], ah, vl[sub], vl[sub + 2]);
                }
            }
        }
    };

    const int ntiles = 2 * (qt + 1);
    {
        uint4 kh[2], kl[2], vh[2], vl[2];
        loadKV(0, kh, kl, vh, vl);
        storeKV(0, kh, kl, vh, vl);
    }
    __syncthreads();

    for (int jt = 0; jt < ntiles; jt++) {
        const int b = jt & 1;
        uint4 kh[2], kl[2], vh[2], vl[2];
        const bool pf = (jt + 1 < ntiles);
        if (pf) loadKV(jt + 1, kh, kl, vh, vl);
        compute(jt, b);
        if (pf) storeKV(b ^ 1, kh, kl, vh, vl);
        __syncthreads();
    }

    // ---- epilogue: normalize, split, store pre-split O (token-major) ----
    const float inv0 = 1.0f / lrow[0];
    const float inv1 = 1.0f / lrow[1];
    const int q0 = qt * 128 + wq * 16 + (lane >> 2);
    const int q1 = q0 + 8;
#pragma unroll
    for (int nf = 0; nf < 8; nf++) {
        const int col = h * DHD + nf * 8 + 2 * (lane & 3);
        uint32_t hw, lw;
        split2(accO[nf][0] * inv0, accO[nf][1] * inv0, hw, lw);
        *reinterpret_cast<uint32_t*>(g_Oh + ((size_t)bbi * TT + q0) * DD + col) = hw;
        *reinterpret_cast<uint32_t*>(g_Ol + ((size_t)bbi * TT + q0) * DD + col) = lw;
        split2(accO[nf][2] * inv1, accO[nf][3] * inv1, hw, lw);
        *reinterpret_cast<uint32_t*>(g_Oh + ((size_t)bbi * TT + q1) * DD + col) = hw;
        *reinterpret_cast<uint32_t*>(g_Ol + ((size_t)bbi * TT + q1) * DD + col) = lw;
    }
}

// ---------------------------------------------------------------------------
extern "C" void kernel_launch(void* const* d_in, const int* in_sizes, int n_in,
                              void* d_out, int out_size)
{
    (void)in_sizes; (void)n_in; (void)out_size;
    const float* x  = (const float*)d_in[0];
    // d_in[1] is the causal mask — statically known, ignored
    const float* Wq = (const float*)d_in[2];
    const float* Wk = (const float*)d_in[3];
    const float* Wv = (const float*)d_in[4];
    const float* Wo = (const float*)d_in[5];
    float* out = (float*)d_out;

    cudaFuncSetAttribute(qkv_mma_kernel,  cudaFuncAttributeMaxDynamicSharedMemorySize, SMEM_GEMM);
    cudaFuncSetAttribute(proj_mma_kernel, cudaFuncAttributeMaxDynamicSharedMemorySize, SMEM_GEMM);
    cudaFuncSetAttribute(attn_mma_kernel, cudaFuncAttributeMaxDynamicSharedMemorySize, SMEM_ATTN);

    // 0. split x + transpose/split W (Wq pre-scaled by 1/8)
    prep_split_x<<<MM * DD / (256 * 8), 256>>>(x);
    dim3 gw(DD / 32, DD / 32, 4);
    prep_wt<<<gw, 256>>>(Wq, Wk, Wv, Wo);

    // 1. QKV projections (pure bf16 HMMA, pre-split)
    dim3 g1(DD / 128, MM / 128, 3);
    qkv_mma_kernel<<<g1, 256, SMEM_GEMM>>>();

    // 2. causal flash attention (HMMA, pre-split)
    dim3 g2(TT / 128, BB * HH);
    attn_mma_kernel<<<g2, 256, SMEM_ATTN>>>();

    // 3. output projection
    dim3 g3(DD / 128, MM / 128);
    proj_mma_kernel<<<g3, 256, SMEM_GEMM>>>(out);
}

// round 7
// speedup vs baseline: 2.8460x; 1.0046x over previous
#include <cuda_runtime.h>
#include <cuda_bf16.h>
#include <math.h>
#include <stdint.h>

// Problem constants
constexpr int BB  = 2;
constexpr int TT  = 2048;
constexpr int DD  = 1024;
constexpr int HH  = 16;
constexpr int DHD = 64;
constexpr int MM  = BB * TT;     // 4096

// Pre-split bf16 scratch (device globals)
__device__ __nv_bfloat16 g_xh[MM * DD], g_xl[MM * DD];
__device__ __nv_bfloat16 g_Wth[4 * DD * DD], g_Wtl[4 * DD * DD];  // W^T hi/lo (Wq pre-scaled)
__device__ __nv_bfloat16 g_Qh[MM * DD], g_Ql[MM * DD];            // head-major
__device__ __nv_bfloat16 g_Kh[MM * DD], g_Kl[MM * DD];
__device__ __nv_bfloat16 g_Vh[MM * DD], g_Vl[MM * DD];
__device__ __nv_bfloat16 g_Oh[MM * DD], g_Ol[MM * DD];            // token-major

// ---------------------------------------------------------------------------
// PTX helpers
// ---------------------------------------------------------------------------
__device__ __forceinline__ void ldsm_x4(uint32_t& r0, uint32_t& r1,
                                        uint32_t& r2, uint32_t& r3, uint32_t addr) {
    asm volatile("ldmatrix.sync.aligned.m8n8.x4.shared.b16 {%0,%1,%2,%3}, [%4];"
                 : "=r"(r0), "=r"(r1), "=r"(r2), "=r"(r3) : "r"(addr));
}

__device__ __forceinline__ void mma_bf16(float* d, const uint32_t* a,
                                         uint32_t b0, uint32_t b1) {
    asm volatile(
        "mma.sync.aligned.m16n8k16.row.col.f32.bf16.bf16.f32 "
        "{%0,%1,%2,%3}, {%4,%5,%6,%7}, {%8,%9}, {%0,%1,%2,%3};"
        : "+f"(d[0]), "+f"(d[1]), "+f"(d[2]), "+f"(d[3])
        : "r"(a[0]), "r"(a[1]), "r"(a[2]), "r"(a[3]), "r"(b0), "r"(b1));
}

__device__ __forceinline__ uint32_t smem_to_u32(const void* p) {
    uint32_t a;
    asm("{ .reg .u64 t; cvta.to.shared.u64 t, %1; cvt.u32.u64 %0, t; }"
        : "=r"(a) : "l"(p));
    return a;
}

__device__ __forceinline__ void cp_async16(uint32_t dst, const void* src) {
    asm volatile("cp.async.cg.shared.global [%0], [%1], 16;" :: "r"(dst), "l"(src));
}
#define CP_COMMIT() asm volatile("cp.async.commit_group;" ::: "memory")
#define CP_WAIT0()  asm volatile("cp.async.wait_group 0;"  ::: "memory")

__device__ __forceinline__ uint32_t pack_bf2(__nv_bfloat16 a, __nv_bfloat16 b) {
    __nv_bfloat162 t = __halves2bfloat162(a, b);
    return *reinterpret_cast<uint32_t*>(&t);
}

__device__ __forceinline__ void split2(float f0, float f1, uint32_t& hw, uint32_t& lw) {
    __nv_bfloat16 h0 = __float2bfloat16(f0);
    __nv_bfloat16 h1 = __float2bfloat16(f1);
    __nv_bfloat16 l0 = __float2bfloat16(f0 - __bfloat162float(h0));
    __nv_bfloat16 l1 = __float2bfloat16(f1 - __bfloat162float(h1));
    hw = pack_bf2(h0, h1);
    lw = pack_bf2(l0, l1);
}

// ---------------------------------------------------------------------------
// Prep kernels
// ---------------------------------------------------------------------------
__global__ void __launch_bounds__(256)
prep_split_x(const float* __restrict__ x)
{
    const size_t i = ((size_t)blockIdx.x * 256 + threadIdx.x) * 8;
    float4 f0 = *reinterpret_cast<const float4*>(x + i);
    float4 f1 = *reinterpret_cast<const float4*>(x + i + 4);
    uint32_t h[4], l[4];
    split2(f0.x, f0.y, h[0], l[0]); split2(f0.z, f0.w, h[1], l[1]);
    split2(f1.x, f1.y, h[2], l[2]); split2(f1.z, f1.w, h[3], l[3]);
    *reinterpret_cast<uint4*>(g_xh + i) = make_uint4(h[0], h[1], h[2], h[3]);
    *reinterpret_cast<uint4*>(g_xl + i) = make_uint4(l[0], l[1], l[2], l[3]);
}

__global__ void __launch_bounds__(256)
prep_wt(const float* __restrict__ Wq, const float* __restrict__ Wk,
        const float* __restrict__ Wv, const float* __restrict__ Wo)
{
    const int z = blockIdx.z;
    const float* W = (z == 0) ? Wq : (z == 1) ? Wk : (z == 2) ? Wv : Wo;
    const float scale = (z == 0) ? 0.125f : 1.0f;
    __shared__ float tile[32][33];
    const int k0 = blockIdx.y * 32, n0 = blockIdx.x * 32;
    const int tx = threadIdx.x & 31, ty = threadIdx.x >> 5;
#pragma unroll
    for (int r = 0; r < 32; r += 8)
        tile[ty + r][tx] = W[(size_t)(k0 + ty + r) * DD + n0 + tx];
    __syncthreads();
    __nv_bfloat16* Th = g_Wth + (size_t)z * DD * DD;
    __nv_bfloat16* Tl = g_Wtl + (size_t)z * DD * DD;
#pragma unroll
    for (int r = 0; r < 32; r += 8) {
        const int n = n0 + ty + r, k = k0 + tx;
        const float v = tile[tx][ty + r] * scale;
        __nv_bfloat16 h = __float2bfloat16(v);
        __nv_bfloat16 l = __float2bfloat16(v - __bfloat162float(h));
        Th[(size_t)n * DD + k] = h;
        Tl[(size_t)n * DD + k] = l;
    }
}

// ---------------------------------------------------------------------------
// Pure-bf16 HMMA GEMM, 512 threads, 16 warps, warp tile 32x32.
// ---------------------------------------------------------------------------
constexpr int BK   = 32;
constexpr int NITER = DD / BK;          // 32
constexpr int GST  = 40;
constexpr int GOP  = 128 * GST * 2;     // 10240 B
constexpr int GBUF = 4 * GOP;
constexpr int SMEM_GEMM = 2 * GBUF;     // 81920 B

template <int MODE>
__device__ __forceinline__ void gemm_core(const __nv_bfloat16* __restrict__ Ah_g,
                                          const __nv_bfloat16* __restrict__ Al_g,
                                          const __nv_bfloat16* __restrict__ Bh_g,
                                          const __nv_bfloat16* __restrict__ Bl_g,
                                          float* __restrict__ Cf,
                                          __nv_bfloat16* __restrict__ Ch,
                                          __nv_bfloat16* __restrict__ Cl,
                                          int bx, int by)
{
    extern __shared__ char smem[];
    const uint32_t sb = smem_to_u32(smem);
    const int tid  = threadIdx.x;
    const int lane = tid & 31;
    const int wid  = tid >> 5;        // 0..15
    const int wm   = wid >> 2;        // 0..3 (32-row slab)
    const int wn   = wid & 3;         // 0..3 (32-col slab)
    const int m0 = by * 128, n0 = bx * 128;

    float acc[2][4][4];
#pragma unroll
    for (int i = 0; i < 2; i++)
#pragma unroll
        for (int j = 0; j < 4; j++)
#pragma unroll
            for (int k = 0; k < 4; k++) acc[i][j][k] = 0.0f;

    // 512 threads, 1 chunk per operand each: row = tid>>2, c = tid&3
    const int ld_row = tid >> 2;
    const int ld_c   = tid & 3;
    auto issue = [&](int b, int k0) {
        const uint32_t base = sb + b * GBUF;
        const uint32_t soff = (uint32_t)(ld_row * GST + ld_c * 8) * 2;
        const size_t ga = (size_t)(m0 + ld_row) * DD + k0 + ld_c * 8;
        const size_t gb = (size_t)(n0 + ld_row) * DD + k0 + ld_c * 8;
        cp_async16(base + soff,           Ah_g + ga);
        cp_async16(base + GOP + soff,     Al_g + ga);
        cp_async16(base + 2 * GOP + soff, Bh_g + gb);
        cp_async16(base + 3 * GOP + soff, Bl_g + gb);
        CP_COMMIT();
    };

    const int ar = wm * 32 + (lane & 15);
    const int ac = (lane >> 4) * 8;
    const int br = wn * 32 + (lane & 15);
    const int bc = (lane >> 4) * 8;

    auto compute = [&](int b) {
        const uint32_t ah_b = sb + b * GBUF;
        const uint32_t al_b = ah_b + GOP;
        const uint32_t bh_b = al_b + GOP;
        const uint32_t bl_b = bh_b + GOP;
#pragma unroll
        for (int ks = 0; ks < 2; ks++) {
            uint32_t ah[2][4], al[2][4], bh[2][4], bl[2][4];
#pragma unroll
            for (int mf = 0; mf < 2; mf++) {
                const uint32_t off = (uint32_t)(((ar + mf * 16) * GST + ks * 16 + ac) * 2);
                ldsm_x4(ah[mf][0], ah[mf][1], ah[mf][2], ah[mf][3], ah_b + off);
                ldsm_x4(al[mf][0], al[mf][1], al[mf][2], al[mf][3], al_b + off);
            }
#pragma unroll
            for (int g = 0; g < 2; g++) {
                const uint32_t off = (uint32_t)(((br + g * 16) * GST + ks * 16 + bc) * 2);
                ldsm_x4(bh[g][0], bh[g][1], bh[g][2], bh[g][3], bh_b + off);
                ldsm_x4(bl[g][0], bl[g][1], bl[g][2], bl[g][3], bl_b + off);
            }
#pragma unroll
            for (int mf = 0; mf < 2; mf++)
#pragma unroll
                for (int g = 0; g < 2; g++)
#pragma unroll
                    for (int sub = 0; sub < 2; sub++) {
                        const int nf = g * 2 + sub;
                        mma_bf16(acc[mf][nf], ah[mf], bh[g][sub], bh[g][sub + 2]);
                        mma_bf16(acc[mf][nf], al[mf], bh[g][sub], bh[g][sub + 2]);
                        mma_bf16(acc[mf][nf], ah[mf], bl[g][sub], bl[g][sub + 2]);
                    }
        }
    };

    issue(0, 0);
    for (int it = 0; it < NITER; ++it) {
        const int b = it & 1;
        CP_WAIT0();
        __syncthreads();
        if (it + 1 < NITER) issue(b ^ 1, (it + 1) * BK);
        compute(b);
    }

    const int group = lane >> 2;
    const int qd    = lane & 3;
#pragma unroll
    for (int mf = 0; mf < 2; mf++)
#pragma unroll
        for (int nf = 0; nf < 4; nf++) {
            const int rg = m0 + wm * 32 + mf * 16 + group;
            const int cg = n0 + wn * 32 + nf * 8 + qd * 2;
            if (MODE == 0) {
                const int bbi = rg >> 11;
                const int t   = rg & 2047;
                const int h   = cg >> 6;
                const int dd  = cg & 63;
                const size_t i0 = (((size_t)bbi * HH + h) * TT + t) * DHD + dd;
                const size_t i1 = i0 + (size_t)8 * DHD;
                uint32_t hw, lw;
                split2(acc[mf][nf][0], acc[mf][nf][1], hw, lw);
                *reinterpret_cast<uint32_t*>(Ch + i0) = hw;
                *reinterpret_cast<uint32_t*>(Cl + i0) = lw;
                split2(acc[mf][nf][2], acc[mf][nf][3], hw, lw);
                *reinterpret_cast<uint32_t*>(Ch + i1) = hw;
                *reinterpret_cast<uint32_t*>(Cl + i1) = lw;
            } else {
                *reinterpret_cast<float2*>(Cf + (size_t)rg * DD + cg) =
                    make_float2(acc[mf][nf][0], acc[mf][nf][1]);
                *reinterpret_cast<float2*>(Cf + (size_t)(rg + 8) * DD + cg) =
                    make_float2(acc[mf][nf][2], acc[mf][nf][3]);
            }
        }
}

__global__ void __launch_bounds__(512, 1)
qkv_mma_kernel()
{
    const int z = blockIdx.z;
    const __nv_bfloat16* Bh = g_Wth + (size_t)z * DD * DD;
    const __nv_bfloat16* Bl = g_Wtl + (size_t)z * DD * DD;
    __nv_bfloat16* Ch = (z == 0) ? g_Qh : (z == 1) ? g_Kh : g_Vh;
    __nv_bfloat16* Cl = (z == 0) ? g_Ql : (z == 1) ? g_Kl : g_Vl;
    gemm_core<0>(g_xh, g_xl, Bh, Bl, nullptr, Ch, Cl, blockIdx.x, blockIdx.y);
}

__global__ void __launch_bounds__(512, 1)
proj_mma_kernel(float* __restrict__ out)
{
    gemm_core<1>(g_Oh, g_Ol, g_Wth + (size_t)3 * DD * DD, g_Wtl + (size_t)3 * DD * DD,
                 out, nullptr, nullptr, blockIdx.x, blockIdx.y);
}

// ---------------------------------------------------------------------------
// HMMA flash attention: 512 threads, q-tile 256 (16 warps x 16 rows),
// KV tiles of 64 double-buffered; K via cp.async, V reg-staged + transposed.
// ---------------------------------------------------------------------------
constexpr int AQT   = 256;                 // q rows per CTA
constexpr int AST   = 72;
constexpr int AQOP  = AQT * AST * 2;       // 36864 B per Q operand
constexpr int AKOP  = 64 * AST * 2;        // 9216 B
constexpr int AKVB  = 4 * AKOP;            // 36864 B
constexpr int AOFFK = 2 * AQOP;            // 73728
constexpr int SMEM_ATTN = AOFFK + 2 * AKVB;   // 147456 B

__global__ void __launch_bounds__(512, 1)
attn_mma_kernel()
{
    extern __shared__ char smem[];
    const uint32_t sb = smem_to_u32(smem);
    const int bh  = blockIdx.y;
    const int bbi = bh / HH;
    const int h   = bh % HH;
    const int qt  = (int)gridDim.x - 1 - (int)blockIdx.x;
    const int tid = threadIdx.x;
    const int lane = tid & 31;
    const int wq   = tid >> 5;            // 0..15

    const size_t headoff = (size_t)bh * TT * DHD;

    // ---- Q resident: straight copy of pre-split rows (512 thr, 256 rows) ----
    {
        const int row = tid >> 1;
        const int c0  = (tid & 1) * 32;
        const size_t src = headoff + (size_t)(qt * AQT + row) * DHD + c0;
        const uint4* shq = reinterpret_cast<const uint4*>(g_Qh + src);
        const uint4* slq = reinterpret_cast<const uint4*>(g_Ql + src);
        char* ph = smem + (row * AST + c0) * 2;
        char* pl = ph + AQOP;
#pragma unroll
        for (int j = 0; j < 4; j++) {
            *reinterpret_cast<uint4*>(ph + 16 * j) = shq[j];
            *reinterpret_cast<uint4*>(pl + 16 * j) = slq[j];
        }
    }

    float accO[8][4];
#pragma unroll
    for (int i = 0; i < 8; i++)
#pragma unroll
        for (int j = 0; j < 4; j++) accO[i][j] = 0.0f;
    float mrow[2] = {-1e30f, -1e30f};
    float lrow[2] = {0.0f, 0.0f};

    const int qmin_w = qt * AQT + wq * 16;
    const int qmax_w = qmin_w + 15;
    const int r0loc  = qmin_w + (lane >> 2);

    // KV loaders: 512 threads, 64 rows x 64 cols; 1 uint4 per array per thread
    const int kv_row = tid >> 3;          // 0..63
    const int kv_c8  = (tid & 7) * 8;     // 0..56

    auto issueK = [&](int jt, int b) {
        const uint32_t base = sb + AOFFK + b * AKVB;
        const uint32_t soff = (uint32_t)(kv_row * AST + kv_c8) * 2;
        const size_t src = headoff + (size_t)(jt * 64 + kv_row) * DHD + kv_c8;
        cp_async16(base + soff,        g_Kh + src);
        cp_async16(base + AKOP + soff, g_Kl + src);
        CP_COMMIT();
    };

    auto loadV = [&](int jt, uint4& vh, uint4& vl) {
        const size_t src = headoff + (size_t)(jt * 64 + kv_row) * DHD + kv_c8;
        vh = *reinterpret_cast<const uint4*>(g_Vh + src);
        vl = *reinterpret_cast<const uint4*>(g_Vl + src);
    };

    auto storeV = [&](int b, uint4 vh, uint4 vl) {
        char* base = smem + AOFFK + b * AKVB;
        __nv_bfloat16* ph = reinterpret_cast<__nv_bfloat16*>(base + 2 * AKOP);
        __nv_bfloat16* pl = reinterpret_cast<__nv_bfloat16*>(base + 3 * AKOP);
        const __nv_bfloat16* vhp = reinterpret_cast<const __nv_bfloat16*>(&vh);
        const __nv_bfloat16* vlp = reinterpret_cast<const __nv_bfloat16*>(&vl);
#pragma unroll
        for (int j = 0; j < 8; j++) {
            const int idx = (kv_c8 + j) * AST + kv_row;   // transposed [dh][key]
            ph[idx] = vhp[j];
            pl[idx] = vlp[j];
        }
    };

    const int fr = lane & 15;
    const int fc = (lane >> 4) * 8;

    auto compute = [&](int jt, int b) {
        const int key0 = jt * 64;
        if (key0 > qmax_w) return;
        const uint32_t kvb = sb + AOFFK + b * AKVB;
        const uint32_t qhb = sb;
        const uint32_t qlb = sb + AQOP;

        float accS[8][4];
#pragma unroll
        for (int i = 0; i < 8; i++)
#pragma unroll
            for (int j = 0; j < 4; j++) accS[i][j] = 0.0f;

#pragma unroll
        for (int ks = 0; ks < 4; ks++) {
            uint32_t qh[4], ql[4];
            const uint32_t qoff = (uint32_t)(((wq * 16 + fr) * AST + ks * 16 + fc) * 2);
            ldsm_x4(qh[0], qh[1], qh[2], qh[3], qhb + qoff);
            ldsm_x4(ql[0], ql[1], ql[2], ql[3], qlb + qoff);
#pragma unroll
            for (int g = 0; g < 4; g++) {
                uint32_t kh[4], kl[4];
                const uint32_t koff = (uint32_t)(((g * 16 + fr) * AST + ks * 16 + fc) * 2);
                ldsm_x4(kh[0], kh[1], kh[2], kh[3], kvb + koff);
                ldsm_x4(kl[0], kl[1], kl[2], kl[3], kvb + AKOP + koff);
#pragma unroll
                for (int sub = 0; sub < 2; sub++) {
                    const int nf = g * 2 + sub;
                    mma_bf16(accS[nf], qh, kh[sub], kh[sub + 2]);
                    mma_bf16(accS[nf], ql, kh[sub], kh[sub + 2]);
                    mma_bf16(accS[nf], qh, kl[sub], kl[sub + 2]);
                }
            }
        }

        if (key0 + 63 > qmin_w) {
            const int r1loc = r0loc + 8;
#pragma unroll
            for (int nf = 0; nf < 8; nf++) {
                const int c = key0 + nf * 8 + 2 * (lane & 3);
                if (c     > r0loc) accS[nf][0] = -1e30f;
                if (c + 1 > r0loc) accS[nf][1] = -1e30f;
                if (c     > r1loc) accS[nf][2] = -1e30f;
                if (c + 1 > r1loc) accS[nf][3] = -1e30f;
            }
        }

        float ml0 = -1e30f, ml1 = -1e30f;
#pragma unroll
        for (int nf = 0; nf < 8; nf++) {
            ml0 = fmaxf(ml0, fmaxf(accS[nf][0], accS[nf][1]));
            ml1 = fmaxf(ml1, fmaxf(accS[nf][2], accS[nf][3]));
        }
        ml0 = fmaxf(ml0, __shfl_xor_sync(0xffffffffu, ml0, 1));
        ml0 = fmaxf(ml0, __shfl_xor_sync(0xffffffffu, ml0, 2));
        ml1 = fmaxf(ml1, __shfl_xor_sync(0xffffffffu, ml1, 1));
        ml1 = fmaxf(ml1, __shfl_xor_sync(0xffffffffu, ml1, 2));
        const float mn0 = fmaxf(mrow[0], ml0);
        const float mn1 = fmaxf(mrow[1], ml1);
        const float corr0 = __expf(mrow[0] - mn0);
        const float corr1 = __expf(mrow[1] - mn1);
        mrow[0] = mn0; mrow[1] = mn1;

        float ls0 = 0.0f, ls1 = 0.0f;
#pragma unroll
        for (int nf = 0; nf < 8; nf++) {
            accS[nf][0] = __expf(accS[nf][0] - mn0);
            accS[nf][1] = __expf(accS[nf][1] - mn0);
            accS[nf][2] = __expf(accS[nf][2] - mn1);
            accS[nf][3] = __expf(accS[nf][3] - mn1);
            ls0 += accS[nf][0] + accS[nf][1];
            ls1 += accS[nf][2] + accS[nf][3];
        }
        ls0 += __shfl_xor_sync(0xffffffffu, ls0, 1);
        ls0 += __shfl_xor_sync(0xffffffffu, ls0, 2);
        ls1 += __shfl_xor_sync(0xffffffffu, ls1, 1);
        ls1 += __shfl_xor_sync(0xffffffffu, ls1, 2);
        lrow[0] = lrow[0] * corr0 + ls0;
        lrow[1] = lrow[1] * corr1 + ls1;

#pragma unroll
        for (int nf = 0; nf < 8; nf++) {
            accO[nf][0] *= corr0; accO[nf][1] *= corr0;
            accO[nf][2] *= corr1; accO[nf][3] *= corr1;
        }

        // P split folded into the PV loop (each fragment consumed once)
#pragma unroll
        for (int kp = 0; kp < 4; kp++) {
            uint32_t ah[4], al[4];
            split2(accS[2*kp][0],   accS[2*kp][1],   ah[0], al[0]);   // rows 0-7,  keys 8kp*2
            split2(accS[2*kp][2],   accS[2*kp][3],   ah[1], al[1]);
            split2(accS[2*kp+1][0], accS[2*kp+1][1], ah[2], al[2]);
            split2(accS[2*kp+1][2], accS[2*kp+1][3], ah[3], al[3]);
#pragma unroll
            for (int vg = 0; vg < 4; vg++) {
                uint32_t vh[4], vl[4];
                const uint32_t voff = (uint32_t)(((vg * 16 + fr) * AST + kp * 16 + fc) * 2);
                ldsm_x4(vh[0], vh[1], vh[2], vh[3], kvb + 2 * AKOP + voff);
                ldsm_x4(vl[0], vl[1], vl[2], vl[3], kvb + 3 * AKOP + voff);
#pragma unroll
                for (int sub = 0; sub < 2; sub++) {
                    const int nf = vg * 2 + sub;
                    mma_bf16(accO[nf], ah, vh[sub], vh[sub + 2]);
                    mma_bf16(accO[nf], al, vh[sub], vh[sub + 2]);
                    mma_bf16(accO[nf], ah, vl[sub], vl[sub + 2]);
                }
            }
        }
    };

    // ---- mainloop ----
    const int ntiles = (qt + 1) * (AQT / 64);
    {
        uint4 vh, vl;
        issueK(0, 0);
        loadV(0, vh, vl);
        CP_WAIT0();
        storeV(0, vh, vl);
    }
    __syncthreads();

    for (int jt = 0; jt < ntiles; jt++) {
        const int b = jt & 1;
        uint4 vh, vl;
        const bool pf = (jt + 1 < ntiles);
        if (pf) { issueK(jt + 1, b ^ 1); loadV(jt + 1, vh, vl); }
        compute(jt, b);
        if (pf) { CP_WAIT0(); storeV(b ^ 1, vh, vl); }
        __syncthreads();
    }

    // ---- epilogue: normalize, split, store pre-split O (token-major) ----
    const float inv0 = 1.0f / lrow[0];
    const float inv1 = 1.0f / lrow[1];
    const int q0 = qt * AQT + wq * 16 + (lane >> 2);
    const int q1 = q0 + 8;
#pragma unroll
    for (int nf = 0; nf < 8; nf++) {
        const int col = h * DHD + nf * 8 + 2 * (lane & 3);
        uint32_t hw, lw;
        split2(accO[nf][0] * inv0, accO[nf][1] * inv0, hw, lw);
        *reinterpret_cast<uint32_t*>(g_Oh + ((size_t)bbi * TT + q0) * DD + col) = hw;
        *reinterpret_cast<uint32_t*>(g_Ol + ((size_t)bbi * TT + q0) * DD + col) = lw;
        split2(accO[nf][2] * inv1, accO[nf][3] * inv1, hw, lw);
        *reinterpret_cast<uint32_t*>(g_Oh + ((size_t)bbi * TT + q1) * DD + col) = hw;
        *reinterpret_cast<uint32_t*>(g_Ol + ((size_t)bbi * TT + q1) * DD + col) = lw;
    }
}

// ---------------------------------------------------------------------------
extern "C" void kernel_launch(void* const* d_in, const int* in_sizes, int n_in,
                              void* d_out, int out_size)
{
    (void)in_sizes; (void)n_in; (void)out_size;
    const float* x  = (const float*)d_in[0];
    // d_in[1] is the causal mask — statically known, ignored
    const float* Wq = (const float*)d_in[2];
    const float* Wk = (const float*)d_in[3];
    const float* Wv = (const float*)d_in[4];
    const float* Wo = (const float*)d_in[5];
    float* out = (float*)d_out;

    cudaFuncSetAttribute(qkv_mma_kernel,  cudaFuncAttributeMaxDynamicSharedMemorySize, SMEM_GEMM);
    cudaFuncSetAttribute(proj_mma_kernel, cudaFuncAttributeMaxDynamicSharedMemorySize, SMEM_GEMM);
    cudaFuncSetAttribute(attn_mma_kernel, cudaFuncAttributeMaxDynamicSharedMemorySize, SMEM_ATTN);

    // 0. split x + transpose/split W (Wq pre-scaled by 1/8)
    prep_split_x<<<MM * DD / (256 * 8), 256>>>(x);
    dim3 gw(DD / 32, DD / 32, 4);
    prep_wt<<<gw, 256>>>(Wq, Wk, Wv, Wo);

    // 1. QKV projections
    dim3 g1(DD / 128, MM / 128, 3);
    qkv_mma_kernel<<<g1, 512, SMEM_GEMM>>>();

    // 2. causal flash attention
    dim3 g2(TT / AQT, BB * HH);
    attn_mma_kernel<<<g2, 512, SMEM_ATTN>>>();

    // 3. output projection
    dim3 g3(DD / 128, MM / 128);
    proj_mma_kernel<<<g3, 512, SMEM_GEMM>>>(out);
}

// round 8
// speedup vs baseline: 2.9112x; 1.0229x over previous
#include <cuda_runtime.h>
#include <cuda_bf16.h>
#include <math.h>
#include <stdint.h>

// Problem constants
constexpr int BB  = 2;
constexpr int TT  = 2048;
constexpr int DD  = 1024;
constexpr int HH  = 16;
constexpr int DHD = 64;
constexpr int MM  = BB * TT;     // 4096

// Pre-split bf16 scratch (device globals)
__device__ __nv_bfloat16 g_xh[MM * DD], g_xl[MM * DD];
__device__ __nv_bfloat16 g_Wth[4 * DD * DD], g_Wtl[4 * DD * DD];  // W^T hi/lo (Wq pre-scaled by 0.125*log2e)
__device__ __nv_bfloat16 g_Qh[MM * DD], g_Ql[MM * DD];            // head-major
__device__ __nv_bfloat16 g_Kh[MM * DD], g_Kl[MM * DD];
__device__ __nv_bfloat16 g_Vh[MM * DD], g_Vl[MM * DD];
__device__ __nv_bfloat16 g_Oh[MM * DD], g_Ol[MM * DD];            // token-major

// ---------------------------------------------------------------------------
// PTX helpers
// ---------------------------------------------------------------------------
__device__ __forceinline__ void ldsm_x4(uint32_t& r0, uint32_t& r1,
                                        uint32_t& r2, uint32_t& r3, uint32_t addr) {
    asm volatile("ldmatrix.sync.aligned.m8n8.x4.shared.b16 {%0,%1,%2,%3}, [%4];"
                 : "=r"(r0), "=r"(r1), "=r"(r2), "=r"(r3) : "r"(addr));
}

__device__ __forceinline__ void mma_bf16(float* d, const uint32_t* a,
                                         uint32_t b0, uint32_t b1) {
    asm volatile(
        "mma.sync.aligned.m16n8k16.row.col.f32.bf16.bf16.f32 "
        "{%0,%1,%2,%3}, {%4,%5,%6,%7}, {%8,%9}, {%0,%1,%2,%3};"
        : "+f"(d[0]), "+f"(d[1]), "+f"(d[2]), "+f"(d[3])
        : "r"(a[0]), "r"(a[1]), "r"(a[2]), "r"(a[3]), "r"(b0), "r"(b1));
}

__device__ __forceinline__ uint32_t smem_to_u32(const void* p) {
    uint32_t a;
    asm("{ .reg .u64 t; cvta.to.shared.u64 t, %1; cvt.u32.u64 %0, t; }"
        : "=r"(a) : "l"(p));
    return a;
}

__device__ __forceinline__ void cp_async16(uint32_t dst, const void* src) {
    asm volatile("cp.async.cg.shared.global [%0], [%1], 16;" :: "r"(dst), "l"(src));
}
#define CP_COMMIT() asm volatile("cp.async.commit_group;" ::: "memory")
#define CP_WAIT0()  asm volatile("cp.async.wait_group 0;"  ::: "memory")

__device__ __forceinline__ float ex2f(float x) {
    float r;
    asm("ex2.approx.f32 %0, %1;" : "=f"(r) : "f"(x));
    return r;
}

__device__ __forceinline__ uint32_t pack_bf2(__nv_bfloat16 a, __nv_bfloat16 b) {
    __nv_bfloat162 t = __halves2bfloat162(a, b);
    return *reinterpret_cast<uint32_t*>(&t);
}

__device__ __forceinline__ void split2(float f0, float f1, uint32_t& hw, uint32_t& lw) {
    __nv_bfloat16 h0 = __float2bfloat16(f0);
    __nv_bfloat16 h1 = __float2bfloat16(f1);
    __nv_bfloat16 l0 = __float2bfloat16(f0 - __bfloat162float(h0));
    __nv_bfloat16 l1 = __float2bfloat16(f1 - __bfloat162float(h1));
    hw = pack_bf2(h0, h1);
    lw = pack_bf2(l0, l1);
}

// ---------------------------------------------------------------------------
// Prep kernels
// ---------------------------------------------------------------------------
__global__ void __launch_bounds__(256)
prep_split_x(const float* __restrict__ x)
{
    const size_t i = ((size_t)blockIdx.x * 256 + threadIdx.x) * 8;
    float4 f0 = *reinterpret_cast<const float4*>(x + i);
    float4 f1 = *reinterpret_cast<const float4*>(x + i + 4);
    uint32_t h[4], l[4];
    split2(f0.x, f0.y, h[0], l[0]); split2(f0.z, f0.w, h[1], l[1]);
    split2(f1.x, f1.y, h[2], l[2]); split2(f1.z, f1.w, h[3], l[3]);
    *reinterpret_cast<uint4*>(g_xh + i) = make_uint4(h[0], h[1], h[2], h[3]);
    *reinterpret_cast<uint4*>(g_xl + i) = make_uint4(l[0], l[1], l[2], l[3]);
}

__global__ void __launch_bounds__(256)
prep_wt(const float* __restrict__ Wq, const float* __restrict__ Wk,
        const float* __restrict__ Wv, const float* __restrict__ Wo)
{
    const int z = blockIdx.z;
    const float* W = (z == 0) ? Wq : (z == 1) ? Wk : (z == 2) ? Wv : Wo;
    // Wq folded scale: (1/8) * log2(e) so attention scores are in log2 domain
    const float scale = (z == 0) ? 0.18033688011112042f : 1.0f;
    __shared__ float tile[32][33];
    const int k0 = blockIdx.y * 32, n0 = blockIdx.x * 32;
    const int tx = threadIdx.x & 31, ty = threadIdx.x >> 5;
#pragma unroll
    for (int r = 0; r < 32; r += 8)
        tile[ty + r][tx] = W[(size_t)(k0 + ty + r) * DD + n0 + tx];
    __syncthreads();
    __nv_bfloat16* Th = g_Wth + (size_t)z * DD * DD;
    __nv_bfloat16* Tl = g_Wtl + (size_t)z * DD * DD;
#pragma unroll
    for (int r = 0; r < 32; r += 8) {
        const int n = n0 + ty + r, k = k0 + tx;
        const float v = tile[tx][ty + r] * scale;
        __nv_bfloat16 h = __float2bfloat16(v);
        __nv_bfloat16 l = __float2bfloat16(v - __bfloat162float(h));
        Th[(size_t)n * DD + k] = h;
        Tl[(size_t)n * DD + k] = l;
    }
}

// ---------------------------------------------------------------------------
// Pure-bf16 HMMA GEMM, 512 threads, 16 warps, warp tile 32x32. (unchanged R7)
// ---------------------------------------------------------------------------
constexpr int BK   = 32;
constexpr int NITER = DD / BK;          // 32
constexpr int GST  = 40;
constexpr int GOP  = 128 * GST * 2;     // 10240 B
constexpr int GBUF = 4 * GOP;
constexpr int SMEM_GEMM = 2 * GBUF;     // 81920 B

template <int MODE>
__device__ __forceinline__ void gemm_core(const __nv_bfloat16* __restrict__ Ah_g,
                                          const __nv_bfloat16* __restrict__ Al_g,
                                          const __nv_bfloat16* __restrict__ Bh_g,
                                          const __nv_bfloat16* __restrict__ Bl_g,
                                          float* __restrict__ Cf,
                                          __nv_bfloat16* __restrict__ Ch,
                                          __nv_bfloat16* __restrict__ Cl,
                                          int bx, int by)
{
    extern __shared__ char smem[];
    const uint32_t sb = smem_to_u32(smem);
    const int tid  = threadIdx.x;
    const int lane = tid & 31;
    const int wid  = tid >> 5;
    const int wm   = wid >> 2;
    const int wn   = wid & 3;
    const int m0 = by * 128, n0 = bx * 128;

    float acc[2][4][4];
#pragma unroll
    for (int i = 0; i < 2; i++)
#pragma unroll
        for (int j = 0; j < 4; j++)
#pragma unroll
            for (int k = 0; k < 4; k++) acc[i][j][k] = 0.0f;

    const int ld_row = tid >> 2;
    const int ld_c   = tid & 3;
    auto issue = [&](int b, int k0) {
        const uint32_t base = sb + b * GBUF;
        const uint32_t soff = (uint32_t)(ld_row * GST + ld_c * 8) * 2;
        const size_t ga = (size_t)(m0 + ld_row) * DD + k0 + ld_c * 8;
        const size_t gb = (size_t)(n0 + ld_row) * DD + k0 + ld_c * 8;
        cp_async16(base + soff,           Ah_g + ga);
        cp_async16(base + GOP + soff,     Al_g + ga);
        cp_async16(base + 2 * GOP + soff, Bh_g + gb);
        cp_async16(base + 3 * GOP + soff, Bl_g + gb);
        CP_COMMIT();
    };

    const int ar = wm * 32 + (lane & 15);
    const int ac = (lane >> 4) * 8;
    const int br = wn * 32 + (lane & 15);
    const int bc = (lane >> 4) * 8;

    auto compute = [&](int b) {
        const uint32_t ah_b = sb + b * GBUF;
        const uint32_t al_b = ah_b + GOP;
        const uint32_t bh_b = al_b + GOP;
        const uint32_t bl_b = bh_b + GOP;
#pragma unroll
        for (int ks = 0; ks < 2; ks++) {
            uint32_t ah[2][4], al[2][4], bh[2][4], bl[2][4];
#pragma unroll
            for (int mf = 0; mf < 2; mf++) {
                const uint32_t off = (uint32_t)(((ar + mf * 16) * GST + ks * 16 + ac) * 2);
                ldsm_x4(ah[mf][0], ah[mf][1], ah[mf][2], ah[mf][3], ah_b + off);
                ldsm_x4(al[mf][0], al[mf][1], al[mf][2], al[mf][3], al_b + off);
            }
#pragma unroll
            for (int g = 0; g < 2; g++) {
                const uint32_t off = (uint32_t)(((br + g * 16) * GST + ks * 16 + bc) * 2);
                ldsm_x4(bh[g][0], bh[g][1], bh[g][2], bh[g][3], bh_b + off);
                ldsm_x4(bl[g][0], bl[g][1], bl[g][2], bl[g][3], bl_b + off);
            }
#pragma unroll
            for (int mf = 0; mf < 2; mf++)
#pragma unroll
                for (int g = 0; g < 2; g++)
#pragma unroll
                    for (int sub = 0; sub < 2; sub++) {
                        const int nf = g * 2 + sub;
                        mma_bf16(acc[mf][nf], ah[mf], bh[g][sub], bh[g][sub + 2]);
                        mma_bf16(acc[mf][nf], al[mf], bh[g][sub], bh[g][sub + 2]);
                        mma_bf16(acc[mf][nf], ah[mf], bl[g][sub], bl[g][sub + 2]);
                    }
        }
    };

    issue(0, 0);
    for (int it = 0; it < NITER; ++it) {
        const int b = it & 1;
        CP_WAIT0();
        __syncthreads();
        if (it + 1 < NITER) issue(b ^ 1, (it + 1) * BK);
        compute(b);
    }

    const int group = lane >> 2;
    const int qd    = lane & 3;
#pragma unroll
    for (int mf = 0; mf < 2; mf++)
#pragma unroll
        for (int nf = 0; nf < 4; nf++) {
            const int rg = m0 + wm * 32 + mf * 16 + group;
            const int cg = n0 + wn * 32 + nf * 8 + qd * 2;
            if (MODE == 0) {
                const int bbi = rg >> 11;
                const int t   = rg & 2047;
                const int h   = cg >> 6;
                const int dd  = cg & 63;
                const size_t i0 = (((size_t)bbi * HH + h) * TT + t) * DHD + dd;
                const size_t i1 = i0 + (size_t)8 * DHD;
                uint32_t hw, lw;
                split2(acc[mf][nf][0], acc[mf][nf][1], hw, lw);
                *reinterpret_cast<uint32_t*>(Ch + i0) = hw;
                *reinterpret_cast<uint32_t*>(Cl + i0) = lw;
                split2(acc[mf][nf][2], acc[mf][nf][3], hw, lw);
                *reinterpret_cast<uint32_t*>(Ch + i1) = hw;
                *reinterpret_cast<uint32_t*>(Cl + i1) = lw;
            } else {
                *reinterpret_cast<float2*>(Cf + (size_t)rg * DD + cg) =
                    make_float2(acc[mf][nf][0], acc[mf][nf][1]);
                *reinterpret_cast<float2*>(Cf + (size_t)(rg + 8) * DD + cg) =
                    make_float2(acc[mf][nf][2], acc[mf][nf][3]);
            }
        }
}

__global__ void __launch_bounds__(512, 1)
qkv_mma_kernel()
{
    const int z = blockIdx.z;
    const __nv_bfloat16* Bh = g_Wth + (size_t)z * DD * DD;
    const __nv_bfloat16* Bl = g_Wtl + (size_t)z * DD * DD;
    __nv_bfloat16* Ch = (z == 0) ? g_Qh : (z == 1) ? g_Kh : g_Vh;
    __nv_bfloat16* Cl = (z == 0) ? g_Ql : (z == 1) ? g_Kl : g_Vl;
    gemm_core<0>(g_xh, g_xl, Bh, Bl, nullptr, Ch, Cl, blockIdx.x, blockIdx.y);
}

__global__ void __launch_bounds__(512, 1)
proj_mma_kernel(float* __restrict__ out)
{
    gemm_core<1>(g_Oh, g_Ol, g_Wth + (size_t)3 * DD * DD, g_Wtl + (size_t)3 * DD * DD,
                 out, nullptr, nullptr, blockIdx.x, blockIdx.y);
}

// ---------------------------------------------------------------------------
// HMMA flash attention, software-pipelined: S(j+1) overlaps softmax(j)/PV(j).
// 256 threads, q-tile 128 (8 warps x 16 rows), KV tiles 64 double-buffered.
// exp2 domain (scale folded into Wq), deferred l-reduction.
// ---------------------------------------------------------------------------
constexpr int AQT   = 128;
constexpr int AST   = 72;
constexpr int AQOP  = AQT * AST * 2;       // 18432 B
constexpr int AKOP  = 64 * AST * 2;        // 9216 B
constexpr int AKVB  = 4 * AKOP;            // 36864 B (Kh,Kl,Vh,Vl)
constexpr int AOFFK = 2 * AQOP;            // 36864
constexpr int SMEM_ATTN = AOFFK + 2 * AKVB;   // 110592 B

__global__ void __launch_bounds__(256, 1)
attn_mma_kernel()
{
    extern __shared__ char smem[];
    const uint32_t sb = smem_to_u32(smem);
    const int bh  = blockIdx.y;
    const int bbi = bh / HH;
    const int h   = bh % HH;
    const int qt  = (int)gridDim.x - 1 - (int)blockIdx.x;
    const int tid = threadIdx.x;
    const int lane = tid & 31;
    const int wq   = tid >> 5;            // 0..7

    const size_t headoff = (size_t)bh * TT * DHD;

    // ---- Q resident ----
    {
        const int row = tid >> 1;
        const int c0  = (tid & 1) * 32;
        const size_t src = headoff + (size_t)(qt * AQT + row) * DHD + c0;
        const uint4* shq = reinterpret_cast<const uint4*>(g_Qh + src);
        const uint4* slq = reinterpret_cast<const uint4*>(g_Ql + src);
        char* ph = smem + (row * AST + c0) * 2;
        char* pl = ph + AQOP;
#pragma unroll
        for (int j = 0; j < 4; j++) {
            *reinterpret_cast<uint4*>(ph + 16 * j) = shq[j];
            *reinterpret_cast<uint4*>(pl + 16 * j) = slq[j];
        }
    }

    float accO[8][4];
#pragma unroll
    for (int i = 0; i < 8; i++)
#pragma unroll
        for (int j = 0; j < 4; j++) accO[i][j] = 0.0f;
    float accA[8][4], accB[8][4];
    float mrow[2] = {-1e30f, -1e30f};
    float lrow[2] = {0.0f, 0.0f};

    const int qmin_w = qt * AQT + wq * 16;
    const int qmax_w = qmin_w + 15;
    const int r0loc  = qmin_w + (lane >> 2);
    const int ntiles = 2 * (qt + 1);

    // KV loaders: 256 threads, 64 rows x 64 cols
    const int kv_row = tid >> 2;          // 0..63
    const int kv_c16 = (tid & 3) * 16;    // 0,16,32,48

    auto issueK = [&](int jt, int b) {
        const uint32_t base = sb + AOFFK + b * AKVB;
        const uint32_t soff = (uint32_t)(kv_row * AST + kv_c16) * 2;
        const size_t src = headoff + (size_t)(jt * 64 + kv_row) * DHD + kv_c16;
        cp_async16(base + soff,             g_Kh + src);
        cp_async16(base + soff + 16,        g_Kh + src + 8);
        cp_async16(base + AKOP + soff,      g_Kl + src);
        cp_async16(base + AKOP + soff + 16, g_Kl + src + 8);
        CP_COMMIT();
    };

    auto loadV = [&](int jt, uint4* vh, uint4* vl) {
        const size_t src = headoff + (size_t)(jt * 64 + kv_row) * DHD + kv_c16;
        const uint4* p;
        p = reinterpret_cast<const uint4*>(g_Vh + src); vh[0] = p[0]; vh[1] = p[1];
        p = reinterpret_cast<const uint4*>(g_Vl + src); vl[0] = p[0]; vl[1] = p[1];
    };

    auto storeV = [&](int b, const uint4* vh, const uint4* vl) {
        char* base = smem + AOFFK + b * AKVB;
        __nv_bfloat16* ph = reinterpret_cast<__nv_bfloat16*>(base + 2 * AKOP);
        __nv_bfloat16* pl = reinterpret_cast<__nv_bfloat16*>(base + 3 * AKOP);
        const __nv_bfloat16* vhp = reinterpret_cast<const __nv_bfloat16*>(vh);
        const __nv_bfloat16* vlp = reinterpret_cast<const __nv_bfloat16*>(vl);
#pragma unroll
        for (int j = 0; j < 16; j++) {
            const int idx = (kv_c16 + j) * AST + kv_row;   // transposed [dh][key]
            ph[idx] = vhp[j];
            pl[idx] = vlp[j];
        }
    };

    const int fr = lane & 15;
    const int fc = (lane >> 4) * 8;

    // S: Q·K^T for tile jt into acc
    auto sphase = [&](int jt, float (*acc)[4]) {
        const uint32_t kvb = sb + AOFFK + (jt & 1) * AKVB;
        const uint32_t qhb = sb;
        const uint32_t qlb = sb + AQOP;
#pragma unroll
        for (int i = 0; i < 8; i++)
#pragma unroll
            for (int j = 0; j < 4; j++) acc[i][j] = 0.0f;
#pragma unroll
        for (int ks = 0; ks < 4; ks++) {
            uint32_t qh[4], ql[4];
            const uint32_t qoff = (uint32_t)(((wq * 16 + fr) * AST + ks * 16 + fc) * 2);
            ldsm_x4(qh[0], qh[1], qh[2], qh[3], qhb + qoff);
            ldsm_x4(ql[0], ql[1], ql[2], ql[3], qlb + qoff);
#pragma unroll
            for (int g = 0; g < 4; g++) {
                uint32_t kh[4], kl[4];
                const uint32_t koff = (uint32_t)(((g * 16 + fr) * AST + ks * 16 + fc) * 2);
                ldsm_x4(kh[0], kh[1], kh[2], kh[3], kvb + koff);
                ldsm_x4(kl[0], kl[1], kl[2], kl[3], kvb + AKOP + koff);
#pragma unroll
                for (int sub = 0; sub < 2; sub++) {
                    const int nf = g * 2 + sub;
                    mma_bf16(acc[nf], qh, kh[sub], kh[sub + 2]);
                    mma_bf16(acc[nf], ql, kh[sub], kh[sub + 2]);
                    mma_bf16(acc[nf], qh, kl[sub], kl[sub + 2]);
                }
            }
        }
    };

    uint4 vstg_h[2], vstg_l[2];

    // ---- prologue: tiles 0 and 1 into both buffers, then S(0) ----
    issueK(0, 0);
    if (1 < ntiles) issueK(1, 1);
    loadV(0, vstg_h, vstg_l);
    storeV(0, vstg_h, vstg_l);
    if (1 < ntiles) { loadV(1, vstg_h, vstg_l); storeV(1, vstg_h, vstg_l); }
    CP_WAIT0();
    __syncthreads();
    sphase(0, accA);
    if (2 < ntiles) loadV(2, vstg_h, vstg_l);

    // ---- pipelined mainloop (unrolled x2 for accA/accB swap) ----
    auto iterate = [&](int j, float (*cur)[4], float (*nxt)[4]) {
        const int key0 = j * 64;
        const bool live = (key0 <= qmax_w);

        // prefetch K(j+2) into the K region of buf j&1 (K(j) consumed last iter)
        if (j + 2 < ntiles) issueK(j + 2, j & 1);

        uint32_t p01h[8], p01l[8], p23h[8], p23l[8];
        float corr0 = 1.0f, corr1 = 1.0f;
        if (live) {
            if (key0 + 63 > qmin_w) {
                const int r1loc = r0loc + 8;
#pragma unroll
                for (int nf = 0; nf < 8; nf++) {
                    const int c = key0 + nf * 8 + 2 * (lane & 3);
                    if (c     > r0loc) cur[nf][0] = -1e30f;
                    if (c + 1 > r0loc) cur[nf][1] = -1e30f;
                    if (c     > r1loc) cur[nf][2] = -1e30f;
                    if (c + 1 > r1loc) cur[nf][3] = -1e30f;
                }
            }
            float ml0 = -1e30f, ml1 = -1e30f;
#pragma unroll
            for (int nf = 0; nf < 8; nf++) {
                ml0 = fmaxf(ml0, fmaxf(cur[nf][0], cur[nf][1]));
                ml1 = fmaxf(ml1, fmaxf(cur[nf][2], cur[nf][3]));
            }
            ml0 = fmaxf(ml0, __shfl_xor_sync(0xffffffffu, ml0, 1));
            ml0 = fmaxf(ml0, __shfl_xor_sync(0xffffffffu, ml0, 2));
            ml1 = fmaxf(ml1, __shfl_xor_sync(0xffffffffu, ml1, 1));
            ml1 = fmaxf(ml1, __shfl_xor_sync(0xffffffffu, ml1, 2));
            const float mn0 = fmaxf(mrow[0], ml0);
            const float mn1 = fmaxf(mrow[1], ml1);
            corr0 = ex2f(mrow[0] - mn0);
            corr1 = ex2f(mrow[1] - mn1);
            mrow[0] = mn0; mrow[1] = mn1;

            float ls0 = 0.0f, ls1 = 0.0f;
#pragma unroll
            for (int nf = 0; nf < 8; nf++) {
                cur[nf][0] = ex2f(cur[nf][0] - mn0);
                cur[nf][1] = ex2f(cur[nf][1] - mn0);
                cur[nf][2] = ex2f(cur[nf][2] - mn1);
                cur[nf][3] = ex2f(cur[nf][3] - mn1);
                ls0 += cur[nf][0] + cur[nf][1];
                ls1 += cur[nf][2] + cur[nf][3];
            }
            lrow[0] = lrow[0] * corr0 + ls0;   // per-thread partial; quad-reduce at end
            lrow[1] = lrow[1] * corr1 + ls1;
#pragma unroll
            for (int nf = 0; nf < 8; nf++) {
                split2(cur[nf][0], cur[nf][1], p01h[nf], p01l[nf]);
                split2(cur[nf][2], cur[nf][3], p23h[nf], p23l[nf]);
            }
        }

        // ---- S(j+1): independent of softmax(j); fills the latency gaps ----
        if (j + 1 < ntiles) sphase(j + 1, nxt);

        // ---- PV(j) ----
        if (live) {
#pragma unroll
            for (int nf = 0; nf < 8; nf++) {
                accO[nf][0] *= corr0; accO[nf][1] *= corr0;
                accO[nf][2] *= corr1; accO[nf][3] *= corr1;
            }
            const uint32_t kvb = sb + AOFFK + (j & 1) * AKVB;
#pragma unroll
            for (int kp = 0; kp < 4; kp++) {
                uint32_t ah[4] = {p01h[2*kp], p23h[2*kp], p01h[2*kp+1], p23h[2*kp+1]};
                uint32_t al[4] = {p01l[2*kp], p23l[2*kp], p01l[2*kp+1], p23l[2*kp+1]};
#pragma unroll
                for (int vg = 0; vg < 4; vg++) {
                    uint32_t vh[4], vl[4];
                    const uint32_t voff = (uint32_t)(((vg * 16 + fr) * AST + kp * 16 + fc) * 2);
                    ldsm_x4(vh[0], vh[1], vh[2], vh[3], kvb + 2 * AKOP + voff);
                    ldsm_x4(vl[0], vl[1], vl[2], vl[3], kvb + 3 * AKOP + voff);
#pragma unroll
                    for (int sub = 0; sub < 2; sub++) {
                        const int nf = vg * 2 + sub;
                        mma_bf16(accO[nf], ah, vh[sub], vh[sub + 2]);
                        mma_bf16(accO[nf], al, vh[sub], vh[sub + 2]);
                        mma_bf16(accO[nf], ah, vl[sub], vl[sub + 2]);
                    }
                }
            }
        }

        __syncthreads();                       // V(j) fully consumed CTA-wide
        if (j + 2 < ntiles) storeV(j & 1, vstg_h, vstg_l);
        if (j + 3 < ntiles) loadV(j + 3, vstg_h, vstg_l);
        CP_WAIT0();                            // K(j+2) arrived (issued at iter start)
        __syncthreads();                       // publish V(j+2)/K(j+2) before next S
    };

    for (int j = 0; j < ntiles; j += 2) {
        iterate(j,     accA, accB);
        iterate(j + 1, accB, accA);
    }

    // ---- epilogue: finish deferred l-reduction, normalize, split, store ----
    lrow[0] += __shfl_xor_sync(0xffffffffu, lrow[0], 1);
    lrow[0] += __shfl_xor_sync(0xffffffffu, lrow[0], 2);
    lrow[1] += __shfl_xor_sync(0xffffffffu, lrow[1], 1);
    lrow[1] += __shfl_xor_sync(0xffffffffu, lrow[1], 2);
    const float inv0 = 1.0f / lrow[0];
    const float inv1 = 1.0f / lrow[1];
    const int q0 = qt * AQT + wq * 16 + (lane >> 2);
    const int q1 = q0 + 8;
#pragma unroll
    for (int nf = 0; nf < 8; nf++) {
        const int col = h * DHD + nf * 8 + 2 * (lane & 3);
        uint32_t hw, lw;
        split2(accO[nf][0] * inv0, accO[nf][1] * inv0, hw, lw);
        *reinterpret_cast<uint32_t*>(g_Oh + ((size_t)bbi * TT + q0) * DD + col) = hw;
        *reinterpret_cast<uint32_t*>(g_Ol + ((size_t)bbi * TT + q0) * DD + col) = lw;
        split2(accO[nf][2] * inv1, accO[nf][3] * inv1, hw, lw);
        *reinterpret_cast<uint32_t*>(g_Oh + ((size_t)bbi * TT + q1) * DD + col) = hw;
        *reinterpret_cast<uint32_t*>(g_Ol + ((size_t)bbi * TT + q1) * DD + col) = lw;
    }
}

// ---------------------------------------------------------------------------
extern "C" void kernel_launch(void* const* d_in, const int* in_sizes, int n_in,
                              void* d_out, int out_size)
{
    (void)in_sizes; (void)n_in; (void)out_size;
    const float* x  = (const float*)d_in[0];
    // d_in[1] is the causal mask — statically known, ignored
    const float* Wq = (const float*)d_in[2];
    const float* Wk = (const float*)d_in[3];
    const float* Wv = (const float*)d_in[4];
    const float* Wo = (const float*)d_in[5];
    float* out = (float*)d_out;

    cudaFuncSetAttribute(qkv_mma_kernel,  cudaFuncAttributeMaxDynamicSharedMemorySize, SMEM_GEMM);
    cudaFuncSetAttribute(proj_mma_kernel, cudaFuncAttributeMaxDynamicSharedMemorySize, SMEM_GEMM);
    cudaFuncSetAttribute(attn_mma_kernel, cudaFuncAttributeMaxDynamicSharedMemorySize, SMEM_ATTN);

    // 0. split x + transpose/split W (Wq pre-scaled by 0.125*log2e)
    prep_split_x<<<MM * DD / (256 * 8), 256>>>(x);
    dim3 gw(DD / 32, DD / 32, 4);
    prep_wt<<<gw, 256>>>(Wq, Wk, Wv, Wo);

    // 1. QKV projections
    dim3 g1(DD / 128, MM / 128, 3);
    qkv_mma_kernel<<<g1, 512, SMEM_GEMM>>>();

    // 2. causal flash attention (pipelined)
    dim3 g2(TT / AQT, BB * HH);
    attn_mma_kernel<<<g2, 256, SMEM_ATTN>>>();

    // 3. output projection
    dim3 g3(DD / 128, MM / 128);
    proj_mma_kernel<<<g3, 512, SMEM_GEMM>>>(out);
}

// round 10
// speedup vs baseline: 2.9748x; 1.0218x over previous
#include <cuda_runtime.h>
#include <cuda_bf16.h>
#include <math.h>
#include <stdint.h>

// Problem constants
constexpr int BB  = 2;
constexpr int TT  = 2048;
constexpr int DD  = 1024;
constexpr int HH  = 16;
constexpr int DHD = 64;
constexpr int MM  = BB * TT;     // 4096

// Pre-split bf16 scratch (device globals)
__device__ __nv_bfloat16 g_xh[MM * DD], g_xl[MM * DD];
__device__ __nv_bfloat16 g_Wth[4 * DD * DD], g_Wtl[4 * DD * DD];  // W^T hi/lo (Wq pre-scaled by 0.125*log2e)
__device__ __nv_bfloat16 g_Qh[MM * DD], g_Ql[MM * DD];            // head-major
__device__ __nv_bfloat16 g_Kh[MM * DD], g_Kl[MM * DD];
__device__ __nv_bfloat16 g_Vh[MM * DD], g_Vl[MM * DD];
__device__ __nv_bfloat16 g_Oh[MM * DD], g_Ol[MM * DD];            // token-major

// ---------------------------------------------------------------------------
// PTX helpers
// ---------------------------------------------------------------------------
__device__ __forceinline__ void ldsm_x4(uint32_t& r0, uint32_t& r1,
                                        uint32_t& r2, uint32_t& r3, uint32_t addr) {
    asm volatile("ldmatrix.sync.aligned.m8n8.x4.shared.b16 {%0,%1,%2,%3}, [%4];"
                 : "=r"(r0), "=r"(r1), "=r"(r2), "=r"(r3) : "r"(addr));
}

// transposing variant: loads 4 8x8 b16 tiles, each transposed
__device__ __forceinline__ void ldsm_x4_t(uint32_t& r0, uint32_t& r1,
                                          uint32_t& r2, uint32_t& r3, uint32_t addr) {
    asm volatile("ldmatrix.sync.aligned.m8n8.x4.trans.shared.b16 {%0,%1,%2,%3}, [%4];"
                 : "=r"(r0), "=r"(r1), "=r"(r2), "=r"(r3) : "r"(addr));
}

__device__ __forceinline__ void mma_bf16(float* d, const uint32_t* a,
                                         uint32_t b0, uint32_t b1) {
    asm volatile(
        "mma.sync.aligned.m16n8k16.row.col.f32.bf16.bf16.f32 "
        "{%0,%1,%2,%3}, {%4,%5,%6,%7}, {%8,%9}, {%0,%1,%2,%3};"
        : "+f"(d[0]), "+f"(d[1]), "+f"(d[2]), "+f"(d[3])
        : "r"(a[0]), "r"(a[1]), "r"(a[2]), "r"(a[3]), "r"(b0), "r"(b1));
}

__device__ __forceinline__ uint32_t smem_to_u32(const void* p) {
    uint32_t a;
    asm("{ .reg .u64 t; cvta.to.shared.u64 t, %1; cvt.u32.u64 %0, t; }"
        : "=r"(a) : "l"(p));
    return a;
}

__device__ __forceinline__ void cp_async16(uint32_t dst, const void* src) {
    asm volatile("cp.async.cg.shared.global [%0], [%1], 16;" :: "r"(dst), "l"(src));
}
#define CP_COMMIT() asm volatile("cp.async.commit_group;" ::: "memory")
#define CP_WAIT1()  asm volatile("cp.async.wait_group 1;"  ::: "memory")

__device__ __forceinline__ float ex2f(float x) {
    float r;
    asm("ex2.approx.f32 %0, %1;" : "=f"(r) : "f"(x));
    return r;
}

__device__ __forceinline__ uint32_t pack_bf2(__nv_bfloat16 a, __nv_bfloat16 b) {
    __nv_bfloat162 t = __halves2bfloat162(a, b);
    return *reinterpret_cast<uint32_t*>(&t);
}

__device__ __forceinline__ void split2(float f0, float f1, uint32_t& hw, uint32_t& lw) {
    __nv_bfloat16 h0 = __float2bfloat16(f0);
    __nv_bfloat16 h1 = __float2bfloat16(f1);
    __nv_bfloat16 l0 = __float2bfloat16(f0 - __bfloat162float(h0));
    __nv_bfloat16 l1 = __float2bfloat16(f1 - __bfloat162float(h1));
    hw = pack_bf2(h0, h1);
    lw = pack_bf2(l0, l1);
}

// ---------------------------------------------------------------------------
// Prep kernels
// ---------------------------------------------------------------------------
__global__ void __launch_bounds__(256)
prep_split_x(const float* __restrict__ x)
{
    const size_t i = ((size_t)blockIdx.x * 256 + threadIdx.x) * 8;
    float4 f0 = *reinterpret_cast<const float4*>(x + i);
    float4 f1 = *reinterpret_cast<const float4*>(x + i + 4);
    uint32_t h[4], l[4];
    split2(f0.x, f0.y, h[0], l[0]); split2(f0.z, f0.w, h[1], l[1]);
    split2(f1.x, f1.y, h[2], l[2]); split2(f1.z, f1.w, h[3], l[3]);
    *reinterpret_cast<uint4*>(g_xh + i) = make_uint4(h[0], h[1], h[2], h[3]);
    *reinterpret_cast<uint4*>(g_xl + i) = make_uint4(l[0], l[1], l[2], l[3]);
}

__global__ void __launch_bounds__(256)
prep_wt(const float* __restrict__ Wq, const float* __restrict__ Wk,
        const float* __restrict__ Wv, const float* __restrict__ Wo)
{
    const int z = blockIdx.z;
    const float* W = (z == 0) ? Wq : (z == 1) ? Wk : (z == 2) ? Wv : Wo;
    // Wq folded scale: (1/8) * log2(e) so attention scores are in log2 domain
    const float scale = (z == 0) ? 0.18033688011112042f : 1.0f;
    __shared__ float tile[32][33];
    const int k0 = blockIdx.y * 32, n0 = blockIdx.x * 32;
    const int tx = threadIdx.x & 31, ty = threadIdx.x >> 5;
#pragma unroll
    for (int r = 0; r < 32; r += 8)
        tile[ty + r][tx] = W[(size_t)(k0 + ty + r) * DD + n0 + tx];
    __syncthreads();
    __nv_bfloat16* Th = g_Wth + (size_t)z * DD * DD;
    __nv_bfloat16* Tl = g_Wtl + (size_t)z * DD * DD;
#pragma unroll
    for (int r = 0; r < 32; r += 8) {
        const int n = n0 + ty + r, k = k0 + tx;
        const float v = tile[tx][ty + r] * scale;
        __nv_bfloat16 h = __float2bfloat16(v);
        __nv_bfloat16 l = __float2bfloat16(v - __bfloat162float(h));
        Th[(size_t)n * DD + k] = h;
        Tl[(size_t)n * DD + k] = l;
    }
}

// ---------------------------------------------------------------------------
// Pure-bf16 HMMA GEMM, 512 threads, 16 warps, warp tile 32x32.
// 3-stage cp.async pipeline (wait_group 1).
// ---------------------------------------------------------------------------
constexpr int BK   = 32;
constexpr int NITER = DD / BK;          // 32
constexpr int GST  = 40;
constexpr int GOP  = 128 * GST * 2;     // 10240 B
constexpr int GBUF = 4 * GOP;           // 40960 B
constexpr int SMEM_GEMM = 3 * GBUF;     // 122880 B

template <int MODE>
__device__ __forceinline__ void gemm_core(const __nv_bfloat16* __restrict__ Ah_g,
                                          const __nv_bfloat16* __restrict__ Al_g,
                                          const __nv_bfloat16* __restrict__ Bh_g,
                                          const __nv_bfloat16* __restrict__ Bl_g,
                                          float* __restrict__ Cf,
                                          __nv_bfloat16* __restrict__ Ch,
                                          __nv_bfloat16* __restrict__ Cl,
                                          int bx, int by)
{
    extern __shared__ char smem[];
    const uint32_t sb = smem_to_u32(smem);
    const int tid  = threadIdx.x;
    const int lane = tid & 31;
    const int wid  = tid >> 5;
    const int wm   = wid >> 2;
    const int wn   = wid & 3;
    const int m0 = by * 128, n0 = bx * 128;

    float acc[2][4][4];
#pragma unroll
    for (int i = 0; i < 2; i++)
#pragma unroll
        for (int j = 0; j < 4; j++)
#pragma unroll
            for (int k = 0; k < 4; k++) acc[i][j][k] = 0.0f;

    const int ld_row = tid >> 2;
    const int ld_c   = tid & 3;
    auto issue = [&](int buf, int k0) {
        const uint32_t base = sb + buf * GBUF;
        const uint32_t soff = (uint32_t)(ld_row * GST + ld_c * 8) * 2;
        const size_t ga = (size_t)(m0 + ld_row) * DD + k0 + ld_c * 8;
        const size_t gb = (size_t)(n0 + ld_row) * DD + k0 + ld_c * 8;
        cp_async16(base + soff,           Ah_g + ga);
        cp_async16(base + GOP + soff,     Al_g + ga);
        cp_async16(base + 2 * GOP + soff, Bh_g + gb);
        cp_async16(base + 3 * GOP + soff, Bl_g + gb);
        CP_COMMIT();
    };

    const int ar = wm * 32 + (lane & 15);
    const int ac = (lane >> 4) * 8;
    const int br = wn * 32 + (lane & 15);
    const int bc = (lane >> 4) * 8;

    auto compute = [&](int buf) {
        const uint32_t ah_b = sb + buf * GBUF;
        const uint32_t al_b = ah_b + GOP;
        const uint32_t bh_b = al_b + GOP;
        const uint32_t bl_b = bh_b + GOP;
#pragma unroll
        for (int ks = 0; ks < 2; ks++) {
            uint32_t ah[2][4], al[2][4], bh[2][4], bl[2][4];
#pragma unroll
            for (int mf = 0; mf < 2; mf++) {
                const uint32_t off = (uint32_t)(((ar + mf * 16) * GST + ks * 16 + ac) * 2);
                ldsm_x4(ah[mf][0], ah[mf][1], ah[mf][2], ah[mf][3], ah_b + off);
                ldsm_x4(al[mf][0], al[mf][1], al[mf][2], al[mf][3], al_b + off);
            }
#pragma unroll
            for (int g = 0; g < 2; g++) {
                const uint32_t off = (uint32_t)(((br + g * 16) * GST + ks * 16 + bc) * 2);
                ldsm_x4(bh[g][0], bh[g][1], bh[g][2], bh[g][3], bh_b + off);
                ldsm_x4(bl[g][0], bl[g][1], bl[g][2], bl[g][3], bl_b + off);
            }
#pragma unroll
            for (int mf = 0; mf < 2; mf++)
#pragma unroll
                for (int g = 0; g < 2; g++)
#pragma unroll
                    for (int sub = 0; sub < 2; sub++) {
                        const int nf = g * 2 + sub;
                        mma_bf16(acc[mf][nf], ah[mf], bh[g][sub], bh[g][sub + 2]);
                        mma_bf16(acc[mf][nf], al[mf], bh[g][sub], bh[g][sub + 2]);
                        mma_bf16(acc[mf][nf], ah[mf], bl[g][sub], bl[g][sub + 2]);
                    }
        }
    };

    issue(0, 0);
    issue(1, BK);
    for (int it = 0; it < NITER; ++it) {
        CP_WAIT1();                       // tile `it` arrived (tile it+1 may be in flight)
        __syncthreads();
        if (it + 2 < NITER) issue((it + 2) % 3, (it + 2) * BK);
        compute(it % 3);
    }

    const int group = lane >> 2;
    const int qd    = lane & 3;
#pragma unroll
    for (int mf = 0; mf < 2; mf++)
#pragma unroll
        for (int nf = 0; nf < 4; nf++) {
            const int rg = m0 + wm * 32 + mf * 16 + group;
            const int cg = n0 + wn * 32 + nf * 8 + qd * 2;
            if (MODE == 0) {
                const int bbi = rg >> 11;
                const int t   = rg & 2047;
                const int h   = cg >> 6;
                const int dd  = cg & 63;
                const size_t i0 = (((size_t)bbi * HH + h) * TT + t) * DHD + dd;
                const size_t i1 = i0 + (size_t)8 * DHD;
                uint32_t hw, lw;
                split2(acc[mf][nf][0], acc[mf][nf][1], hw, lw);
                *reinterpret_cast<uint32_t*>(Ch + i0) = hw;
                *reinterpret_cast<uint32_t*>(Cl + i0) = lw;
                split2(acc[mf][nf][2], acc[mf][nf][3], hw, lw);
                *reinterpret_cast<uint32_t*>(Ch + i1) = hw;
                *reinterpret_cast<uint32_t*>(Cl + i1) = lw;
            } else {
                *reinterpret_cast<float2*>(Cf + (size_t)rg * DD + cg) =
                    make_float2(acc[mf][nf][0], acc[mf][nf][1]);
                *reinterpret_cast<float2*>(Cf + (size_t)(rg + 8) * DD + cg) =
                    make_float2(acc[mf][nf][2], acc[mf][nf][3]);
            }
        }
}

__global__ void __launch_bounds__(512, 1)
qkv_mma_kernel()
{
    const int z = blockIdx.z;
    const __nv_bfloat16* Bh = g_Wth + (size_t)z * DD * DD;
    const __nv_bfloat16* Bl = g_Wtl + (size_t)z * DD * DD;
    __nv_bfloat16* Ch = (z == 0) ? g_Qh : (z == 1) ? g_Kh : g_Vh;
    __nv_bfloat16* Cl = (z == 0) ? g_Ql : (z == 1) ? g_Kl : g_Vl;
    gemm_core<0>(g_xh, g_xl, Bh, Bl, nullptr, Ch, Cl, blockIdx.x, blockIdx.y);
}

__global__ void __launch_bounds__(512, 1)
proj_mma_kernel(float* __restrict__ out)
{
    gemm_core<1>(g_Oh, g_Ol, g_Wth + (size_t)3 * DD * DD, g_Wtl + (size_t)3 * DD * DD,
                 out, nullptr, nullptr, blockIdx.x, blockIdx.y);
}

// ---------------------------------------------------------------------------
// HMMA flash attention: pipelined (S(j+1) overlaps softmax(j)/PV(j)),
// 3 KV buffers, K AND V both via cp.async in natural [key][dh] layout,
// V fragments via ldmatrix.trans (no scalar transpose).
// 256 threads, q-tile 128, exp2 domain, deferred l-reduction.
// ---------------------------------------------------------------------------
constexpr int AQT   = 128;
constexpr int AST   = 72;
constexpr int AQOP  = AQT * AST * 2;       // 18432 B
constexpr int AKOP  = 64 * AST * 2;        // 9216 B
constexpr int AKVB  = 4 * AKOP;            // 36864 B (Kh,Kl,Vh,Vl)
constexpr int AOFFK = 2 * AQOP;            // 36864
constexpr int SMEM_ATTN = AOFFK + 3 * AKVB;   // 147456 B

__global__ void __launch_bounds__(256, 1)
attn_mma_kernel()
{
    extern __shared__ char smem[];
    const uint32_t sb = smem_to_u32(smem);
    const int bh  = blockIdx.y;
    const int bbi = bh / HH;
    const int h   = bh % HH;
    const int qt  = (int)gridDim.x - 1 - (int)blockIdx.x;
    const int tid = threadIdx.x;
    const int lane = tid & 31;
    const int wq   = tid >> 5;            // 0..7

    const size_t headoff = (size_t)bh * TT * DHD;

    // ---- Q resident ----
    {
        const int row = tid >> 1;
        const int c0  = (tid & 1) * 32;
        const size_t src = headoff + (size_t)(qt * AQT + row) * DHD + c0;
        const uint4* shq = reinterpret_cast<const uint4*>(g_Qh + src);
        const uint4* slq = reinterpret_cast<const uint4*>(g_Ql + src);
        char* ph = smem + (row * AST + c0) * 2;
        char* pl = ph + AQOP;
#pragma unroll
        for (int j = 0; j < 4; j++) {
            *reinterpret_cast<uint4*>(ph + 16 * j) = shq[j];
            *reinterpret_cast<uint4*>(pl + 16 * j) = slq[j];
        }
    }

    float accO[8][4];
#pragma unroll
    for (int i = 0; i < 8; i++)
#pragma unroll
        for (int j = 0; j < 4; j++) accO[i][j] = 0.0f;
    float accA[8][4], accB[8][4];
    float mrow[2] = {-1e30f, -1e30f};
    float lrow[2] = {0.0f, 0.0f};

    const int qmin_w = qt * AQT + wq * 16;
    const int qmax_w = qmin_w + 15;
    const int r0loc  = qmin_w + (lane >> 2);
    const int ntiles = 2 * (qt + 1);

    // KV loader: 256 threads, 64 rows x 64 cols, K+V hi/lo, one group
    const int kv_row = tid >> 2;          // 0..63
    const int kv_c16 = (tid & 3) * 16;    // 0,16,32,48

    auto issueKV = [&](int jt, int buf) {
        const uint32_t base = sb + AOFFK + buf * AKVB;
        const uint32_t soff = (uint32_t)(kv_row * AST + kv_c16) * 2;
        const size_t src = headoff + (size_t)(jt * 64 + kv_row) * DHD + kv_c16;
        cp_async16(base + soff,                 g_Kh + src);
        cp_async16(base + soff + 16,            g_Kh + src + 8);
        cp_async16(base + AKOP + soff,          g_Kl + src);
        cp_async16(base + AKOP + soff + 16,     g_Kl + src + 8);
        cp_async16(base + 2 * AKOP + soff,      g_Vh + src);
        cp_async16(base + 2 * AKOP + soff + 16, g_Vh + src + 8);
        cp_async16(base + 3 * AKOP + soff,      g_Vl + src);
        cp_async16(base + 3 * AKOP + soff + 16, g_Vl + src + 8);
        CP_COMMIT();
    };

    const int fr = lane & 15;
    const int fc = (lane >> 4) * 8;
    // trans-ldmatrix lane addressing for V [key][dh]:
    const int vkey = (lane & 7) + ((lane >> 4) << 3);   // key within 16-block
    const int vdh  = ((lane >> 3) & 1) << 3;            // dh 8-offset within 16-block

    // S: Q·K^T for tile jt into acc
    auto sphase = [&](int jt, float (*acc)[4]) {
        const uint32_t kvb = sb + AOFFK + (jt % 3) * AKVB;
        const uint32_t qhb = sb;
        const uint32_t qlb = sb + AQOP;
#pragma unroll
        for (int i = 0; i < 8; i++)
#pragma unroll
            for (int j = 0; j < 4; j++) acc[i][j] = 0.0f;
#pragma unroll
        for (int ks = 0; ks < 4; ks++) {
            uint32_t qh[4], ql[4];
            const uint32_t qoff = (uint32_t)(((wq * 16 + fr) * AST + ks * 16 + fc) * 2);
            ldsm_x4(qh[0], qh[1], qh[2], qh[3], qhb + qoff);
            ldsm_x4(ql[0], ql[1], ql[2], ql[3], qlb + qoff);
#pragma unroll
            for (int g = 0; g < 4; g++) {
                uint32_t kh[4], kl[4];
                const uint32_t koff = (uint32_t)(((g * 16 + fr) * AST + ks * 16 + fc) * 2);
                ldsm_x4(kh[0], kh[1], kh[2], kh[3], kvb + koff);
                ldsm_x4(kl[0], kl[1], kl[2], kl[3], kvb + AKOP + koff);
#pragma unroll
                for (int sub = 0; sub < 2; sub++) {
                    const int nf = g * 2 + sub;
                    mma_bf16(acc[nf], qh, kh[sub], kh[sub + 2]);
                    mma_bf16(acc[nf], ql, kh[sub], kh[sub + 2]);
                    mma_bf16(acc[nf], qh, kl[sub], kl[sub + 2]);
                }
            }
        }
    };

    // ---- prologue ----
    issueKV(0, 0);
    issueKV(1, 1);
    CP_WAIT1();                      // tile 0 arrived
    __syncthreads();
    sphase(0, accA);

    // ---- pipelined mainloop ----
    auto iterate = [&](int j, float (*cur)[4], float (*nxt)[4]) {
        const int key0 = j * 64;
        const bool live = (key0 <= qmax_w);

        // prefetch tile j+2 into buf (j+2)%3 (its last reader, PV(j-1), is done)
        if (j + 2 < ntiles) issueKV(j + 2, (j + 2) % 3);

        uint32_t p01h[8], p01l[8], p23h[8], p23l[8];
        float corr0 = 1.0f, corr1 = 1.0f;
        if (live) {
            if (key0 + 63 > qmin_w) {
                const int r1loc = r0loc + 8;
#pragma unroll
                for (int nf = 0; nf < 8; nf++) {
                    const int c = key0 + nf * 8 + 2 * (lane & 3);
                    if (c     > r0loc) cur[nf][0] = -1e30f;
                    if (c + 1 > r0loc) cur[nf][1] = -1e30f;
                    if (c     > r1loc) cur[nf][2] = -1e30f;
                    if (c + 1 > r1loc) cur[nf][3] = -1e30f;
                }
            }
            float ml0 = -1e30f, ml1 = -1e30f;
#pragma unroll
            for (int nf = 0; nf < 8; nf++) {
                ml0 = fmaxf(ml0, fmaxf(cur[nf][0], cur[nf][1]));
                ml1 = fmaxf(ml1, fmaxf(cur[nf][2], cur[nf][3]));
            }
            ml0 = fmaxf(ml0, __shfl_xor_sync(0xffffffffu, ml0, 1));
            ml0 = fmaxf(ml0, __shfl_xor_sync(0xffffffffu, ml0, 2));
            ml1 = fmaxf(ml1, __shfl_xor_sync(0xffffffffu, ml1, 1));
            ml1 = fmaxf(ml1, __shfl_xor_sync(0xffffffffu, ml1, 2));
            const float mn0 = fmaxf(mrow[0], ml0);
            const float mn1 = fmaxf(mrow[1], ml1);
            corr0 = ex2f(mrow[0] - mn0);
            corr1 = ex2f(mrow[1] - mn1);
            mrow[0] = mn0; mrow[1] = mn1;

            float ls0 = 0.0f, ls1 = 0.0f;
#pragma unroll
            for (int nf = 0; nf < 8; nf++) {
                cur[nf][0] = ex2f(cur[nf][0] - mn0);
                cur[nf][1] = ex2f(cur[nf][1] - mn0);
                cur[nf][2] = ex2f(cur[nf][2] - mn1);
                cur[nf][3] = ex2f(cur[nf][3] - mn1);
                ls0 += cur[nf][0] + cur[nf][1];
                ls1 += cur[nf][2] + cur[nf][3];
            }
            lrow[0] = lrow[0] * corr0 + ls0;   // per-thread partial; quad-reduce at end
            lrow[1] = lrow[1] * corr1 + ls1;
#pragma unroll
            for (int nf = 0; nf < 8; nf++) {
                split2(cur[nf][0], cur[nf][1], p01h[nf], p01l[nf]);
                split2(cur[nf][2], cur[nf][3], p23h[nf], p23l[nf]);
            }
        }

        // tile j+1 arrived (issued last iter; j+2 still in flight)
        CP_WAIT1();
        __syncthreads();

        // ---- S(j+1): independent of softmax(j); fills the latency gaps ----
        if (j + 1 < ntiles) sphase(j + 1, nxt);

        // ---- PV(j) ----
        if (live) {
#pragma unroll
            for (int nf = 0; nf < 8; nf++) {
                accO[nf][0] *= corr0; accO[nf][1] *= corr0;
                accO[nf][2] *= corr1; accO[nf][3] *= corr1;
            }
            const uint32_t vhb = sb + AOFFK + (j % 3) * AKVB + 2 * AKOP;
#pragma unroll
            for (int kp = 0; kp < 4; kp++) {
                uint32_t ah[4] = {p01h[2*kp], p23h[2*kp], p01h[2*kp+1], p23h[2*kp+1]};
                uint32_t al[4] = {p01l[2*kp], p23l[2*kp], p01l[2*kp+1], p23l[2*kp+1]};
#pragma unroll
                for (int vg = 0; vg < 4; vg++) {
                    uint32_t vh[4], vl[4];
                    const uint32_t voff =
                        (uint32_t)(((kp * 16 + vkey) * AST + vg * 16 + vdh) * 2);
                    ldsm_x4_t(vh[0], vh[1], vh[2], vh[3], vhb + voff);
                    ldsm_x4_t(vl[0], vl[1], vl[2], vl[3], vhb + AKOP + voff);
#pragma unroll
                    for (int sub = 0; sub < 2; sub++) {
                        const int nf = vg * 2 + sub;
                        mma_bf16(accO[nf], ah, vh[sub], vh[sub + 2]);
                        mma_bf16(accO[nf], al, vh[sub], vh[sub + 2]);
                        mma_bf16(accO[nf], ah, vl[sub], vl[sub + 2]);
                    }
                }
            }
        }

        __syncthreads();                 // all warps done reading buf j%3
    };

    for (int j = 0; j < ntiles; j += 2) {
        iterate(j,     accA, accB);
        iterate(j + 1, accB, accA);
    }

    // ---- epilogue: finish deferred l-reduction, normalize, split, store ----
    lrow[0] += __shfl_xor_sync(0xffffffffu, lrow[0], 1);
    lrow[0] += __shfl_xor_sync(0xffffffffu, lrow[0], 2);
    lrow[1] += __shfl_xor_sync(0xffffffffu, lrow[1], 1);
    lrow[1] += __shfl_xor_sync(0xffffffffu, lrow[1], 2);
    const float inv0 = 1.0f / lrow[0];
    const float inv1 = 1.0f / lrow[1];
    const int q0 = qt * AQT + wq * 16 + (lane >> 2);
    const int q1 = q0 + 8;
#pragma unroll
    for (int nf = 0; nf < 8; nf++) {
        const int col = h * DHD + nf * 8 + 2 * (lane & 3);
        uint32_t hw, lw;
        split2(accO[nf][0] * inv0, accO[nf][1] * inv0, hw, lw);
        *reinterpret_cast<uint32_t*>(g_Oh + ((size_t)bbi * TT + q0) * DD + col) = hw;
        *reinterpret_cast<uint32_t*>(g_Ol + ((size_t)bbi * TT + q0) * DD + col) = lw;
        split2(accO[nf][2] * inv1, accO[nf][3] * inv1, hw, lw);
        *reinterpret_cast<uint32_t*>(g_Oh + ((size_t)bbi * TT + q1) * DD + col) = hw;
        *reinterpret_cast<uint32_t*>(g_Ol + ((size_t)bbi * TT + q1) * DD + col) = lw;
    }
}

// ---------------------------------------------------------------------------
extern "C" void kernel_launch(void* const* d_in, const int* in_sizes, int n_in,
                              void* d_out, int out_size)
{
    (void)in_sizes; (void)n_in; (void)out_size;
    const float* x  = (const float*)d_in[0];
    // d_in[1] is the causal mask — statically known, ignored
    const float* Wq = (const float*)d_in[2];
    const float* Wk = (const float*)d_in[3];
    const float* Wv = (const float*)d_in[4];
    const float* Wo = (const float*)d_in[5];
    float* out = (float*)d_out;

    cudaFuncSetAttribute(qkv_mma_kernel,  cudaFuncAttributeMaxDynamicSharedMemorySize, SMEM_GEMM);
    cudaFuncSetAttribute(proj_mma_kernel, cudaFuncAttributeMaxDynamicSharedMemorySize, SMEM_GEMM);
    cudaFuncSetAttribute(attn_mma_kernel, cudaFuncAttributeMaxDynamicSharedMemorySize, SMEM_ATTN);

    // 0. split x + transpose/split W (Wq pre-scaled by 0.125*log2e)
    prep_split_x<<<MM * DD / (256 * 8), 256>>>(x);
    dim3 gw(DD / 32, DD / 32, 4);
    prep_wt<<<gw, 256>>>(Wq, Wk, Wv, Wo);

    // 1. QKV projections (3-stage pipelined)
    dim3 g1(DD / 128, MM / 128, 3);
    qkv_mma_kernel<<<g1, 512, SMEM_GEMM>>>();

    // 2. causal flash attention (pipelined, trans-ldmatrix V)
    dim3 g2(TT / AQT, BB * HH);
    attn_mma_kernel<<<g2, 256, SMEM_ATTN>>>();

    // 3. output projection
    dim3 g3(DD / 128, MM / 128);
    proj_mma_kernel<<<g3, 512, SMEM_GEMM>>>(out);
}

// round 13
// speedup vs baseline: 3.1299x; 1.0521x over previous
#include <cuda_runtime.h>
#include <cuda_bf16.h>
#include <math.h>
#include <stdint.h>

// Problem constants
constexpr int BB  = 2;
constexpr int TT  = 2048;
constexpr int DD  = 1024;
constexpr int HH  = 16;
constexpr int DHD = 64;
constexpr int MM  = BB * TT;     // 4096

// Pre-split bf16 scratch (device globals)
__device__ __nv_bfloat16 g_xh[MM * DD], g_xl[MM * DD];
__device__ __nv_bfloat16 g_Wth[4 * DD * DD], g_Wtl[4 * DD * DD];  // W^T hi/lo (Wq pre-scaled by 0.125*log2e)
__device__ __nv_bfloat16 g_Qh[MM * DD], g_Ql[MM * DD];            // head-major
__device__ __nv_bfloat16 g_Kh[MM * DD], g_Kl[MM * DD];
__device__ __nv_bfloat16 g_Vh[MM * DD], g_Vl[MM * DD];
__device__ __nv_bfloat16 g_Oh[MM * DD], g_Ol[MM * DD];            // token-major

// ---------------------------------------------------------------------------
// PTX helpers
// ---------------------------------------------------------------------------
__device__ __forceinline__ void ldsm_x4(uint32_t& r0, uint32_t& r1,
                                        uint32_t& r2, uint32_t& r3, uint32_t addr) {
    asm volatile("ldmatrix.sync.aligned.m8n8.x4.shared.b16 {%0,%1,%2,%3}, [%4];"
                 : "=r"(r0), "=r"(r1), "=r"(r2), "=r"(r3) : "r"(addr));
}

__device__ __forceinline__ void ldsm_x4_t(uint32_t& r0, uint32_t& r1,
                                          uint32_t& r2, uint32_t& r3, uint32_t addr) {
    asm volatile("ldmatrix.sync.aligned.m8n8.x4.trans.shared.b16 {%0,%1,%2,%3}, [%4];"
                 : "=r"(r0), "=r"(r1), "=r"(r2), "=r"(r3) : "r"(addr));
}

__device__ __forceinline__ void mma_bf16(float* d, const uint32_t* a,
                                         uint32_t b0, uint32_t b1) {
    asm volatile(
        "mma.sync.aligned.m16n8k16.row.col.f32.bf16.bf16.f32 "
        "{%0,%1,%2,%3}, {%4,%5,%6,%7}, {%8,%9}, {%0,%1,%2,%3};"
        : "+f"(d[0]), "+f"(d[1]), "+f"(d[2]), "+f"(d[3])
        : "r"(a[0]), "r"(a[1]), "r"(a[2]), "r"(a[3]), "r"(b0), "r"(b1));
}

__device__ __forceinline__ uint32_t smem_to_u32(const void* p) {
    uint32_t a;
    asm("{ .reg .u64 t; cvta.to.shared.u64 t, %1; cvt.u32.u64 %0, t; }"
        : "=r"(a) : "l"(p));
    return a;
}

__device__ __forceinline__ void cp_async16(uint32_t dst, const void* src) {
    asm volatile("cp.async.cg.shared.global [%0], [%1], 16;" :: "r"(dst), "l"(src));
}
#define CP_COMMIT() asm volatile("cp.async.commit_group;" ::: "memory")
#define CP_WAIT0()  asm volatile("cp.async.wait_group 0;"  ::: "memory")
#define CP_WAIT1()  asm volatile("cp.async.wait_group 1;"  ::: "memory")

__device__ __forceinline__ float ex2f(float x) {
    float r;
    asm("ex2.approx.f32 %0, %1;" : "=f"(r) : "f"(x));
    return r;
}

__device__ __forceinline__ uint32_t pack_bf2(__nv_bfloat16 a, __nv_bfloat16 b) {
    __nv_bfloat162 t = __halves2bfloat162(a, b);
    return *reinterpret_cast<uint32_t*>(&t);
}

__device__ __forceinline__ void split2(float f0, float f1, uint32_t& hw, uint32_t& lw) {
    __nv_bfloat16 h0 = __float2bfloat16(f0);
    __nv_bfloat16 h1 = __float2bfloat16(f1);
    __nv_bfloat16 l0 = __float2bfloat16(f0 - __bfloat162float(h0));
    __nv_bfloat16 l1 = __float2bfloat16(f1 - __bfloat162float(h1));
    hw = pack_bf2(h0, h1);
    lw = pack_bf2(l0, l1);
}

// ---------------------------------------------------------------------------
// Prep kernels
// ---------------------------------------------------------------------------
__global__ void __launch_bounds__(256)
prep_split_x(const float* __restrict__ x)
{
    const size_t i = ((size_t)blockIdx.x * 256 + threadIdx.x) * 8;
    float4 f0 = *reinterpret_cast<const float4*>(x + i);
    float4 f1 = *reinterpret_cast<const float4*>(x + i + 4);
    uint32_t h[4], l[4];
    split2(f0.x, f0.y, h[0], l[0]); split2(f0.z, f0.w, h[1], l[1]);
    split2(f1.x, f1.y, h[2], l[2]); split2(f1.z, f1.w, h[3], l[3]);
    *reinterpret_cast<uint4*>(g_xh + i) = make_uint4(h[0], h[1], h[2], h[3]);
    *reinterpret_cast<uint4*>(g_xl + i) = make_uint4(l[0], l[1], l[2], l[3]);
}

__global__ void __launch_bounds__(256)
prep_wt(const float* __restrict__ Wq, const float* __restrict__ Wk,
        const float* __restrict__ Wv, const float* __restrict__ Wo)
{
    const int z = blockIdx.z;
    const float* W = (z == 0) ? Wq : (z == 1) ? Wk : (z == 2) ? Wv : Wo;
    const float scale = (z == 0) ? 0.18033688011112042f : 1.0f;  // (1/8)*log2(e)
    __shared__ float tile[32][33];
    const int k0 = blockIdx.y * 32, n0 = blockIdx.x * 32;
    const int tx = threadIdx.x & 31, ty = threadIdx.x >> 5;
#pragma unroll
    for (int r = 0; r < 32; r += 8)
        tile[ty + r][tx] = W[(size_t)(k0 + ty + r) * DD + n0 + tx];
    __syncthreads();
    __nv_bfloat16* Th = g_Wth + (size_t)z * DD * DD;
    __nv_bfloat16* Tl = g_Wtl + (size_t)z * DD * DD;
#pragma unroll
    for (int r = 0; r < 32; r += 8) {
        const int n = n0 + ty + r, k = k0 + tx;
        const float v = tile[tx][ty + r] * scale;
        __nv_bfloat16 h = __float2bfloat16(v);
        __nv_bfloat16 l = __float2bfloat16(v - __bfloat162float(h));
        Th[(size_t)n * DD + k] = h;
        Tl[(size_t)n * DD + k] = l;
    }
}

// ---------------------------------------------------------------------------
// Pure-bf16 HMMA GEMM, 512 threads, 16 warps, warp tile 32x32.  (unchanged)
// ---------------------------------------------------------------------------
constexpr int BK   = 32;
constexpr int NITER = DD / BK;          // 32
constexpr int GST  = 40;
constexpr int GOP  = 128 * GST * 2;     // 10240 B
constexpr int GBUF = 4 * GOP;           // 40960 B
constexpr int SMEM_GEMM = 3 * GBUF;     // 122880 B

template <int MODE>
__device__ __forceinline__ void gemm_core(const __nv_bfloat16* __restrict__ Ah_g,
                                          const __nv_bfloat16* __restrict__ Al_g,
                                          const __nv_bfloat16* __restrict__ Bh_g,
                                          const __nv_bfloat16* __restrict__ Bl_g,
                                          float* __restrict__ Cf,
                                          __nv_bfloat16* __restrict__ Ch,
                                          __nv_bfloat16* __restrict__ Cl,
                                          int bx, int by)
{
    extern __shared__ char smem[];
    const uint32_t sb = smem_to_u32(smem);
    const int tid  = threadIdx.x;
    const int lane = tid & 31;
    const int wid  = tid >> 5;
    const int wm   = wid >> 2;
    const int wn   = wid & 3;
    const int m0 = by * 128, n0 = bx * 128;

    float acc[2][4][4];
#pragma unroll
    for (int i = 0; i < 2; i++)
#pragma unroll
        for (int j = 0; j < 4; j++)
#pragma unroll
            for (int k = 0; k < 4; k++) acc[i][j][k] = 0.0f;

    const int ld_row = tid >> 2;
    const int ld_c   = tid & 3;
    auto issue = [&](int buf, int k0) {
        const uint32_t base = sb + buf * GBUF;
        const uint32_t soff = (uint32_t)(ld_row * GST + ld_c * 8) * 2;
        const size_t ga = (size_t)(m0 + ld_row) * DD + k0 + ld_c * 8;
        const size_t gb = (size_t)(n0 + ld_row) * DD + k0 + ld_c * 8;
        cp_async16(base + soff,           Ah_g + ga);
        cp_async16(base + GOP + soff,     Al_g + ga);
        cp_async16(base + 2 * GOP + soff, Bh_g + gb);
        cp_async16(base + 3 * GOP + soff, Bl_g + gb);
        CP_COMMIT();
    };

    const int ar = wm * 32 + (lane & 15);
    const int ac = (lane >> 4) * 8;
    const int br = wn * 32 + (lane & 15);
    const int bc = (lane >> 4) * 8;

    auto compute = [&](int buf) {
        const uint32_t ah_b = sb + buf * GBUF;
        const uint32_t al_b = ah_b + GOP;
        const uint32_t bh_b = al_b + GOP;
        const uint32_t bl_b = bh_b + GOP;
#pragma unroll
        for (int ks = 0; ks < 2; ks++) {
            uint32_t ah[2][4], al[2][4], bh[2][4], bl[2][4];
#pragma unroll
            for (int mf = 0; mf < 2; mf++) {
                const uint32_t off = (uint32_t)(((ar + mf * 16) * GST + ks * 16 + ac) * 2);
                ldsm_x4(ah[mf][0], ah[mf][1], ah[mf][2], ah[mf][3], ah_b + off);
                ldsm_x4(al[mf][0], al[mf][1], al[mf][2], al[mf][3], al_b + off);
            }
#pragma unroll
            for (int g = 0; g < 2; g++) {
                const uint32_t off = (uint32_t)(((br + g * 16) * GST + ks * 16 + bc) * 2);
                ldsm_x4(bh[g][0], bh[g][1], bh[g][2], bh[g][3], bh_b + off);
                ldsm_x4(bl[g][0], bl[g][1], bl[g][2], bl[g][3], bl_b + off);
            }
#pragma unroll
            for (int mf = 0; mf < 2; mf++)
#pragma unroll
                for (int g = 0; g < 2; g++)
#pragma unroll
                    for (int sub = 0; sub < 2; sub++) {
                        const int nf = g * 2 + sub;
                        mma_bf16(acc[mf][nf], ah[mf], bh[g][sub], bh[g][sub + 2]);
                        mma_bf16(acc[mf][nf], al[mf], bh[g][sub], bh[g][sub + 2]);
                        mma_bf16(acc[mf][nf], ah[mf], bl[g][sub], bl[g][sub + 2]);
                    }
        }
    };

    issue(0, 0);
    issue(1, BK);
    for (int it = 0; it < NITER; ++it) {
        CP_WAIT1();
        __syncthreads();
        if (it + 2 < NITER) issue((it + 2) % 3, (it + 2) * BK);
        compute(it % 3);
    }

    const int group = lane >> 2;
    const int qd    = lane & 3;
#pragma unroll
    for (int mf = 0; mf < 2; mf++)
#pragma unroll
        for (int nf = 0; nf < 4; nf++) {
            const int rg = m0 + wm * 32 + mf * 16 + group;
            const int cg = n0 + wn * 32 + nf * 8 + qd * 2;
            if (MODE == 0) {
                const int bbi = rg >> 11;
                const int t   = rg & 2047;
                const int h   = cg >> 6;
                const int dd  = cg & 63;
                const size_t i0 = (((size_t)bbi * HH + h) * TT + t) * DHD + dd;
                const size_t i1 = i0 + (size_t)8 * DHD;
                uint32_t hw, lw;
                split2(acc[mf][nf][0], acc[mf][nf][1], hw, lw);
                *reinterpret_cast<uint32_t*>(Ch + i0) = hw;
                *reinterpret_cast<uint32_t*>(Cl + i0) = lw;
                split2(acc[mf][nf][2], acc[mf][nf][3], hw, lw);
                *reinterpret_cast<uint32_t*>(Ch + i1) = hw;
                *reinterpret_cast<uint32_t*>(Cl + i1) = lw;
            } else {
                *reinterpret_cast<float2*>(Cf + (size_t)rg * DD + cg) =
                    make_float2(acc[mf][nf][0], acc[mf][nf][1]);
                *reinterpret_cast<float2*>(Cf + (size_t)(rg + 8) * DD + cg) =
                    make_float2(acc[mf][nf][2], acc[mf][nf][3]);
            }
        }
}

__global__ void __launch_bounds__(512, 1)
qkv_mma_kernel()
{
    const int z = blockIdx.z;
    const __nv_bfloat16* Bh = g_Wth + (size_t)z * DD * DD;
    const __nv_bfloat16* Bl = g_Wtl + (size_t)z * DD * DD;
    __nv_bfloat16* Ch = (z == 0) ? g_Qh : (z == 1) ? g_Kh : g_Vh;
    __nv_bfloat16* Cl = (z == 0) ? g_Ql : (z == 1) ? g_Kl : g_Vl;
    gemm_core<0>(g_xh, g_xl, Bh, Bl, nullptr, Ch, Cl, blockIdx.x, blockIdx.y);
}

__global__ void __launch_bounds__(512, 1)
proj_mma_kernel(float* __restrict__ out)
{
    gemm_core<1>(g_Oh, g_Ol, g_Wth + (size_t)3 * DD * DD, g_Wtl + (size_t)3 * DD * DD,
                 out, nullptr, nullptr, blockIdx.x, blockIdx.y);
}

// ---------------------------------------------------------------------------
// Warp-specialized HMMA flash attention:
//   warps 0-7  (S-warps):  S = Q K^T, softmax, write P(hi/lo)+corr to smem
//   warps 8-15 (PV-warps): O += P V, one tile behind
// 512 threads, q-tile 128, 3 KV buffers, 2 P buffers, one barrier per phase.
// Math identical to previous round (same split points, same term set).
// ---------------------------------------------------------------------------
constexpr int AQT   = 128;
constexpr int AST   = 72;
constexpr int AQOP  = AQT * AST * 2;       // 18432 B per Q component
constexpr int AKOP  = 64 * AST * 2;        // 9216 B per KV component
constexpr int AKVB  = 4 * AKOP;            // 36864 B (Kh,Kl,Vh,Vl)
constexpr int AOFFK = 2 * AQOP;            // 36864
constexpr int POP   = AQT * AST * 2;       // 18432 B per P component
constexpr int PBUF  = 2 * POP;             // 36864 (hi+lo)
constexpr int AOFFP = AOFFK + 3 * AKVB;    // 147456
constexpr int AOFFC = AOFFP + 2 * PBUF;    // 221184 (corr[2][128] floats)
constexpr int AOFFL = AOFFC + 1024;        // 222208 (l[128] floats)
constexpr int SMEM_ATTN = AOFFL + 512;     // 222720 B

__global__ void __launch_bounds__(512, 1)
attn_ws_kernel()
{
    extern __shared__ char smem[];
    const uint32_t sb = smem_to_u32(smem);
    const int bh  = blockIdx.y;
    const int bbi = bh / HH;
    const int h   = bh % HH;
    const int qt  = (int)gridDim.x - 1 - (int)blockIdx.x;
    const int tid = threadIdx.x;
    const int lane = tid & 31;
    const int wq   = tid >> 5;            // 0..15
    const bool isS = wq < 8;
    const int rw   = wq & 7;              // row-warp id (rows rw*16..rw*16+15)

    const size_t headoff = (size_t)bh * TT * DHD;

    // ---- Q resident (all 512 threads) ----
    {
        const int row = tid >> 2;
        const int c16 = (tid & 3) * 16;
        const size_t src = headoff + (size_t)(qt * AQT + row) * DHD + c16;
        const uint4* shq = reinterpret_cast<const uint4*>(g_Qh + src);
        const uint4* slq = reinterpret_cast<const uint4*>(g_Ql + src);
        char* ph = smem + (row * AST + c16) * 2;
        char* pl = ph + AQOP;
        *reinterpret_cast<uint4*>(ph)      = shq[0];
        *reinterpret_cast<uint4*>(ph + 16) = shq[1];
        *reinterpret_cast<uint4*>(pl)      = slq[0];
        *reinterpret_cast<uint4*>(pl + 16) = slq[1];
    }

    float accO[8][4];
#pragma unroll
    for (int i = 0; i < 8; i++)
#pragma unroll
        for (int j = 0; j < 4; j++) accO[i][j] = 0.0f;
    float mrow[2] = {-1e30f, -1e30f};
    float lrow[2] = {0.0f, 0.0f};

    const int qmin_w = qt * AQT + rw * 16;
    const int qmax_w = qmin_w + 15;
    const int r0loc  = qmin_w + (lane >> 2);
    const int ntiles = 2 * (qt + 1);

    // KV loader: 512 threads, 64 rows x 64 cols, 4 arrays, 1 cp each
    const int kv_row = tid >> 3;          // 0..63
    const int kv_c8  = (tid & 7) * 8;     // 0..56

    auto issueKV = [&](int jt, int buf) {
        const uint32_t base = sb + AOFFK + buf * AKVB;
        const uint32_t soff = (uint32_t)(kv_row * AST + kv_c8) * 2;
        const size_t src = headoff + (size_t)(jt * 64 + kv_row) * DHD + kv_c8;
        cp_async16(base + soff,            g_Kh + src);
        cp_async16(base + AKOP + soff,     g_Kl + src);
        cp_async16(base + 2 * AKOP + soff, g_Vh + src);
        cp_async16(base + 3 * AKOP + soff, g_Vl + src);
        CP_COMMIT();
    };

    const int fr = lane & 15;
    const int fc = (lane >> 4) * 8;
    const int vkey = (lane & 7) + ((lane >> 4) << 3);
    const int vdh  = ((lane >> 3) & 1) << 3;

    // ---- S phase: S(j) -> softmax -> P/corr to smem ----
    auto s_phase = [&](int j) {
        const int key0 = j * 64;
        if (key0 > qmax_w) return;
        const uint32_t kvb = sb + AOFFK + (j % 3) * AKVB;
        const uint32_t qhb = sb;
        const uint32_t qlb = sb + AQOP;

        float accS[8][4];
#pragma unroll
        for (int i = 0; i < 8; i++)
#pragma unroll
            for (int jj = 0; jj < 4; jj++) accS[i][jj] = 0.0f;
#pragma unroll
        for (int ks = 0; ks < 4; ks++) {
            uint32_t qh[4], ql[4];
            const uint32_t qoff = (uint32_t)(((rw * 16 + fr) * AST + ks * 16 + fc) * 2);
            ldsm_x4(qh[0], qh[1], qh[2], qh[3], qhb + qoff);
            ldsm_x4(ql[0], ql[1], ql[2], ql[3], qlb + qoff);
#pragma unroll
            for (int g = 0; g < 4; g++) {
                uint32_t kh[4], kl[4];
                const uint32_t koff = (uint32_t)(((g * 16 + fr) * AST + ks * 16 + fc) * 2);
                ldsm_x4(kh[0], kh[1], kh[2], kh[3], kvb + koff);
                ldsm_x4(kl[0], kl[1], kl[2], kl[3], kvb + AKOP + koff);
#pragma unroll
                for (int sub = 0; sub < 2; sub++) {
                    const int nf = g * 2 + sub;
                    mma_bf16(accS[nf], qh, kh[sub], kh[sub + 2]);
                    mma_bf16(accS[nf], ql, kh[sub], kh[sub + 2]);
                    mma_bf16(accS[nf], qh, kl[sub], kl[sub + 2]);
                }
            }
        }

        if (key0 + 63 > qmin_w) {
            const int r1loc = r0loc + 8;
#pragma unroll
            for (int nf = 0; nf < 8; nf++) {
                const int c = key0 + nf * 8 + 2 * (lane & 3);
                if (c     > r0loc) accS[nf][0] = -1e30f;
                if (c + 1 > r0loc) accS[nf][1] = -1e30f;
                if (c     > r1loc) accS[nf][2] = -1e30f;
                if (c + 1 > r1loc) accS[nf][3] = -1e30f;
            }
        }

        float ml0 = -1e30f, ml1 = -1e30f;
#pragma unroll
        for (int nf = 0; nf < 8; nf++) {
            ml0 = fmaxf(ml0, fmaxf(accS[nf][0], accS[nf][1]));
            ml1 = fmaxf(ml1, fmaxf(accS[nf][2], accS[nf][3]));
        }
        ml0 = fmaxf(ml0, __shfl_xor_sync(0xffffffffu, ml0, 1));
        ml0 = fmaxf(ml0, __shfl_xor_sync(0xffffffffu, ml0, 2));
        ml1 = fmaxf(ml1, __shfl_xor_sync(0xffffffffu, ml1, 1));
        ml1 = fmaxf(ml1, __shfl_xor_sync(0xffffffffu, ml1, 2));
        const float mn0 = fmaxf(mrow[0], ml0);
        const float mn1 = fmaxf(mrow[1], ml1);
        const float corr0 = ex2f(mrow[0] - mn0);
        const float corr1 = ex2f(mrow[1] - mn1);
        mrow[0] = mn0; mrow[1] = mn1;

        float ls0 = 0.0f, ls1 = 0.0f;
        const uint32_t pbase = sb + AOFFP + (j & 1) * PBUF;
        const uint32_t prow0 = pbase + (uint32_t)((rw * 16 + (lane >> 2)) * AST) * 2;
        const uint32_t pcol  = (uint32_t)(2 * (lane & 3)) * 2;
#pragma unroll
        for (int nf = 0; nf < 8; nf++) {
            const float p0 = ex2f(accS[nf][0] - mn0);
            const float p1 = ex2f(accS[nf][1] - mn0);
            const float p2 = ex2f(accS[nf][2] - mn1);
            const float p3 = ex2f(accS[nf][3] - mn1);
            ls0 += p0 + p1;
            ls1 += p2 + p3;
            uint32_t hw, lw;
            const uint32_t o0 = prow0 + (uint32_t)(nf * 8) * 2 + pcol;
            split2(p0, p1, hw, lw);
            *reinterpret_cast<uint32_t*>(smem + (o0 - sb)) = hw;
            *reinterpret_cast<uint32_t*>(smem + (o0 + POP - sb)) = lw;
            split2(p2, p3, hw, lw);
            const uint32_t o1 = o0 + (uint32_t)(8 * AST) * 2;
            *reinterpret_cast<uint32_t*>(smem + (o1 - sb)) = hw;
            *reinterpret_cast<uint32_t*>(smem + (o1 + POP - sb)) = lw;
        }
        lrow[0] = lrow[0] * corr0 + ls0;
        lrow[1] = lrow[1] * corr1 + ls1;

        if ((lane & 3) == 0) {
            float* cb = reinterpret_cast<float*>(smem + AOFFC + (j & 1) * 512);
            cb[rw * 16 + (lane >> 2)]     = corr0;
            cb[rw * 16 + (lane >> 2) + 8] = corr1;
        }
    };

    // ---- PV phase: O += P(t) V(t), t = j-1 ----
    auto pv_phase = [&](int t) {
        const int key0 = t * 64;
        if (key0 > qmax_w) return;
        const float* cb = reinterpret_cast<const float*>(smem + AOFFC + (t & 1) * 512);
        const float corr0 = cb[rw * 16 + (lane >> 2)];
        const float corr1 = cb[rw * 16 + (lane >> 2) + 8];
#pragma unroll
        for (int nf = 0; nf < 8; nf++) {
            accO[nf][0] *= corr0; accO[nf][1] *= corr0;
            accO[nf][2] *= corr1; accO[nf][3] *= corr1;
        }
        const uint32_t pbase = sb + AOFFP + (t & 1) * PBUF;
        const uint32_t vhb   = sb + AOFFK + (t % 3) * AKVB + 2 * AKOP;
#pragma unroll
        for (int kp = 0; kp < 4; kp++) {
            uint32_t ph[4], pl[4];
            const uint32_t poff = (uint32_t)(((rw * 16 + fr) * AST + kp * 16 + fc) * 2);
            ldsm_x4(ph[0], ph[1], ph[2], ph[3], pbase + poff);
            ldsm_x4(pl[0], pl[1], pl[2], pl[3], pbase + POP + poff);
#pragma unroll
            for (int vg = 0; vg < 4; vg++) {
                uint32_t vh[4], vl[4];
                const uint32_t voff =
                    (uint32_t)(((kp * 16 + vkey) * AST + vg * 16 + vdh) * 2);
                ldsm_x4_t(vh[0], vh[1], vh[2], vh[3], vhb + voff);
                ldsm_x4_t(vl[0], vl[1], vl[2], vl[3], vhb + AKOP + voff);
#pragma unroll
                for (int sub = 0; sub < 2; sub++) {
                    const int nf = vg * 2 + sub;
                    mma_bf16(accO[nf], ph, vh[sub], vh[sub + 2]);
                    mma_bf16(accO[nf], pl, vh[sub], vh[sub + 2]);
                    mma_bf16(accO[nf], ph, vl[sub], vl[sub + 2]);
                }
            }
        }
    };

    // ---- phase loop: phase j runs S(j) on S-warps, PV(j-1) on PV-warps ----
    issueKV(0, 0);
    for (int j = 0; j <= ntiles; j++) {
        if (j + 1 < ntiles) { issueKV(j + 1, (j + 1) % 3); CP_WAIT1(); }
        else CP_WAIT0();
        __syncthreads();          // KV(j) visible; P/corr(j-1) published; P buf (j&1) free
        if (isS) {
            if (j < ntiles) s_phase(j);
            else {
                // final phase: publish l
                lrow[0] += __shfl_xor_sync(0xffffffffu, lrow[0], 1);
                lrow[0] += __shfl_xor_sync(0xffffffffu, lrow[0], 2);
                lrow[1] += __shfl_xor_sync(0xffffffffu, lrow[1], 1);
                lrow[1] += __shfl_xor_sync(0xffffffffu, lrow[1], 2);
                if ((lane & 3) == 0) {
                    float* lb = reinterpret_cast<float*>(smem + AOFFL);
                    lb[rw * 16 + (lane >> 2)]     = lrow[0];
                    lb[rw * 16 + (lane >> 2) + 8] = lrow[1];
                }
            }
        } else {
            if (j >= 1) pv_phase(j - 1);
        }
    }
    __syncthreads();

    // ---- epilogue (PV-warps): normalize, split, store pre-split O ----
    if (!isS) {
        const float* lb = reinterpret_cast<const float*>(smem + AOFFL);
        const float inv0 = 1.0f / lb[rw * 16 + (lane >> 2)];
        const float inv1 = 1.0f / lb[rw * 16 + (lane >> 2) + 8];
        const int q0 = qt * AQT + rw * 16 + (lane >> 2);
        const int q1 = q0 + 8;
#pragma unroll
        for (int nf = 0; nf < 8; nf++) {
            const int col = h * DHD + nf * 8 + 2 * (lane & 3);
            uint32_t hw, lw;
            split2(accO[nf][0] * inv0, accO[nf][1] * inv0, hw, lw);
            *reinterpret_cast<uint32_t*>(g_Oh + ((size_t)bbi * TT + q0) * DD + col) = hw;
            *reinterpret_cast<uint32_t*>(g_Ol + ((size_t)bbi * TT + q0) * DD + col) = lw;
            split2(accO[nf][2] * inv1, accO[nf][3] * inv1, hw, lw);
            *reinterpret_cast<uint32_t*>(g_Oh + ((size_t)bbi * TT + q1) * DD + col) = hw;
            *reinterpret_cast<uint32_t*>(g_Ol + ((size_t)bbi * TT + q1) * DD + col) = lw;
        }
    }
}

// ---------------------------------------------------------------------------
extern "C" void kernel_launch(void* const* d_in, const int* in_sizes, int n_in,
                              void* d_out, int out_size)
{
    (void)in_sizes; (void)n_in; (void)out_size;
    const float* x  = (const float*)d_in[0];
    // d_in[1] is the causal mask — statically known, ignored
    const float* Wq = (const float*)d_in[2];
    const float* Wk = (const float*)d_in[3];
    const float* Wv = (const float*)d_in[4];
    const float* Wo = (const float*)d_in[5];
    float* out = (float*)d_out;

    cudaFuncSetAttribute(qkv_mma_kernel,  cudaFuncAttributeMaxDynamicSharedMemorySize, SMEM_GEMM);
    cudaFuncSetAttribute(proj_mma_kernel, cudaFuncAttributeMaxDynamicSharedMemorySize, SMEM_GEMM);
    cudaFuncSetAttribute(attn_ws_kernel,  cudaFuncAttributeMaxDynamicSharedMemorySize, SMEM_ATTN);

    // 0. split x + transpose/split W (Wq pre-scaled by 0.125*log2e)
    prep_split_x<<<MM * DD / (256 * 8), 256>>>(x);
    dim3 gw(DD / 32, DD / 32, 4);
    prep_wt<<<gw, 256>>>(Wq, Wk, Wv, Wo);

    // 1. QKV projections
    dim3 g1(DD / 128, MM / 128, 3);
    qkv_mma_kernel<<<g1, 512, SMEM_GEMM>>>();

    // 2. causal flash attention (warp-specialized S/PV pipeline)
    dim3 g2(TT / AQT, BB * HH);
    attn_ws_kernel<<<g2, 512, SMEM_ATTN>>>();

    // 3. output projection
    dim3 g3(DD / 128, MM / 128);
    proj_mma_kernel<<<g3, 512, SMEM_GEMM>>>(out);
}

// round 14
// speedup vs baseline: 3.1501x; 1.0065x over previous
#include <cuda_runtime.h>
#include <cuda_bf16.h>
#include <math.h>
#include <stdint.h>

// Problem constants
constexpr int BB  = 2;
constexpr int TT  = 2048;
constexpr int DD  = 1024;
constexpr int HH  = 16;
constexpr int DHD = 64;
constexpr int MM  = BB * TT;     // 4096

// Pre-split bf16 scratch (device globals)
__device__ __nv_bfloat16 g_xh[MM * DD], g_xl[MM * DD];
__device__ __nv_bfloat16 g_Wth[4 * DD * DD], g_Wtl[4 * DD * DD];  // W^T hi/lo (Wq pre-scaled by 0.125*log2e)
__device__ __nv_bfloat16 g_Qh[MM * DD], g_Ql[MM * DD];            // head-major
__device__ __nv_bfloat16 g_Kh[MM * DD], g_Kl[MM * DD];
__device__ __nv_bfloat16 g_Vh[MM * DD], g_Vl[MM * DD];
__device__ __nv_bfloat16 g_Oh[MM * DD], g_Ol[MM * DD];            // token-major

// ---------------------------------------------------------------------------
// PTX helpers
// ---------------------------------------------------------------------------
__device__ __forceinline__ void ldsm_x4(uint32_t& r0, uint32_t& r1,
                                        uint32_t& r2, uint32_t& r3, uint32_t addr) {
    asm volatile("ldmatrix.sync.aligned.m8n8.x4.shared.b16 {%0,%1,%2,%3}, [%4];"
                 : "=r"(r0), "=r"(r1), "=r"(r2), "=r"(r3) : "r"(addr));
}

__device__ __forceinline__ void ldsm_x4_t(uint32_t& r0, uint32_t& r1,
                                          uint32_t& r2, uint32_t& r3, uint32_t addr) {
    asm volatile("ldmatrix.sync.aligned.m8n8.x4.trans.shared.b16 {%0,%1,%2,%3}, [%4];"
                 : "=r"(r0), "=r"(r1), "=r"(r2), "=r"(r3) : "r"(addr));
}

__device__ __forceinline__ void mma_bf16(float* d, const uint32_t* a,
                                         uint32_t b0, uint32_t b1) {
    asm volatile(
        "mma.sync.aligned.m16n8k16.row.col.f32.bf16.bf16.f32 "
        "{%0,%1,%2,%3}, {%4,%5,%6,%7}, {%8,%9}, {%0,%1,%2,%3};"
        : "+f"(d[0]), "+f"(d[1]), "+f"(d[2]), "+f"(d[3])
        : "r"(a[0]), "r"(a[1]), "r"(a[2]), "r"(a[3]), "r"(b0), "r"(b1));
}

__device__ __forceinline__ uint32_t smem_to_u32(const void* p) {
    uint32_t a;
    asm("{ .reg .u64 t; cvta.to.shared.u64 t, %1; cvt.u32.u64 %0, t; }"
        : "=r"(a) : "l"(p));
    return a;
}

__device__ __forceinline__ void cp_async16(uint32_t dst, const void* src) {
    asm volatile("cp.async.cg.shared.global [%0], [%1], 16;" :: "r"(dst), "l"(src));
}
#define CP_COMMIT() asm volatile("cp.async.commit_group;" ::: "memory")
#define CP_WAIT0()  asm volatile("cp.async.wait_group 0;"  ::: "memory")
#define CP_WAIT1()  asm volatile("cp.async.wait_group 1;"  ::: "memory")

__device__ __forceinline__ float ex2f(float x) {
    float r;
    asm("ex2.approx.f32 %0, %1;" : "=f"(r) : "f"(x));
    return r;
}

__device__ __forceinline__ uint32_t pack_bf2(__nv_bfloat16 a, __nv_bfloat16 b) {
    __nv_bfloat162 t = __halves2bfloat162(a, b);
    return *reinterpret_cast<uint32_t*>(&t);
}

__device__ __forceinline__ void split2(float f0, float f1, uint32_t& hw, uint32_t& lw) {
    __nv_bfloat16 h0 = __float2bfloat16(f0);
    __nv_bfloat16 h1 = __float2bfloat16(f1);
    __nv_bfloat16 l0 = __float2bfloat16(f0 - __bfloat162float(h0));
    __nv_bfloat16 l1 = __float2bfloat16(f1 - __bfloat162float(h1));
    hw = pack_bf2(h0, h1);
    lw = pack_bf2(l0, l1);
}

// ---------------------------------------------------------------------------
// Prep kernels
// ---------------------------------------------------------------------------
__global__ void __launch_bounds__(256)
prep_split_x(const float* __restrict__ x)
{
    const size_t i = ((size_t)blockIdx.x * 256 + threadIdx.x) * 8;
    float4 f0 = *reinterpret_cast<const float4*>(x + i);
    float4 f1 = *reinterpret_cast<const float4*>(x + i + 4);
    uint32_t h[4], l[4];
    split2(f0.x, f0.y, h[0], l[0]); split2(f0.z, f0.w, h[1], l[1]);
    split2(f1.x, f1.y, h[2], l[2]); split2(f1.z, f1.w, h[3], l[3]);
    *reinterpret_cast<uint4*>(g_xh + i) = make_uint4(h[0], h[1], h[2], h[3]);
    *reinterpret_cast<uint4*>(g_xl + i) = make_uint4(l[0], l[1], l[2], l[3]);
}

__global__ void __launch_bounds__(256)
prep_wt(const float* __restrict__ Wq, const float* __restrict__ Wk,
        const float* __restrict__ Wv, const float* __restrict__ Wo)
{
    const int z = blockIdx.z;
    const float* W = (z == 0) ? Wq : (z == 1) ? Wk : (z == 2) ? Wv : Wo;
    const float scale = (z == 0) ? 0.18033688011112042f : 1.0f;  // (1/8)*log2(e)
    __shared__ float tile[32][33];
    const int k0 = blockIdx.y * 32, n0 = blockIdx.x * 32;
    const int tx = threadIdx.x & 31, ty = threadIdx.x >> 5;
#pragma unroll
    for (int r = 0; r < 32; r += 8)
        tile[ty + r][tx] = W[(size_t)(k0 + ty + r) * DD + n0 + tx];
    __syncthreads();
    __nv_bfloat16* Th = g_Wth + (size_t)z * DD * DD;
    __nv_bfloat16* Tl = g_Wtl + (size_t)z * DD * DD;
#pragma unroll
    for (int r = 0; r < 32; r += 8) {
        const int n = n0 + ty + r, k = k0 + tx;
        const float v = tile[tx][ty + r] * scale;
        __nv_bfloat16 h = __float2bfloat16(v);
        __nv_bfloat16 l = __float2bfloat16(v - __bfloat162float(h));
        Th[(size_t)n * DD + k] = h;
        Tl[(size_t)n * DD + k] = l;
    }
}

// ---------------------------------------------------------------------------
// Pure-bf16 HMMA GEMM, 512 threads, 16 warps, warp tile 32x32.
// BK=64, 3-stage cp.async pipeline, term-ordered MMA emission.
// ---------------------------------------------------------------------------
constexpr int GBK    = 64;
constexpr int GNITER = DD / GBK;        // 16
constexpr int GST    = 72;              // padded row stride (bf16 elems)
constexpr int GOP    = 128 * GST * 2;   // 18432 B per operand component
constexpr int GBUF   = 4 * GOP;         // 73728 B (Ah, Al, Bh, Bl)
constexpr int SMEM_GEMM = 3 * GBUF;     // 221184 B

template <int MODE>
__device__ __forceinline__ void gemm_core(const __nv_bfloat16* __restrict__ Ah_g,
                                          const __nv_bfloat16* __restrict__ Al_g,
                                          const __nv_bfloat16* __restrict__ Bh_g,
                                          const __nv_bfloat16* __restrict__ Bl_g,
                                          float* __restrict__ Cf,
                                          __nv_bfloat16* __restrict__ Ch,
                                          __nv_bfloat16* __restrict__ Cl,
                                          int bx, int by)
{
    extern __shared__ char smem[];
    const uint32_t sb = smem_to_u32(smem);
    const int tid  = threadIdx.x;
    const int lane = tid & 31;
    const int wid  = tid >> 5;
    const int wm   = wid >> 2;
    const int wn   = wid & 3;
    const int m0 = by * 128, n0 = bx * 128;

    float acc[2][4][4];
#pragma unroll
    for (int i = 0; i < 2; i++)
#pragma unroll
        for (int j = 0; j < 4; j++)
#pragma unroll
            for (int k = 0; k < 4; k++) acc[i][j][k] = 0.0f;

    // loader: 512 threads, 128 rows x 64 cols per component; 2 cp16 each
    const int ld_row = tid >> 2;
    const int ld_c16 = (tid & 3) * 16;
    auto issue = [&](int buf, int k0) {
        const uint32_t base = sb + buf * GBUF;
        const uint32_t soff = (uint32_t)(ld_row * GST + ld_c16) * 2;
        const size_t ga = (size_t)(m0 + ld_row) * DD + k0 + ld_c16;
        const size_t gb = (size_t)(n0 + ld_row) * DD + k0 + ld_c16;
        cp_async16(base + soff,                Ah_g + ga);
        cp_async16(base + soff + 16,           Ah_g + ga + 8);
        cp_async16(base + GOP + soff,          Al_g + ga);
        cp_async16(base + GOP + soff + 16,     Al_g + ga + 8);
        cp_async16(base + 2 * GOP + soff,      Bh_g + gb);
        cp_async16(base + 2 * GOP + soff + 16, Bh_g + gb + 8);
        cp_async16(base + 3 * GOP + soff,      Bl_g + gb);
        cp_async16(base + 3 * GOP + soff + 16, Bl_g + gb + 8);
        CP_COMMIT();
    };

    const int ar = wm * 32 + (lane & 15);
    const int ac = (lane >> 4) * 8;
    const int br = wn * 32 + (lane & 15);
    const int bc = (lane >> 4) * 8;

    auto compute = [&](int buf) {
        const uint32_t ah_b = sb + buf * GBUF;
        const uint32_t al_b = ah_b + GOP;
        const uint32_t bh_b = al_b + GOP;
        const uint32_t bl_b = bh_b + GOP;
#pragma unroll
        for (int ks = 0; ks < 4; ks++) {
            uint32_t ah[2][4], al[2][4], bh[2][4], bl[2][4];
#pragma unroll
            for (int mf = 0; mf < 2; mf++) {
                const uint32_t off = (uint32_t)(((ar + mf * 16) * GST + ks * 16 + ac) * 2);
                ldsm_x4(ah[mf][0], ah[mf][1], ah[mf][2], ah[mf][3], ah_b + off);
                ldsm_x4(al[mf][0], al[mf][1], al[mf][2], al[mf][3], al_b + off);
            }
#pragma unroll
            for (int g = 0; g < 2; g++) {
                const uint32_t off = (uint32_t)(((br + g * 16) * GST + ks * 16 + bc) * 2);
                ldsm_x4(bh[g][0], bh[g][1], bh[g][2], bh[g][3], bh_b + off);
                ldsm_x4(bl[g][0], bl[g][1], bl[g][2], bl[g][3], bl_b + off);
            }
            // term-ordered: 8 independent accs between same-acc reuses;
            // per-acc order remains hh -> lh -> hl (bit-identical math)
#pragma unroll
            for (int mf = 0; mf < 2; mf++)
#pragma unroll
                for (int g = 0; g < 2; g++)
#pragma unroll
                    for (int sub = 0; sub < 2; sub++)
                        mma_bf16(acc[mf][g * 2 + sub], ah[mf], bh[g][sub], bh[g][sub + 2]);
#pragma unroll
            for (int mf = 0; mf < 2; mf++)
#pragma unroll
                for (int g = 0; g < 2; g++)
#pragma unroll
                    for (int sub = 0; sub < 2; sub++)
                        mma_bf16(acc[mf][g * 2 + sub], al[mf], bh[g][sub], bh[g][sub + 2]);
#pragma unroll
            for (int mf = 0; mf < 2; mf++)
#pragma unroll
                for (int g = 0; g < 2; g++)
#pragma unroll
                    for (int sub = 0; sub < 2; sub++)
                        mma_bf16(acc[mf][g * 2 + sub], ah[mf], bl[g][sub], bl[g][sub + 2]);
        }
    };

    issue(0, 0);
    issue(1, GBK);
    for (int it = 0; it < GNITER; ++it) {
        CP_WAIT1();
        __syncthreads();
        if (it + 2 < GNITER) issue((it + 2) % 3, (it + 2) * GBK);
        compute(it % 3);
    }

    const int group = lane >> 2;
    const int qd    = lane & 3;
#pragma unroll
    for (int mf = 0; mf < 2; mf++)
#pragma unroll
        for (int nf = 0; nf < 4; nf++) {
            const int rg = m0 + wm * 32 + mf * 16 + group;
            const int cg = n0 + wn * 32 + nf * 8 + qd * 2;
            if (MODE == 0) {
                const int bbi = rg >> 11;
                const int t   = rg & 2047;
                const int h   = cg >> 6;
                const int dd  = cg & 63;
                const size_t i0 = (((size_t)bbi * HH + h) * TT + t) * DHD + dd;
                const size_t i1 = i0 + (size_t)8 * DHD;
                uint32_t hw, lw;
                split2(acc[mf][nf][0], acc[mf][nf][1], hw, lw);
                *reinterpret_cast<uint32_t*>(Ch + i0) = hw;
                *reinterpret_cast<uint32_t*>(Cl + i0) = lw;
                split2(acc[mf][nf][2], acc[mf][nf][3], hw, lw);
                *reinterpret_cast<uint32_t*>(Ch + i1) = hw;
                *reinterpret_cast<uint32_t*>(Cl + i1) = lw;
            } else {
                *reinterpret_cast<float2*>(Cf + (size_t)rg * DD + cg) =
                    make_float2(acc[mf][nf][0], acc[mf][nf][1]);
                *reinterpret_cast<float2*>(Cf + (size_t)(rg + 8) * DD + cg) =
                    make_float2(acc[mf][nf][2], acc[mf][nf][3]);
            }
        }
}

__global__ void __launch_bounds__(512, 1)
qkv_mma_kernel()
{
    const int z = blockIdx.z;
    const __nv_bfloat16* Bh = g_Wth + (size_t)z * DD * DD;
    const __nv_bfloat16* Bl = g_Wtl + (size_t)z * DD * DD;
    __nv_bfloat16* Ch = (z == 0) ? g_Qh : (z == 1) ? g_Kh : g_Vh;
    __nv_bfloat16* Cl = (z == 0) ? g_Ql : (z == 1) ? g_Kl : g_Vl;
    gemm_core<0>(g_xh, g_xl, Bh, Bl, nullptr, Ch, Cl, blockIdx.x, blockIdx.y);
}

__global__ void __launch_bounds__(512, 1)
proj_mma_kernel(float* __restrict__ out)
{
    gemm_core<1>(g_Oh, g_Ol, g_Wth + (size_t)3 * DD * DD, g_Wtl + (size_t)3 * DD * DD,
                 out, nullptr, nullptr, blockIdx.x, blockIdx.y);
}

// ---------------------------------------------------------------------------
// Warp-specialized HMMA flash attention (unchanged from R13):
//   warps 0-7  (S-warps):  S = Q K^T, softmax, write P(hi/lo)+corr to smem
//   warps 8-15 (PV-warps): O += P V, one tile behind
// ---------------------------------------------------------------------------
constexpr int AQT   = 128;
constexpr int AST   = 72;
constexpr int AQOP  = AQT * AST * 2;       // 18432 B per Q component
constexpr int AKOP  = 64 * AST * 2;        // 9216 B per KV component
constexpr int AKVB  = 4 * AKOP;            // 36864 B (Kh,Kl,Vh,Vl)
constexpr int AOFFK = 2 * AQOP;            // 36864
constexpr int POP   = AQT * AST * 2;       // 18432 B per P component
constexpr int PBUF  = 2 * POP;             // 36864 (hi+lo)
constexpr int AOFFP = AOFFK + 3 * AKVB;    // 147456
constexpr int AOFFC = AOFFP + 2 * PBUF;    // 221184 (corr[2][128] floats)
constexpr int AOFFL = AOFFC + 1024;        // 222208 (l[128] floats)
constexpr int SMEM_ATTN = AOFFL + 512;     // 222720 B

__global__ void __launch_bounds__(512, 1)
attn_ws_kernel()
{
    extern __shared__ char smem[];
    const uint32_t sb = smem_to_u32(smem);
    const int bh  = blockIdx.y;
    const int bbi = bh / HH;
    const int h   = bh % HH;
    const int qt  = (int)gridDim.x - 1 - (int)blockIdx.x;
    const int tid = threadIdx.x;
    const int lane = tid & 31;
    const int wq   = tid >> 5;            // 0..15
    const bool isS = wq < 8;
    const int rw   = wq & 7;              // row-warp id

    const size_t headoff = (size_t)bh * TT * DHD;

    // ---- Q resident ----
    {
        const int row = tid >> 2;
        const int c16 = (tid & 3) * 16;
        const size_t src = headoff + (size_t)(qt * AQT + row) * DHD + c16;
        const uint4* shq = reinterpret_cast<const uint4*>(g_Qh + src);
        const uint4* slq = reinterpret_cast<const uint4*>(g_Ql + src);
        char* ph = smem + (row * AST + c16) * 2;
        char* pl = ph + AQOP;
        *reinterpret_cast<uint4*>(ph)      = shq[0];
        *reinterpret_cast<uint4*>(ph + 16) = shq[1];
        *reinterpret_cast<uint4*>(pl)      = slq[0];
        *reinterpret_cast<uint4*>(pl + 16) = slq[1];
    }

    float accO[8][4];
#pragma unroll
    for (int i = 0; i < 8; i++)
#pragma unroll
        for (int j = 0; j < 4; j++) accO[i][j] = 0.0f;
    float mrow[2] = {-1e30f, -1e30f};
    float lrow[2] = {0.0f, 0.0f};

    const int qmin_w = qt * AQT + rw * 16;
    const int qmax_w = qmin_w + 15;
    const int r0loc  = qmin_w + (lane >> 2);
    const int ntiles = 2 * (qt + 1);

    const int kv_row = tid >> 3;
    const int kv_c8  = (tid & 7) * 8;

    auto issueKV = [&](int jt, int buf) {
        const uint32_t base = sb + AOFFK + buf * AKVB;
        const uint32_t soff = (uint32_t)(kv_row * AST + kv_c8) * 2;
        const size_t src = headoff + (size_t)(jt * 64 + kv_row) * DHD + kv_c8;
        cp_async16(base + soff,            g_Kh + src);
        cp_async16(base + AKOP + soff,     g_Kl + src);
        cp_async16(base + 2 * AKOP + soff, g_Vh + src);
        cp_async16(base + 3 * AKOP + soff, g_Vl + src);
        CP_COMMIT();
    };

    const int fr = lane & 15;
    const int fc = (lane >> 4) * 8;
    const int vkey = (lane & 7) + ((lane >> 4) << 3);
    const int vdh  = ((lane >> 3) & 1) << 3;

    auto s_phase = [&](int j) {
        const int key0 = j * 64;
        if (key0 > qmax_w) return;
        const uint32_t kvb = sb + AOFFK + (j % 3) * AKVB;
        const uint32_t qhb = sb;
        const uint32_t qlb = sb + AQOP;

        float accS[8][4];
#pragma unroll
        for (int i = 0; i < 8; i++)
#pragma unroll
            for (int jj = 0; jj < 4; jj++) accS[i][jj] = 0.0f;
#pragma unroll
        for (int ks = 0; ks < 4; ks++) {
            uint32_t qh[4], ql[4];
            const uint32_t qoff = (uint32_t)(((rw * 16 + fr) * AST + ks * 16 + fc) * 2);
            ldsm_x4(qh[0], qh[1], qh[2], qh[3], qhb + qoff);
            ldsm_x4(ql[0], ql[1], ql[2], ql[3], qlb + qoff);
#pragma unroll
            for (int g = 0; g < 4; g++) {
                uint32_t kh[4], kl[4];
                const uint32_t koff = (uint32_t)(((g * 16 + fr) * AST + ks * 16 + fc) * 2);
                ldsm_x4(kh[0], kh[1], kh[2], kh[3], kvb + koff);
                ldsm_x4(kl[0], kl[1], kl[2], kl[3], kvb + AKOP + koff);
#pragma unroll
                for (int sub = 0; sub < 2; sub++) {
                    const int nf = g * 2 + sub;
                    mma_bf16(accS[nf], qh, kh[sub], kh[sub + 2]);
                    mma_bf16(accS[nf], ql, kh[sub], kh[sub + 2]);
                    mma_bf16(accS[nf], qh, kl[sub], kl[sub + 2]);
                }
            }
        }

        if (key0 + 63 > qmin_w) {
            const int r1loc = r0loc + 8;
#pragma unroll
            for (int nf = 0; nf < 8; nf++) {
                const int c = key0 + nf * 8 + 2 * (lane & 3);
                if (c     > r0loc) accS[nf][0] = -1e30f;
                if (c + 1 > r0loc) accS[nf][1] = -1e30f;
                if (c     > r1loc) accS[nf][2] = -1e30f;
                if (c + 1 > r1loc) accS[nf][3] = -1e30f;
            }
        }

        float ml0 = -1e30f, ml1 = -1e30f;
#pragma unroll
        for (int nf = 0; nf < 8; nf++) {
            ml0 = fmaxf(ml0, fmaxf(accS[nf][0], accS[nf][1]));
            ml1 = fmaxf(ml1, fmaxf(accS[nf][2], accS[nf][3]));
        }
        ml0 = fmaxf(ml0, __shfl_xor_sync(0xffffffffu, ml0, 1));
        ml0 = fmaxf(ml0, __shfl_xor_sync(0xffffffffu, ml0, 2));
        ml1 = fmaxf(ml1, __shfl_xor_sync(0xffffffffu, ml1, 1));
        ml1 = fmaxf(ml1, __shfl_xor_sync(0xffffffffu, ml1, 2));
        const float mn0 = fmaxf(mrow[0], ml0);
        const float mn1 = fmaxf(mrow[1], ml1);
        const float corr0 = ex2f(mrow[0] - mn0);
        const float corr1 = ex2f(mrow[1] - mn1);
        mrow[0] = mn0; mrow[1] = mn1;

        float ls0 = 0.0f, ls1 = 0.0f;
        const uint32_t pbase = sb + AOFFP + (j & 1) * PBUF;
        const uint32_t prow0 = pbase + (uint32_t)((rw * 16 + (lane >> 2)) * AST) * 2;
        const uint32_t pcol  = (uint32_t)(2 * (lane & 3)) * 2;
#pragma unroll
        for (int nf = 0; nf < 8; nf++) {
            const float p0 = ex2f(accS[nf][0] - mn0);
            const float p1 = ex2f(accS[nf][1] - mn0);
            const float p2 = ex2f(accS[nf][2] - mn1);
            const float p3 = ex2f(accS[nf][3] - mn1);
            ls0 += p0 + p1;
            ls1 += p2 + p3;
            uint32_t hw, lw;
            const uint32_t o0 = prow0 + (uint32_t)(nf * 8) * 2 + pcol;
            split2(p0, p1, hw, lw);
            *reinterpret_cast<uint32_t*>(smem + (o0 - sb)) = hw;
            *reinterpret_cast<uint32_t*>(smem + (o0 + POP - sb)) = lw;
            split2(p2, p3, hw, lw);
            const uint32_t o1 = o0 + (uint32_t)(8 * AST) * 2;
            *reinterpret_cast<uint32_t*>(smem + (o1 - sb)) = hw;
            *reinterpret_cast<uint32_t*>(smem + (o1 + POP - sb)) = lw;
        }
        lrow[0] = lrow[0] * corr0 + ls0;
        lrow[1] = lrow[1] * corr1 + ls1;

        if ((lane & 3) == 0) {
            float* cb = reinterpret_cast<float*>(smem + AOFFC + (j & 1) * 512);
            cb[rw * 16 + (lane >> 2)]     = corr0;
            cb[rw * 16 + (lane >> 2) + 8] = corr1;
        }
    };

    auto pv_phase = [&](int t) {
        const int key0 = t * 64;
        if (key0 > qmax_w) return;
        const float* cb = reinterpret_cast<const float*>(smem + AOFFC + (t & 1) * 512);
        const float corr0 = cb[rw * 16 + (lane >> 2)];
        const float corr1 = cb[rw * 16 + (lane >> 2) + 8];
#pragma unroll
        for (int nf = 0; nf < 8; nf++) {
            accO[nf][0] *= corr0; accO[nf][1] *= corr0;
            accO[nf][2] *= corr1; accO[nf][3] *= corr1;
        }
        const uint32_t pbase = sb + AOFFP + (t & 1) * PBUF;
        const uint32_t vhb   = sb + AOFFK + (t % 3) * AKVB + 2 * AKOP;
#pragma unroll
        for (int kp = 0; kp < 4; kp++) {
            uint32_t ph[4], pl[4];
            const uint32_t poff = (uint32_t)(((rw * 16 + fr) * AST + kp * 16 + fc) * 2);
            ldsm_x4(ph[0], ph[1], ph[2], ph[3], pbase + poff);
            ldsm_x4(pl[0], pl[1], pl[2], pl[3], pbase + POP + poff);
#pragma unroll
            for (int vg = 0; vg < 4; vg++) {
                uint32_t vh[4], vl[4];
                const uint32_t voff =
                    (uint32_t)(((kp * 16 + vkey) * AST + vg * 16 + vdh) * 2);
                ldsm_x4_t(vh[0], vh[1], vh[2], vh[3], vhb + voff);
                ldsm_x4_t(vl[0], vl[1], vl[2], vl[3], vhb + AKOP + voff);
#pragma unroll
                for (int sub = 0; sub < 2; sub++) {
                    const int nf = vg * 2 + sub;
                    mma_bf16(accO[nf], ph, vh[sub], vh[sub + 2]);
                    mma_bf16(accO[nf], pl, vh[sub], vh[sub + 2]);
                    mma_bf16(accO[nf], ph, vl[sub], vl[sub + 2]);
                }
            }
        }
    };

    issueKV(0, 0);
    for (int j = 0; j <= ntiles; j++) {
        if (j + 1 < ntiles) { issueKV(j + 1, (j + 1) % 3); CP_WAIT1(); }
        else CP_WAIT0();
        __syncthreads();
        if (isS) {
            if (j < ntiles) s_phase(j);
            else {
                lrow[0] += __shfl_xor_sync(0xffffffffu, lrow[0], 1);
                lrow[0] += __shfl_xor_sync(0xffffffffu, lrow[0], 2);
                lrow[1] += __shfl_xor_sync(0xffffffffu, lrow[1], 1);
                lrow[1] += __shfl_xor_sync(0xffffffffu, lrow[1], 2);
                if ((lane & 3) == 0) {
                    float* lb = reinterpret_cast<float*>(smem + AOFFL);
                    lb[rw * 16 + (lane >> 2)]     = lrow[0];
                    lb[rw * 16 + (lane >> 2) + 8] = lrow[1];
                }
            }
        } else {
            if (j >= 1) pv_phase(j - 1);
        }
    }
    __syncthreads();

    if (!isS) {
        const float* lb = reinterpret_cast<const float*>(smem + AOFFL);
        const float inv0 = 1.0f / lb[rw * 16 + (lane >> 2)];
        const float inv1 = 1.0f / lb[rw * 16 + (lane >> 2) + 8];
        const int q0 = qt * AQT + rw * 16 + (lane >> 2);
        const int q1 = q0 + 8;
#pragma unroll
        for (int nf = 0; nf < 8; nf++) {
            const int col = h * DHD + nf * 8 + 2 * (lane & 3);
            uint32_t hw, lw;
            split2(accO[nf][0] * inv0, accO[nf][1] * inv0, hw, lw);
            *reinterpret_cast<uint32_t*>(g_Oh + ((size_t)bbi * TT + q0) * DD + col) = hw;
            *reinterpret_cast<uint32_t*>(g_Ol + ((size_t)bbi * TT + q0) * DD + col) = lw;
            split2(accO[nf][2] * inv1, accO[nf][3] * inv1, hw, lw);
            *reinterpret_cast<uint32_t*>(g_Oh + ((size_t)bbi * TT + q1) * DD + col) = hw;
            *reinterpret_cast<uint32_t*>(g_Ol + ((size_t)bbi * TT + q1) * DD + col) = lw;
        }
    }
}

// ---------------------------------------------------------------------------
extern "C" void kernel_launch(void* const* d_in, const int* in_sizes, int n_in,
                              void* d_out, int out_size)
{
    (void)in_sizes; (void)n_in; (void)out_size;
    const float* x  = (const float*)d_in[0];
    // d_in[1] is the causal mask — statically known, ignored
    const float* Wq = (const float*)d_in[2];
    const float* Wk = (const float*)d_in[3];
    const float* Wv = (const float*)d_in[4];
    const float* Wo = (const float*)d_in[5];
    float* out = (float*)d_out;

    cudaFuncSetAttribute(qkv_mma_kernel,  cudaFuncAttributeMaxDynamicSharedMemorySize, SMEM_GEMM);
    cudaFuncSetAttribute(proj_mma_kernel, cudaFuncAttributeMaxDynamicSharedMemorySize, SMEM_GEMM);
    cudaFuncSetAttribute(attn_ws_kernel,  cudaFuncAttributeMaxDynamicSharedMemorySize, SMEM_ATTN);

    // 0. split x + transpose/split W (Wq pre-scaled by 0.125*log2e)
    prep_split_x<<<MM * DD / (256 * 8), 256>>>(x);
    dim3 gw(DD / 32, DD / 32, 4);
    prep_wt<<<gw, 256>>>(Wq, Wk, Wv, Wo);

    // 1. QKV projections (BK=64, 3-stage)
    dim3 g1(DD / 128, MM / 128, 3);
    qkv_mma_kernel<<<g1, 512, SMEM_GEMM>>>();

    // 2. causal flash attention (warp-specialized S/PV pipeline)
    dim3 g2(TT / AQT, BB * HH);
    attn_ws_kernel<<<g2, 512, SMEM_ATTN>>>();

    // 3. output projection
    dim3 g3(DD / 128, MM / 128);
    proj_mma_kernel<<<g3, 512, SMEM_GEMM>>>(out);
}